// round 1
// baseline (speedup 1.0000x reference)
#include <cuda_runtime.h>
#include <math.h>

// Problem constants
#define DIM   512
#define NTOK  4096            // B*S = B*T = 4*1024
#define NHEAD 8
#define DD    (512*512)
#define HD    4096            // H*D

// ---------------- static scratch (no allocation allowed) ----------------
__device__ float g_Q [4096*4096];
__device__ float g_K [4096*4096];
__device__ float g_V [4096*4096];
__device__ float g_Sc[32*1024*1024];
__device__ float g_O [4096*4096];
__device__ float g_OC[4096*4096];
__device__ float g_H [4096*512];
__device__ float g_X1[4096*512];
__device__ float g_X2[4096*512];
__device__ float g_MID[4096*2048];

// ---------------- generic batched GEMM ----------------
// C[m,n] = alpha * sum_k A[m,k]*B(k,n) + bias[n]
// NT=true: B stored [N,K] row-major (B(k,n) = B[n*ldb+k])
// batch p: offsets (p/div)*s?1 + (p%div)*s?2
// flags: 1 = ReLU, 2 = causal mask (n > m -> -1e30, local indices)
struct GemmP {
    const float* A; const float* B; const float* bias; float* C;
    int M, N, K, lda, ldb, ldc;
    long long sA1, sA2, sB1, sB2, sC1, sC2;
    int div; int biasStride;
    float alpha; int flags;
};

#define BM 128
#define BN 128
#define BK 16

template<bool NT>
__global__ __launch_bounds__(256)
void gemm_k(GemmP p) {
    const int pb = blockIdx.z;
    const int pq = pb / p.div, pr = pb % p.div;
    const float* A  = p.A + (long long)pq * p.sA1 + (long long)pr * p.sA2;
    const float* Bm = p.B + (long long)pq * p.sB1 + (long long)pr * p.sB2;
    float*       C  = p.C + (long long)pq * p.sC1 + (long long)pr * p.sC2;

    __shared__ float As[BK][BM];
    __shared__ float Bs[BK][BN];

    const int tid = threadIdx.x;
    const int tx = tid & 15, ty = tid >> 4;
    const int m0 = blockIdx.y * BM, n0 = blockIdx.x * BN;

    float acc[8][8];
#pragma unroll
    for (int i = 0; i < 8; i++)
#pragma unroll
        for (int j = 0; j < 8; j++) acc[i][j] = 0.f;

    for (int kt = 0; kt < p.K; kt += BK) {
        // load A tile (BM x BK), store transposed As[k][m]
#pragma unroll
        for (int i = 0; i < 2; i++) {
            int idx = tid + i * 256;
            int r = idx >> 2, c = (idx & 3) << 2;
            float4 v = *(const float4*)(A + (long long)(m0 + r) * p.lda + kt + c);
            As[c + 0][r] = v.x; As[c + 1][r] = v.y;
            As[c + 2][r] = v.z; As[c + 3][r] = v.w;
        }
        if (NT) {
            // B stored [N,K]: load 128 n-rows x 16 k-cols, scatter to Bs[k][n]
#pragma unroll
            for (int i = 0; i < 2; i++) {
                int idx = tid + i * 256;
                int n = idx >> 2, c = (idx & 3) << 2;
                float4 v = *(const float4*)(Bm + (long long)(n0 + n) * p.ldb + kt + c);
                Bs[c + 0][n] = v.x; Bs[c + 1][n] = v.y;
                Bs[c + 2][n] = v.z; Bs[c + 3][n] = v.w;
            }
        } else {
            // B stored [K,N]: straight vector copy Bs[k][n]
#pragma unroll
            for (int i = 0; i < 2; i++) {
                int idx = tid + i * 256;
                int r = idx >> 5, c = (idx & 31) << 2;
                *(float4*)&Bs[r][c] =
                    *(const float4*)(Bm + (long long)(kt + r) * p.ldb + n0 + c);
            }
        }
        __syncthreads();

#pragma unroll
        for (int k = 0; k < BK; k++) {
            float a[8], b[8];
            *(float4*)&a[0] = *(const float4*)&As[k][ty * 8];
            *(float4*)&a[4] = *(const float4*)&As[k][ty * 8 + 4];
            *(float4*)&b[0] = *(const float4*)&Bs[k][tx * 8];
            *(float4*)&b[4] = *(const float4*)&Bs[k][tx * 8 + 4];
#pragma unroll
            for (int i = 0; i < 8; i++)
#pragma unroll
                for (int j = 0; j < 8; j++)
                    acc[i][j] = fmaf(a[i], b[j], acc[i][j]);
        }
        __syncthreads();
    }

    // epilogue
#pragma unroll
    for (int i = 0; i < 8; i++) {
        int m = m0 + ty * 8 + i;
        float out[8];
#pragma unroll
        for (int j = 0; j < 8; j++) {
            int n = n0 + tx * 8 + j;
            float v = acc[i][j] * p.alpha;
            if (p.bias) v += p.bias[pr * p.biasStride + n];
            if ((p.flags & 2) && n > m) v = -1e30f;
            if (p.flags & 1) v = fmaxf(v, 0.f);
            out[j] = v;
        }
        float* cp = C + (long long)m * p.ldc + n0 + tx * 8;
        *(float4*)cp       = *(float4*)&out[0];
        *(float4*)(cp + 4) = *(float4*)&out[4];
    }
}

// ---------------- row softmax over 1024 columns ----------------
__global__ __launch_bounds__(256)
void softmax_k(float* S) {
    __shared__ float red[8];
    const long long row = blockIdx.x;
    float4* rp = (float4*)(S + row * 1024);
    float4 v = rp[threadIdx.x];
    const int lane = threadIdx.x & 31, warp = threadIdx.x >> 5;

    float mx = fmaxf(fmaxf(v.x, v.y), fmaxf(v.z, v.w));
#pragma unroll
    for (int o = 16; o; o >>= 1) mx = fmaxf(mx, __shfl_xor_sync(~0u, mx, o));
    if (lane == 0) red[warp] = mx;
    __syncthreads();
    float m2 = red[lane & 7];
#pragma unroll
    for (int o = 4; o; o >>= 1) m2 = fmaxf(m2, __shfl_xor_sync(~0u, m2, o));
    mx = m2;  // every thread has the max now (broadcast via shfl over 8 warps' vals)
    __syncthreads();

    v.x = __expf(v.x - mx); v.y = __expf(v.y - mx);
    v.z = __expf(v.z - mx); v.w = __expf(v.w - mx);
    float s = v.x + v.y + v.z + v.w;
#pragma unroll
    for (int o = 16; o; o >>= 1) s += __shfl_xor_sync(~0u, s, o);
    if (lane == 0) red[warp] = s;
    __syncthreads();
    float s2 = red[lane & 7];
#pragma unroll
    for (int o = 4; o; o >>= 1) s2 += __shfl_xor_sync(~0u, s2, o);
    float inv = 1.f / s2;

    v.x *= inv; v.y *= inv; v.z *= inv; v.w *= inv;
    rp[threadIdx.x] = v;
}

// ---------------- residual add + LayerNorm over D=512 ----------------
__device__ __forceinline__ float block_sum_512(float val, float* red) {
    const int lane = threadIdx.x & 31, warp = threadIdx.x >> 5;
#pragma unroll
    for (int o = 16; o; o >>= 1) val += __shfl_xor_sync(~0u, val, o);
    if (lane == 0) red[warp] = val;
    __syncthreads();
    float s = red[lane & 7];
#pragma unroll
    for (int o = 4; o; o >>= 1) s += __shfl_xor_sync(~0u, s, o);
    __syncthreads();
    return s;
}

__global__ __launch_bounds__(256)
void add_ln_k(const float* __restrict__ a, const float* __restrict__ r,
              const float* __restrict__ g, const float* __restrict__ b,
              float* __restrict__ o) {
    __shared__ float red[8];
    const long long row = blockIdx.x;
    const int t = threadIdx.x;
    const float* pa = a + row * 512;
    const float* pr = r + row * 512;

    float x0 = pa[t] + pr[t];
    float x1 = pa[t + 256] + pr[t + 256];
    float mean = block_sum_512(x0 + x1, red) * (1.f / 512.f);
    float d0 = x0 - mean, d1 = x1 - mean;
    float var = block_sum_512(d0 * d0 + d1 * d1, red) * (1.f / 512.f);
    float inv = rsqrtf(var + 1e-5f);
    o[row * 512 + t]       = d0 * inv * g[t] + b[t];
    o[row * 512 + t + 256] = d1 * inv * g[t + 256] + b[t + 256];
}

// ---------------- host orchestration ----------------
static inline void run_gemm(bool nt, const float* A, const float* B, const float* bias, float* C,
                            int M, int N, int K, int lda, int ldb, int ldc,
                            long long sA1, long long sA2, long long sB1, long long sB2,
                            long long sC1, long long sC2,
                            int div, int biasStride, float alpha, int flags, int batch) {
    GemmP p{A, B, bias, C, M, N, K, lda, ldb, ldc,
            sA1, sA2, sB1, sB2, sC1, sC2, div, biasStride, alpha, flags};
    dim3 grid(N / BN, M / BM, batch);
    if (nt) gemm_k<true><<<grid, 256>>>(p);
    else    gemm_k<false><<<grid, 256>>>(p);
}

static void mha(const float* xq, const float* xkv,
                const float* wq, const float* bq, const float* wk, const float* bk,
                const float* wv, const float* bv, const float* wo, const float* bo,
                const float* wf, const float* bf, bool causal,
                float* Q, float* K, float* V, float* Sc, float* O, float* OC, float* Hout) {
    const float iscale = 0.044194173824159216f;  // 1/sqrt(512)
    // Q/K/V projections: batch over heads, one big M=4096 GEMM per head
    run_gemm(false, xq,  wq, bq, Q, 4096, 512, 512, 512, 512, 4096,
             0, 0, 0, DD, 0, 512, 8, 512, 1.f, 0, 8);
    run_gemm(false, xkv, wk, bk, K, 4096, 512, 512, 512, 512, 4096,
             0, 0, 0, DD, 0, 512, 8, 512, 1.f, 0, 8);
    run_gemm(false, xkv, wv, bv, V, 4096, 512, 512, 512, 512, 4096,
             0, 0, 0, DD, 0, 512, 8, 512, 1.f, 0, 8);
    // scores = Q K^T / sqrt(512), batch (b,h)=32, fused causal mask
    run_gemm(true, Q, K, nullptr, Sc, 1024, 1024, 512, 4096, 4096, 1024,
             1024LL * 4096, 512, 1024LL * 4096, 512,
             8LL * 1048576, 1048576, 8, 0, iscale, causal ? 2 : 0, 32);
    softmax_k<<<32768, 256>>>(Sc);
    // O = A V
    run_gemm(false, Sc, V, nullptr, O, 1024, 512, 1024, 1024, 4096, 4096,
             8LL * 1048576, 1048576, 1024LL * 4096, 512,
             1024LL * 4096, 512, 8, 0, 1.f, 0, 32);
    // per-head output projection
    run_gemm(false, O, wo, bo, OC, 4096, 512, 512, 4096, 512, 4096,
             0, 512, 0, DD, 0, 512, 8, 512, 1.f, 0, 8);
    // final concat projection wf: [4096, 4096] @ [4096, 512]
    run_gemm(false, OC, wf, bf, Hout, 4096, 512, 4096, 4096, 512, 512,
             0, 0, 0, 0, 0, 0, 1, 0, 1.f, 0, 1);
}

extern "C" void kernel_launch(void* const* d_in, const int* in_sizes, int n_in,
                              void* d_out, int out_size) {
    const float* x   = (const float*)d_in[0];
    const float* enc = (const float*)d_in[1];
    const float* sa_wq = (const float*)d_in[2];  const float* sa_bq = (const float*)d_in[3];
    const float* sa_wk = (const float*)d_in[4];  const float* sa_bk = (const float*)d_in[5];
    const float* sa_wv = (const float*)d_in[6];  const float* sa_bv = (const float*)d_in[7];
    const float* sa_wo = (const float*)d_in[8];  const float* sa_bo = (const float*)d_in[9];
    const float* sa_wf = (const float*)d_in[10]; const float* sa_bf = (const float*)d_in[11];
    const float* ca_wq = (const float*)d_in[12]; const float* ca_bq = (const float*)d_in[13];
    const float* ca_wk = (const float*)d_in[14]; const float* ca_bk = (const float*)d_in[15];
    const float* ca_wv = (const float*)d_in[16]; const float* ca_bv = (const float*)d_in[17];
    const float* ca_wo = (const float*)d_in[18]; const float* ca_bo = (const float*)d_in[19];
    const float* ca_wf = (const float*)d_in[20]; const float* ca_bf = (const float*)d_in[21];
    const float* ln1_g = (const float*)d_in[22]; const float* ln1_b = (const float*)d_in[23];
    const float* ln2_g = (const float*)d_in[24]; const float* ln2_b = (const float*)d_in[25];
    const float* ln3_g = (const float*)d_in[26]; const float* ln3_b = (const float*)d_in[27];
    const float* fc1_w = (const float*)d_in[28]; const float* fc1_b = (const float*)d_in[29];
    const float* fc2_w = (const float*)d_in[30]; const float* fc2_b = (const float*)d_in[31];

    float *Q, *K, *V, *Sc, *O, *OC, *H, *X1, *X2, *MID;
    cudaGetSymbolAddress((void**)&Q,  g_Q);
    cudaGetSymbolAddress((void**)&K,  g_K);
    cudaGetSymbolAddress((void**)&V,  g_V);
    cudaGetSymbolAddress((void**)&Sc, g_Sc);
    cudaGetSymbolAddress((void**)&O,  g_O);
    cudaGetSymbolAddress((void**)&OC, g_OC);
    cudaGetSymbolAddress((void**)&H,  g_H);
    cudaGetSymbolAddress((void**)&X1, g_X1);
    cudaGetSymbolAddress((void**)&X2, g_X2);
    cudaGetSymbolAddress((void**)&MID, g_MID);

    // self-attention (causal) + residual LN
    mha(x, x, sa_wq, sa_bq, sa_wk, sa_bk, sa_wv, sa_bv, sa_wo, sa_bo, sa_wf, sa_bf,
        true, Q, K, V, Sc, O, OC, H);
    add_ln_k<<<4096, 256>>>(H, x, ln1_g, ln1_b, X1);

    // cross-attention (no mask) + residual LN
    mha(X1, enc, ca_wq, ca_bq, ca_wk, ca_bk, ca_wv, ca_bv, ca_wo, ca_bo, ca_wf, ca_bf,
        false, Q, K, V, Sc, O, OC, H);
    add_ln_k<<<4096, 256>>>(H, X1, ln2_g, ln2_b, X2);

    // FFN: relu(X2 @ fc1 + b1) @ fc2 + b2, residual LN -> d_out
    run_gemm(false, X2, fc1_w, fc1_b, MID, 4096, 2048, 512, 512, 2048, 2048,
             0, 0, 0, 0, 0, 0, 1, 0, 1.f, 1, 1);
    run_gemm(false, MID, fc2_w, fc2_b, H, 4096, 512, 2048, 2048, 512, 512,
             0, 0, 0, 0, 0, 0, 1, 0, 1.f, 0, 1);
    add_ln_k<<<4096, 256>>>(H, X2, ln3_g, ln3_b, (float*)d_out);
}

// round 2
// speedup vs baseline: 2.3285x; 2.3285x over previous
#include <cuda_runtime.h>
#include <cuda_bf16.h>
#include <math.h>

#define SMEM_BYTES 81920
#define SSTR 40

// ---------------- static scratch ----------------
__device__ __nv_bfloat16 g_Qh[16777216], g_Ql[16777216];
__device__ __nv_bfloat16 g_Kh[16777216], g_Kl[16777216];
__device__ __nv_bfloat16 g_Vh[16777216], g_Vl[16777216];
__device__ __nv_bfloat16 g_Sh[33554432], g_Sl[33554432];
__device__ __nv_bfloat16 g_Oh[16777216], g_Ol[16777216];
__device__ __nv_bfloat16 g_Ph[16777216], g_Pl[16777216];   // per-head out-proj (concat)
__device__ __nv_bfloat16 g_Mh[8388608],  g_Ml[8388608];    // FFN mid
__device__ __nv_bfloat16 g_Wh[23068672], g_Wl[23068672];   // all weights split
__device__ __nv_bfloat16 g_xh[2097152],  g_xl[2097152];
__device__ __nv_bfloat16 g_eh[2097152],  g_el[2097152];
__device__ __nv_bfloat16 g_X1h[2097152], g_X1l[2097152];
__device__ __nv_bfloat16 g_X2h[2097152], g_X2l[2097152];
__device__ float g_Hf[2097152], g_X1f[2097152], g_X2f[2097152];

// weight offsets (elements)
#define OW_SAQ 0LL
#define OW_SAK 2097152LL
#define OW_SAV 4194304LL
#define OW_SAO 6291456LL
#define OW_SAF 8388608LL
#define OW_CAQ 10485760LL
#define OW_CAK 12582912LL
#define OW_CAV 14680064LL
#define OW_CAO 16777216LL
#define OW_CAF 18874368LL
#define OW_FC1 20971520LL
#define OW_FC2 22020096LL

// ---------------- PTX helpers ----------------
__device__ __forceinline__ void mma16816(float* d, const unsigned* a, const unsigned* b) {
    asm volatile(
        "mma.sync.aligned.m16n8k16.row.col.f32.bf16.bf16.f32 "
        "{%0,%1,%2,%3}, {%4,%5,%6,%7}, {%8,%9}, {%0,%1,%2,%3};"
        : "+f"(d[0]), "+f"(d[1]), "+f"(d[2]), "+f"(d[3])
        : "r"(a[0]), "r"(a[1]), "r"(a[2]), "r"(a[3]), "r"(b[0]), "r"(b[1]));
}
__device__ __forceinline__ void ldsm4(unsigned* r, unsigned a) {
    asm volatile("ldmatrix.sync.aligned.m8n8.x4.shared.b16 {%0,%1,%2,%3}, [%4];"
                 : "=r"(r[0]), "=r"(r[1]), "=r"(r[2]), "=r"(r[3]) : "r"(a));
}
__device__ __forceinline__ void cp16(unsigned d, const void* s) {
    asm volatile("cp.async.cg.shared.global [%0], [%1], 16;" :: "r"(d), "l"(s));
}

// ---------------- split-bf16 GEMM ----------------
// C = alpha * A*B + bias; A [M,K] row-major split bf16.
// NT=true : B stored [N,K] row-major (direct cp.async copy)
// NT=false: B stored [K,N] row-major (register transpose load)
// flags: 1 relu, 2 causal (local idx), 4 write fp32 C, 8 write split-bf16 C
struct GemmP {
    const __nv_bfloat16 *Ah, *Al, *Bh, *Bl;
    const float* bias;
    __nv_bfloat16 *Ch, *Cl;
    float* Cf;
    int K, lda, ldb, ldc;
    long long sA1, sA2, sB1, sB2, sC1, sC2;
    int div, biasStride;
    float alpha; int flags;
};

template<bool NT>
__global__ __launch_bounds__(256) void gemm_k(GemmP p) {
    extern __shared__ unsigned char raw[];
    __nv_bfloat16* As = (__nv_bfloat16*)raw;            // [(st*2+hl)*128+m]*SSTR + k
    __nv_bfloat16* Bs = As + 4 * 128 * SSTR;            // [(st*2+hl)*128+n]*SSTR + k

    const int pb = blockIdx.z, pq = pb / p.div, pr = pb - pq * p.div;
    const __nv_bfloat16* Abase[2] = { p.Ah + pq * p.sA1 + pr * p.sA2,
                                      p.Al + pq * p.sA1 + pr * p.sA2 };
    const __nv_bfloat16* Bbase[2] = { p.Bh + pq * p.sB1 + pr * p.sB2,
                                      p.Bl + pq * p.sB1 + pr * p.sB2 };

    const int tid = threadIdx.x, lane = tid & 31, warp = tid >> 5;
    const int wm = warp >> 1, wn = warp & 1;
    const int m0 = blockIdx.y * 128, n0 = blockIdx.x * 128;

    const unsigned sA = (unsigned)__cvta_generic_to_shared(As);
    const unsigned sB = (unsigned)__cvta_generic_to_shared(Bs);

    const int crow = tid >> 2, cseg = (tid & 3) * 8;        // cp.async map
    const int tn = (tid & 63) * 2, tk0 = (tid >> 6) * 8;    // transpose map

    float acc[2][8][4];
#pragma unroll
    for (int i = 0; i < 2; i++)
#pragma unroll
        for (int j = 0; j < 8; j++)
#pragma unroll
            for (int q = 0; q < 4; q++) acc[i][j][q] = 0.f;

    unsigned trh[8], trl[8];

    auto issue_stage = [&](int st, int kt) {
#pragma unroll
        for (int hl = 0; hl < 2; hl++)
#pragma unroll
            for (int r = 0; r < 2; r++) {
                int row = crow + r * 64;
                cp16(sA + 2u * (((st * 2 + hl) * 128 + row) * SSTR + cseg),
                     Abase[hl] + (long long)(m0 + row) * p.lda + kt + cseg);
                if (NT)
                    cp16(sB + 2u * (((st * 2 + hl) * 128 + row) * SSTR + cseg),
                         Bbase[hl] + (long long)(n0 + row) * p.ldb + kt + cseg);
            }
        asm volatile("cp.async.commit_group;");
    };
    auto load_trans = [&](int kt) {
#pragma unroll
        for (int kk = 0; kk < 8; kk++) {
            int k = tk0 + kk;
            trh[kk] = *(const unsigned*)(Bbase[0] + (long long)(kt + k) * p.ldb + n0 + tn);
            trl[kk] = *(const unsigned*)(Bbase[1] + (long long)(kt + k) * p.ldb + n0 + tn);
        }
    };
    auto store_trans = [&](int st) {
#pragma unroll
        for (int kk = 0; kk < 8; kk++) {
            int k = tk0 + kk;
            __nv_bfloat162 h = *(__nv_bfloat162*)&trh[kk];
            __nv_bfloat162 l = *(__nv_bfloat162*)&trl[kk];
            Bs[((st * 2 + 0) * 128 + tn) * SSTR + k]     = h.x;
            Bs[((st * 2 + 0) * 128 + tn + 1) * SSTR + k] = h.y;
            Bs[((st * 2 + 1) * 128 + tn) * SSTR + k]     = l.x;
            Bs[((st * 2 + 1) * 128 + tn + 1) * SSTR + k] = l.y;
        }
    };

    // prologue
    issue_stage(0, 0);
    if (!NT) load_trans(0);
    asm volatile("cp.async.wait_group 0;" ::: "memory");
    if (!NT) store_trans(0);
    __syncthreads();

    int st = 0;
    for (int kt = 0; kt < p.K; kt += 32) {
        const int nxt = kt + 32;
        const bool more = nxt < p.K;
        if (more) {
            issue_stage(st ^ 1, nxt);
            if (!NT) load_trans(nxt);
        }
#pragma unroll
        for (int ks = 0; ks < 32; ks += 16) {
            unsigned ah[2][4], alr[2][4], bh[8][2], blr[8][2];
#pragma unroll
            for (int i = 0; i < 2; i++) {
                int row = wm * 32 + i * 16 + (lane & 15);
                int ko = ks + (lane >> 4) * 8;
                ldsm4(ah[i],  sA + 2u * (((st * 2 + 0) * 128 + row) * SSTR + ko));
                ldsm4(alr[i], sA + 2u * (((st * 2 + 1) * 128 + row) * SSTR + ko));
            }
#pragma unroll
            for (int jj = 0; jj < 4; jj++) {
                int row = wn * 64 + jj * 16 + (lane & 7) + ((lane >> 4) & 1) * 8;
                int ko = ks + ((lane >> 3) & 1) * 8;
                unsigned t0[4];
                ldsm4(t0, sB + 2u * (((st * 2 + 0) * 128 + row) * SSTR + ko));
                bh[2 * jj][0] = t0[0]; bh[2 * jj][1] = t0[1];
                bh[2 * jj + 1][0] = t0[2]; bh[2 * jj + 1][1] = t0[3];
                ldsm4(t0, sB + 2u * (((st * 2 + 1) * 128 + row) * SSTR + ko));
                blr[2 * jj][0] = t0[0]; blr[2 * jj][1] = t0[1];
                blr[2 * jj + 1][0] = t0[2]; blr[2 * jj + 1][1] = t0[3];
            }
#pragma unroll
            for (int i = 0; i < 2; i++)
#pragma unroll
                for (int j = 0; j < 8; j++) {
                    mma16816(acc[i][j], ah[i],  bh[j]);
                    mma16816(acc[i][j], ah[i],  blr[j]);
                    mma16816(acc[i][j], alr[i], bh[j]);
                }
        }
        if (more) {
            asm volatile("cp.async.wait_group 0;" ::: "memory");
            if (!NT) store_trans(st ^ 1);
            __syncthreads();
        }
        st ^= 1;
    }

    // epilogue
    __nv_bfloat16* Ch = p.Ch + pq * p.sC1 + pr * p.sC2;
    __nv_bfloat16* Cl = p.Cl + pq * p.sC1 + pr * p.sC2;
    float*         Cf = p.Cf + pq * p.sC1 + pr * p.sC2;
    const int rbase = m0 + wm * 32 + (lane >> 2);
    const int cbase = n0 + wn * 64 + (lane & 3) * 2;
#pragma unroll
    for (int i = 0; i < 2; i++)
#pragma unroll
        for (int j = 0; j < 8; j++) {
            int c = cbase + j * 8;
            float b0 = 0.f, b1 = 0.f;
            if (p.bias) {
                b0 = p.bias[pr * p.biasStride + c];
                b1 = p.bias[pr * p.biasStride + c + 1];
            }
#pragma unroll
            for (int h = 0; h < 2; h++) {
                int r = rbase + i * 16 + h * 8;
                float v0 = acc[i][j][2 * h + 0] * p.alpha + b0;
                float v1 = acc[i][j][2 * h + 1] * p.alpha + b1;
                if (p.flags & 2) {
                    if (c > r)     v0 = -1e30f;
                    if (c + 1 > r) v1 = -1e30f;
                }
                if (p.flags & 1) { v0 = fmaxf(v0, 0.f); v1 = fmaxf(v1, 0.f); }
                long long off = (long long)r * p.ldc + c;
                if (p.flags & 4) *(float2*)(Cf + off) = make_float2(v0, v1);
                if (p.flags & 8) {
                    __nv_bfloat16 h0 = __float2bfloat16(v0), h1 = __float2bfloat16(v1);
                    __nv_bfloat162 hh; hh.x = h0; hh.y = h1;
                    __nv_bfloat162 ll;
                    ll.x = __float2bfloat16(v0 - __bfloat162float(h0));
                    ll.y = __float2bfloat16(v1 - __bfloat162float(h1));
                    *(__nv_bfloat162*)(Ch + off) = hh;
                    *(__nv_bfloat162*)(Cl + off) = ll;
                }
            }
        }
}

// ---------------- fp32 -> split bf16 ----------------
__global__ void cvt_k(const float4* __restrict__ in, __nv_bfloat162* __restrict__ hi,
                      __nv_bfloat162* __restrict__ lo, int n4) {
    int i = blockIdx.x * blockDim.x + threadIdx.x;
    if (i >= n4) return;
    float4 v = in[i];
    __nv_bfloat16 hx = __float2bfloat16(v.x), hy = __float2bfloat16(v.y);
    __nv_bfloat16 hz = __float2bfloat16(v.z), hw = __float2bfloat16(v.w);
    __nv_bfloat162 h0; h0.x = hx; h0.y = hy;
    __nv_bfloat162 h1; h1.x = hz; h1.y = hw;
    __nv_bfloat162 l0, l1;
    l0.x = __float2bfloat16(v.x - __bfloat162float(hx));
    l0.y = __float2bfloat16(v.y - __bfloat162float(hy));
    l1.x = __float2bfloat16(v.z - __bfloat162float(hz));
    l1.y = __float2bfloat16(v.w - __bfloat162float(hw));
    hi[2 * i] = h0; hi[2 * i + 1] = h1;
    lo[2 * i] = l0; lo[2 * i + 1] = l1;
}

// ---------------- softmax over 1024 cols (split in/out) ----------------
__global__ __launch_bounds__(256)
void softmax_k(__nv_bfloat162* H, __nv_bfloat162* L) {
    __shared__ float red[8];
    const long long row = blockIdx.x;
    __nv_bfloat162* hp = H + row * 512;
    __nv_bfloat162* lp = L + row * 512;
    const int t = threadIdx.x, lane = t & 31, w = t >> 5;
    __nv_bfloat162 h0 = hp[t], h1 = hp[t + 256], l0 = lp[t], l1 = lp[t + 256];
    float v[4] = { __bfloat162float(h0.x) + __bfloat162float(l0.x),
                   __bfloat162float(h0.y) + __bfloat162float(l0.y),
                   __bfloat162float(h1.x) + __bfloat162float(l1.x),
                   __bfloat162float(h1.y) + __bfloat162float(l1.y) };

    float mx = fmaxf(fmaxf(v[0], v[1]), fmaxf(v[2], v[3]));
#pragma unroll
    for (int o = 16; o; o >>= 1) mx = fmaxf(mx, __shfl_xor_sync(~0u, mx, o));
    if (lane == 0) red[w] = mx;
    __syncthreads();
    float m2 = red[lane & 7];
#pragma unroll
    for (int o = 4; o; o >>= 1) m2 = fmaxf(m2, __shfl_xor_sync(~0u, m2, o));
    mx = m2;
    __syncthreads();

    float s = 0.f;
#pragma unroll
    for (int q = 0; q < 4; q++) { v[q] = __expf(v[q] - mx); s += v[q]; }
#pragma unroll
    for (int o = 16; o; o >>= 1) s += __shfl_xor_sync(~0u, s, o);
    if (lane == 0) red[w] = s;
    __syncthreads();
    float s2 = red[lane & 7];
#pragma unroll
    for (int o = 4; o; o >>= 1) s2 += __shfl_xor_sync(~0u, s2, o);
    float inv = 1.f / s2;
#pragma unroll
    for (int q = 0; q < 4; q++) v[q] *= inv;

    __nv_bfloat162 oh0, oh1, ol0, ol1;
    oh0.x = __float2bfloat16(v[0]); oh0.y = __float2bfloat16(v[1]);
    oh1.x = __float2bfloat16(v[2]); oh1.y = __float2bfloat16(v[3]);
    ol0.x = __float2bfloat16(v[0] - __bfloat162float(oh0.x));
    ol0.y = __float2bfloat16(v[1] - __bfloat162float(oh0.y));
    ol1.x = __float2bfloat16(v[2] - __bfloat162float(oh1.x));
    ol1.y = __float2bfloat16(v[3] - __bfloat162float(oh1.y));
    hp[t] = oh0; hp[t + 256] = oh1;
    lp[t] = ol0; lp[t + 256] = ol1;
}

// ---------------- residual add + LayerNorm (D=512) ----------------
__device__ __forceinline__ float bsum(float val, float* red) {
    const int lane = threadIdx.x & 31, w = threadIdx.x >> 5;
#pragma unroll
    for (int o = 16; o; o >>= 1) val += __shfl_xor_sync(~0u, val, o);
    if (lane == 0) red[w] = val;
    __syncthreads();
    float s = red[lane & 7];
#pragma unroll
    for (int o = 4; o; o >>= 1) s += __shfl_xor_sync(~0u, s, o);
    __syncthreads();
    return s;
}

__global__ __launch_bounds__(256)
void add_ln_k(const float2* __restrict__ a, const float2* __restrict__ r,
              const float* __restrict__ g, const float* __restrict__ b,
              float2* __restrict__ o, __nv_bfloat162* oh, __nv_bfloat162* ol) {
    __shared__ float red[8];
    const long long row = blockIdx.x;
    const int t = threadIdx.x;
    float2 va = a[row * 256 + t], vr = r[row * 256 + t];
    float x0 = va.x + vr.x, x1 = va.y + vr.y;
    float mean = bsum(x0 + x1, red) * (1.f / 512.f);
    float d0 = x0 - mean, d1 = x1 - mean;
    float var = bsum(d0 * d0 + d1 * d1, red) * (1.f / 512.f);
    float inv = rsqrtf(var + 1e-5f);
    float y0 = d0 * inv * g[2 * t] + b[2 * t];
    float y1 = d1 * inv * g[2 * t + 1] + b[2 * t + 1];
    o[row * 256 + t] = make_float2(y0, y1);
    if (oh) {
        __nv_bfloat162 hh, ll;
        hh.x = __float2bfloat16(y0); hh.y = __float2bfloat16(y1);
        ll.x = __float2bfloat16(y0 - __bfloat162float(hh.x));
        ll.y = __float2bfloat16(y1 - __bfloat162float(hh.y));
        oh[row * 256 + t] = hh; ol[row * 256 + t] = ll;
    }
}

// ---------------- host ----------------
static void launch_gemm(bool nt, const GemmP& p, int M, int N, int batch) {
    dim3 g(N / 128, M / 128, batch);
    if (nt) gemm_k<true><<<g, 256, SMEM_BYTES>>>(p);
    else    gemm_k<false><<<g, 256, SMEM_BYTES>>>(p);
}
static void cvt(const float* src, __nv_bfloat16* h, __nv_bfloat16* l, long long n) {
    int n4 = (int)(n / 4);
    cvt_k<<<(n4 + 255) / 256, 256>>>((const float4*)src, (__nv_bfloat162*)h,
                                     (__nv_bfloat162*)l, n4);
}

extern "C" void kernel_launch(void* const* d_in, const int* in_sizes, int n_in,
                              void* d_out, int out_size) {
    const float* x   = (const float*)d_in[0];
    const float* enc = (const float*)d_in[1];
    const float* sa_wq = (const float*)d_in[2];  const float* sa_bq = (const float*)d_in[3];
    const float* sa_wk = (const float*)d_in[4];  const float* sa_bk = (const float*)d_in[5];
    const float* sa_wv = (const float*)d_in[6];  const float* sa_bv = (const float*)d_in[7];
    const float* sa_wo = (const float*)d_in[8];  const float* sa_bo = (const float*)d_in[9];
    const float* sa_wf = (const float*)d_in[10]; const float* sa_bf = (const float*)d_in[11];
    const float* ca_wq = (const float*)d_in[12]; const float* ca_bq = (const float*)d_in[13];
    const float* ca_wk = (const float*)d_in[14]; const float* ca_bk = (const float*)d_in[15];
    const float* ca_wv = (const float*)d_in[16]; const float* ca_bv = (const float*)d_in[17];
    const float* ca_wo = (const float*)d_in[18]; const float* ca_bo = (const float*)d_in[19];
    const float* ca_wf = (const float*)d_in[20]; const float* ca_bf = (const float*)d_in[21];
    const float* ln1_g = (const float*)d_in[22]; const float* ln1_b = (const float*)d_in[23];
    const float* ln2_g = (const float*)d_in[24]; const float* ln2_b = (const float*)d_in[25];
    const float* ln3_g = (const float*)d_in[26]; const float* ln3_b = (const float*)d_in[27];
    const float* fc1_w = (const float*)d_in[28]; const float* fc1_b = (const float*)d_in[29];
    const float* fc2_w = (const float*)d_in[30]; const float* fc2_b = (const float*)d_in[31];

    cudaFuncSetAttribute((const void*)gemm_k<true>,
                         cudaFuncAttributeMaxDynamicSharedMemorySize, SMEM_BYTES);
    cudaFuncSetAttribute((const void*)gemm_k<false>,
                         cudaFuncAttributeMaxDynamicSharedMemorySize, SMEM_BYTES);

    __nv_bfloat16 *Qh, *Ql, *Kh, *Kl, *Vh, *Vl, *Sh, *Sl, *Oh, *Ol, *Ph, *Pl;
    __nv_bfloat16 *Mh, *Ml, *Wh, *Wl, *xh, *xl, *eh, *el, *X1h, *X1l, *X2h, *X2l;
    float *Hf, *X1f, *X2f;
    cudaGetSymbolAddress((void**)&Qh, g_Qh);  cudaGetSymbolAddress((void**)&Ql, g_Ql);
    cudaGetSymbolAddress((void**)&Kh, g_Kh);  cudaGetSymbolAddress((void**)&Kl, g_Kl);
    cudaGetSymbolAddress((void**)&Vh, g_Vh);  cudaGetSymbolAddress((void**)&Vl, g_Vl);
    cudaGetSymbolAddress((void**)&Sh, g_Sh);  cudaGetSymbolAddress((void**)&Sl, g_Sl);
    cudaGetSymbolAddress((void**)&Oh, g_Oh);  cudaGetSymbolAddress((void**)&Ol, g_Ol);
    cudaGetSymbolAddress((void**)&Ph, g_Ph);  cudaGetSymbolAddress((void**)&Pl, g_Pl);
    cudaGetSymbolAddress((void**)&Mh, g_Mh);  cudaGetSymbolAddress((void**)&Ml, g_Ml);
    cudaGetSymbolAddress((void**)&Wh, g_Wh);  cudaGetSymbolAddress((void**)&Wl, g_Wl);
    cudaGetSymbolAddress((void**)&xh, g_xh);  cudaGetSymbolAddress((void**)&xl, g_xl);
    cudaGetSymbolAddress((void**)&eh, g_eh);  cudaGetSymbolAddress((void**)&el, g_el);
    cudaGetSymbolAddress((void**)&X1h, g_X1h); cudaGetSymbolAddress((void**)&X1l, g_X1l);
    cudaGetSymbolAddress((void**)&X2h, g_X2h); cudaGetSymbolAddress((void**)&X2l, g_X2l);
    cudaGetSymbolAddress((void**)&Hf, g_Hf);
    cudaGetSymbolAddress((void**)&X1f, g_X1f);
    cudaGetSymbolAddress((void**)&X2f, g_X2f);

    // ---- conversions (inputs + weights) ----
    cvt(x,   xh, xl, 2097152); cvt(enc, eh, el, 2097152);
    cvt(sa_wq, Wh + OW_SAQ, Wl + OW_SAQ, 2097152);
    cvt(sa_wk, Wh + OW_SAK, Wl + OW_SAK, 2097152);
    cvt(sa_wv, Wh + OW_SAV, Wl + OW_SAV, 2097152);
    cvt(sa_wo, Wh + OW_SAO, Wl + OW_SAO, 2097152);
    cvt(sa_wf, Wh + OW_SAF, Wl + OW_SAF, 2097152);
    cvt(ca_wq, Wh + OW_CAQ, Wl + OW_CAQ, 2097152);
    cvt(ca_wk, Wh + OW_CAK, Wl + OW_CAK, 2097152);
    cvt(ca_wv, Wh + OW_CAV, Wl + OW_CAV, 2097152);
    cvt(ca_wo, Wh + OW_CAO, Wl + OW_CAO, 2097152);
    cvt(ca_wf, Wh + OW_CAF, Wl + OW_CAF, 2097152);
    cvt(fc1_w, Wh + OW_FC1, Wl + OW_FC1, 1048576);
    cvt(fc2_w, Wh + OW_FC2, Wl + OW_FC2, 1048576);

    const float ISC = 0.044194173824159216f;  // 1/sqrt(512)

    auto runMHA = [&](const __nv_bfloat16* aqh, const __nv_bfloat16* aql,
                      const __nv_bfloat16* akh, const __nv_bfloat16* akl,
                      long long oq, long long ok, long long ov, long long oo, long long of,
                      const float* bq, const float* bk, const float* bv,
                      const float* bo, const float* bfb, bool causal) {
        GemmP p{};
        // Q projection (batch over heads)
        p.Ah = aqh; p.Al = aql; p.Bh = Wh + oq; p.Bl = Wl + oq; p.bias = bq;
        p.Ch = Qh; p.Cl = Ql; p.Cf = nullptr;
        p.K = 512; p.lda = 512; p.ldb = 512; p.ldc = 4096;
        p.sA1 = 0; p.sA2 = 0; p.sB1 = 0; p.sB2 = 262144; p.sC1 = 0; p.sC2 = 512;
        p.div = 8; p.biasStride = 512; p.alpha = 1.f; p.flags = 8;
        launch_gemm(false, p, 4096, 512, 8);
        // K projection
        p.Ah = akh; p.Al = akl; p.Bh = Wh + ok; p.Bl = Wl + ok; p.bias = bk;
        p.Ch = Kh; p.Cl = Kl;
        launch_gemm(false, p, 4096, 512, 8);
        // V projection
        p.Bh = Wh + ov; p.Bl = Wl + ov; p.bias = bv; p.Ch = Vh; p.Cl = Vl;
        launch_gemm(false, p, 4096, 512, 8);
        // scores = Q K^T / sqrt(512)  (NT, batch 32, causal option)
        p = GemmP{};
        p.Ah = Qh; p.Al = Ql; p.Bh = Kh; p.Bl = Kl; p.bias = nullptr;
        p.Ch = Sh; p.Cl = Sl; p.Cf = nullptr;
        p.K = 512; p.lda = 4096; p.ldb = 4096; p.ldc = 1024;
        p.sA1 = 4194304; p.sA2 = 512; p.sB1 = 4194304; p.sB2 = 512;
        p.sC1 = 8388608; p.sC2 = 1048576;
        p.div = 8; p.biasStride = 0; p.alpha = ISC; p.flags = causal ? (8 | 2) : 8;
        launch_gemm(true, p, 1024, 1024, 32);
        softmax_k<<<32768, 256>>>((__nv_bfloat162*)Sh, (__nv_bfloat162*)Sl);
        // O = A V
        p = GemmP{};
        p.Ah = Sh; p.Al = Sl; p.Bh = Vh; p.Bl = Vl; p.bias = nullptr;
        p.Ch = Oh; p.Cl = Ol; p.Cf = nullptr;
        p.K = 1024; p.lda = 1024; p.ldb = 4096; p.ldc = 4096;
        p.sA1 = 8388608; p.sA2 = 1048576; p.sB1 = 4194304; p.sB2 = 512;
        p.sC1 = 4194304; p.sC2 = 512;
        p.div = 8; p.biasStride = 0; p.alpha = 1.f; p.flags = 8;
        launch_gemm(false, p, 1024, 512, 32);
        // per-head out projection
        p = GemmP{};
        p.Ah = Oh; p.Al = Ol; p.Bh = Wh + oo; p.Bl = Wl + oo; p.bias = bo;
        p.Ch = Ph; p.Cl = Pl; p.Cf = nullptr;
        p.K = 512; p.lda = 4096; p.ldb = 512; p.ldc = 4096;
        p.sA1 = 0; p.sA2 = 512; p.sB1 = 0; p.sB2 = 262144; p.sC1 = 0; p.sC2 = 512;
        p.div = 8; p.biasStride = 512; p.alpha = 1.f; p.flags = 8;
        launch_gemm(false, p, 4096, 512, 8);
        // final concat projection wf -> fp32 H
        p = GemmP{};
        p.Ah = Ph; p.Al = Pl; p.Bh = Wh + of; p.Bl = Wl + of; p.bias = bfb;
        p.Ch = nullptr; p.Cl = nullptr; p.Cf = Hf;
        p.K = 4096; p.lda = 4096; p.ldb = 512; p.ldc = 512;
        p.sA1 = 0; p.sA2 = 0; p.sB1 = 0; p.sB2 = 0; p.sC1 = 0; p.sC2 = 0;
        p.div = 1; p.biasStride = 0; p.alpha = 1.f; p.flags = 4;
        launch_gemm(false, p, 4096, 512, 1);
    };

    // self-attention (causal) + LN1
    runMHA(xh, xl, xh, xl, OW_SAQ, OW_SAK, OW_SAV, OW_SAO, OW_SAF,
           sa_bq, sa_bk, sa_bv, sa_bo, sa_bf, true);
    add_ln_k<<<4096, 256>>>((const float2*)Hf, (const float2*)x, ln1_g, ln1_b,
                            (float2*)X1f, (__nv_bfloat162*)X1h, (__nv_bfloat162*)X1l);

    // cross-attention + LN2
    runMHA(X1h, X1l, eh, el, OW_CAQ, OW_CAK, OW_CAV, OW_CAO, OW_CAF,
           ca_bq, ca_bk, ca_bv, ca_bo, ca_bf, false);
    add_ln_k<<<4096, 256>>>((const float2*)Hf, (const float2*)X1f, ln2_g, ln2_b,
                            (float2*)X2f, (__nv_bfloat162*)X2h, (__nv_bfloat162*)X2l);

    // FFN
    {
        GemmP p{};
        p.Ah = X2h; p.Al = X2l; p.Bh = Wh + OW_FC1; p.Bl = Wl + OW_FC1; p.bias = fc1_b;
        p.Ch = Mh; p.Cl = Ml; p.Cf = nullptr;
        p.K = 512; p.lda = 512; p.ldb = 2048; p.ldc = 2048;
        p.div = 1; p.biasStride = 0; p.alpha = 1.f; p.flags = 8 | 1;
        launch_gemm(false, p, 4096, 2048, 1);

        p = GemmP{};
        p.Ah = Mh; p.Al = Ml; p.Bh = Wh + OW_FC2; p.Bl = Wl + OW_FC2; p.bias = fc2_b;
        p.Ch = nullptr; p.Cl = nullptr; p.Cf = Hf;
        p.K = 2048; p.lda = 2048; p.ldb = 512; p.ldc = 512;
        p.div = 1; p.biasStride = 0; p.alpha = 1.f; p.flags = 4;
        launch_gemm(false, p, 4096, 512, 1);
    }
    add_ln_k<<<4096, 256>>>((const float2*)Hf, (const float2*)X2f, ln3_g, ln3_b,
                            (float2*)d_out, nullptr, nullptr);
}

// round 4
// speedup vs baseline: 2.9983x; 1.2876x over previous
#include <cuda_runtime.h>
#include <cuda_fp16.h>
#include <math.h>

#define SMEM_BYTES 81920
#define SSTR 40

// ---------------- static scratch ----------------
__device__ __half g_Qh[16777216], g_Ql[16777216];
__device__ __half g_Kh[16777216], g_Kl[16777216];
__device__ __half g_Vh[16777216], g_Vl[16777216];
__device__ __half g_Sh[33554432];                     // scores/probs hi only
__device__ __half g_Oh[16777216];
__device__ __half g_Ph[16777216];
__device__ __half g_Mh[8388608];
__device__ __half g_Wh[23068672], g_Wl[23068672];     // all weights split
__device__ __half g_xh[2097152], g_eh[2097152], g_X1h[2097152], g_X2h[2097152];
__device__ float g_Hf[2097152], g_X1f[2097152], g_X2f[2097152];

#define OW_SAQ 0LL
#define OW_SAK 2097152LL
#define OW_SAV 4194304LL
#define OW_SAO 6291456LL
#define OW_SAF 8388608LL
#define OW_CAQ 10485760LL
#define OW_CAK 12582912LL
#define OW_CAV 14680064LL
#define OW_CAO 16777216LL
#define OW_CAF 18874368LL
#define OW_FC1 20971520LL
#define OW_FC2 22020096LL

// ---------------- PTX helpers ----------------
__device__ __forceinline__ void mma16816(float* d, const unsigned* a, const unsigned* b) {
    asm volatile(
        "mma.sync.aligned.m16n8k16.row.col.f32.f16.f16.f32 "
        "{%0,%1,%2,%3}, {%4,%5,%6,%7}, {%8,%9}, {%0,%1,%2,%3};"
        : "+f"(d[0]), "+f"(d[1]), "+f"(d[2]), "+f"(d[3])
        : "r"(a[0]), "r"(a[1]), "r"(a[2]), "r"(a[3]), "r"(b[0]), "r"(b[1]));
}
__device__ __forceinline__ void ldsm4(unsigned* r, unsigned a) {
    asm volatile("ldmatrix.sync.aligned.m8n8.x4.shared.b16 {%0,%1,%2,%3}, [%4];"
                 : "=r"(r[0]), "=r"(r[1]), "=r"(r[2]), "=r"(r[3]) : "r"(a));
}
__device__ __forceinline__ void cp16(unsigned d, const void* s) {
    asm volatile("cp.async.cg.shared.global [%0], [%1], 16;" :: "r"(d), "l"(s));
}
__device__ __forceinline__ __half2 split_hi2(float v0, float v1, __half2& lo) {
    __half h0 = __float2half(v0), h1 = __float2half(v1);
    __half2 hh; hh.x = h0; hh.y = h1;
    lo.x = __float2half(v0 - __half2float(h0));
    lo.y = __float2half(v1 - __half2float(h1));
    return hh;
}

// ---------------- split-fp16 GEMM ----------------
// C = alpha * A*B + bias
// TERMS=2: C ~= Ahi*(Bhi+Blo)    (A hi-only)
// TERMS=3: C ~= Ahi*Bhi + Ahi*Blo + Alo*Bhi
// NT=true : B stored [N,K] row-major; NT=false: B stored [K,N] (register transpose)
// flags: 1 relu, 2 causal, 4 fp32 out, 8 split out, 16 hi-only out
struct GemmP {
    const __half *Ah, *Al, *Bh, *Bl;
    const float* bias;
    __half *Ch, *Cl;
    float* Cf;
    int K, lda, ldb, ldc;
    long long sA1, sA2, sB1, sB2, sC1, sC2;
    int div, biasStride;
    float alpha; int flags;
};

template<bool NT, int TERMS>
__global__ __launch_bounds__(256) void gemm_k(GemmP p) {
    extern __shared__ unsigned char raw[];
    __half* As = (__half*)raw;                 // [(st*2+hl)*128+m]*SSTR + k
    __half* Bs = As + 4 * 128 * SSTR;

    const int pb = blockIdx.z, pq = pb / p.div, pr = pb - pq * p.div;
    const int tid = threadIdx.x, lane = tid & 31, warp = tid >> 5;
    const int wm = warp >> 1, wn = warp & 1;
    const int m0 = blockIdx.y * 128, n0 = blockIdx.x * 128;

    // fully-masked causal tile: write -inf, skip compute
    if ((p.flags & 2) && n0 > m0 + 127) {
        __half2* Ch2 = (__half2*)(p.Ch + pq * p.sC1 + pr * p.sC2);
        const __half2 mi = __half2half2(__float2half(-1e30f));   // -> -inf
        for (int i = tid; i < 128 * 64; i += 256) {
            int r = i >> 6, c = i & 63;
            Ch2[((long long)(m0 + r) * p.ldc + n0) / 2 + c] = mi;
        }
        return;
    }

    const __half* Abase[2] = { p.Ah + pq * p.sA1 + pr * p.sA2,
                               (TERMS == 3) ? p.Al + pq * p.sA1 + pr * p.sA2 : nullptr };
    const __half* Bbase[2] = { p.Bh + pq * p.sB1 + pr * p.sB2,
                               p.Bl + pq * p.sB1 + pr * p.sB2 };

    const unsigned sA = (unsigned)__cvta_generic_to_shared(As);
    const unsigned sB = (unsigned)__cvta_generic_to_shared(Bs);

    const int crow = tid >> 2, cseg = (tid & 3) * 8;
    const int tn = (tid & 63) * 2, tk0 = (tid >> 6) * 8;

    float acc[2][8][4];
#pragma unroll
    for (int i = 0; i < 2; i++)
#pragma unroll
        for (int j = 0; j < 8; j++)
#pragma unroll
            for (int q = 0; q < 4; q++) acc[i][j][q] = 0.f;

    unsigned trh[8], trl[8];

    auto issue_stage = [&](int st, int kt) {
#pragma unroll
        for (int hl = 0; hl < TERMS - 1; hl++)
#pragma unroll
            for (int r = 0; r < 2; r++) {
                int row = crow + r * 64;
                cp16(sA + 2u * (((st * 2 + hl) * 128 + row) * SSTR + cseg),
                     Abase[hl] + (long long)(m0 + row) * p.lda + kt + cseg);
            }
        if (NT) {
#pragma unroll
            for (int hl = 0; hl < 2; hl++)
#pragma unroll
                for (int r = 0; r < 2; r++) {
                    int row = crow + r * 64;
                    cp16(sB + 2u * (((st * 2 + hl) * 128 + row) * SSTR + cseg),
                         Bbase[hl] + (long long)(n0 + row) * p.ldb + kt + cseg);
                }
        }
        asm volatile("cp.async.commit_group;");
    };
    auto load_trans = [&](int kt) {
#pragma unroll
        for (int kk = 0; kk < 8; kk++) {
            int k = tk0 + kk;
            trh[kk] = *(const unsigned*)(Bbase[0] + (long long)(kt + k) * p.ldb + n0 + tn);
            trl[kk] = *(const unsigned*)(Bbase[1] + (long long)(kt + k) * p.ldb + n0 + tn);
        }
    };
    auto store_trans = [&](int st) {
#pragma unroll
        for (int kk = 0; kk < 8; kk++) {
            int k = tk0 + kk;
            __half2 h = *(__half2*)&trh[kk];
            __half2 l = *(__half2*)&trl[kk];
            Bs[((st * 2 + 0) * 128 + tn) * SSTR + k]     = h.x;
            Bs[((st * 2 + 0) * 128 + tn + 1) * SSTR + k] = h.y;
            Bs[((st * 2 + 1) * 128 + tn) * SSTR + k]     = l.x;
            Bs[((st * 2 + 1) * 128 + tn + 1) * SSTR + k] = l.y;
        }
    };

    issue_stage(0, 0);
    if (!NT) load_trans(0);
    asm volatile("cp.async.wait_group 0;" ::: "memory");
    if (!NT) store_trans(0);
    __syncthreads();

    int st = 0;
    for (int kt = 0; kt < p.K; kt += 32) {
        const int nxt = kt + 32;
        const bool more = nxt < p.K;
        if (more) {
            issue_stage(st ^ 1, nxt);
            if (!NT) load_trans(nxt);
        }
#pragma unroll
        for (int ks = 0; ks < 32; ks += 16) {
            unsigned ah[2][4], alr[2][4], bh[8][2], blr[8][2];
#pragma unroll
            for (int i = 0; i < 2; i++) {
                int row = wm * 32 + i * 16 + (lane & 15);
                int ko = ks + (lane >> 4) * 8;
                ldsm4(ah[i], sA + 2u * (((st * 2 + 0) * 128 + row) * SSTR + ko));
                if (TERMS == 3)
                    ldsm4(alr[i], sA + 2u * (((st * 2 + 1) * 128 + row) * SSTR + ko));
            }
#pragma unroll
            for (int jj = 0; jj < 4; jj++) {
                int row = wn * 64 + jj * 16 + (lane & 7) + ((lane >> 4) & 1) * 8;
                int ko = ks + ((lane >> 3) & 1) * 8;
                unsigned t0[4];
                ldsm4(t0, sB + 2u * (((st * 2 + 0) * 128 + row) * SSTR + ko));
                bh[2 * jj][0] = t0[0]; bh[2 * jj][1] = t0[1];
                bh[2 * jj + 1][0] = t0[2]; bh[2 * jj + 1][1] = t0[3];
                ldsm4(t0, sB + 2u * (((st * 2 + 1) * 128 + row) * SSTR + ko));
                blr[2 * jj][0] = t0[0]; blr[2 * jj][1] = t0[1];
                blr[2 * jj + 1][0] = t0[2]; blr[2 * jj + 1][1] = t0[3];
            }
#pragma unroll
            for (int i = 0; i < 2; i++)
#pragma unroll
                for (int j = 0; j < 8; j++) {
                    mma16816(acc[i][j], ah[i], bh[j]);
                    mma16816(acc[i][j], ah[i], blr[j]);
                    if (TERMS == 3) mma16816(acc[i][j], alr[i], bh[j]);
                }
        }
        if (more) {
            asm volatile("cp.async.wait_group 0;" ::: "memory");
            if (!NT) store_trans(st ^ 1);
            __syncthreads();
        }
        st ^= 1;
    }

    // epilogue
    __half* Ch = p.Ch + pq * p.sC1 + pr * p.sC2;
    __half* Cl = (p.flags & 8) ? p.Cl + pq * p.sC1 + pr * p.sC2 : nullptr;
    float*  Cf = (p.flags & 4) ? p.Cf + pq * p.sC1 + pr * p.sC2 : nullptr;
    const int rbase = m0 + wm * 32 + (lane >> 2);
    const int cbase = n0 + wn * 64 + (lane & 3) * 2;
#pragma unroll
    for (int i = 0; i < 2; i++)
#pragma unroll
        for (int j = 0; j < 8; j++) {
            int c = cbase + j * 8;
            float b0 = 0.f, b1 = 0.f;
            if (p.bias) {
                b0 = p.bias[pr * p.biasStride + c];
                b1 = p.bias[pr * p.biasStride + c + 1];
            }
#pragma unroll
            for (int h = 0; h < 2; h++) {
                int r = rbase + i * 16 + h * 8;
                float v0 = acc[i][j][2 * h + 0] * p.alpha + b0;
                float v1 = acc[i][j][2 * h + 1] * p.alpha + b1;
                if (p.flags & 2) {
                    if (c > r)     v0 = -1e30f;
                    if (c + 1 > r) v1 = -1e30f;
                }
                if (p.flags & 1) { v0 = fmaxf(v0, 0.f); v1 = fmaxf(v1, 0.f); }
                long long off = (long long)r * p.ldc + c;
                if (p.flags & 4) *(float2*)(Cf + off) = make_float2(v0, v1);
                else if (p.flags & 8) {
                    __half2 lo;
                    __half2 hi = split_hi2(v0, v1, lo);
                    *(__half2*)(Ch + off) = hi;
                    *(__half2*)(Cl + off) = lo;
                } else {
                    __half2 hi; hi.x = __float2half(v0); hi.y = __float2half(v1);
                    *(__half2*)(Ch + off) = hi;
                }
            }
        }
}

// ---------------- fp32 -> fp16 converters ----------------
__global__ void cvt_hi_k(const float4* __restrict__ in, __half2* __restrict__ hi, int n4) {
    int i = blockIdx.x * blockDim.x + threadIdx.x;
    if (i >= n4) return;
    float4 v = in[i];
    __half2 h0; h0.x = __float2half(v.x); h0.y = __float2half(v.y);
    __half2 h1; h1.x = __float2half(v.z); h1.y = __float2half(v.w);
    hi[2 * i] = h0; hi[2 * i + 1] = h1;
}
__global__ void cvt_sp_k(const float4* __restrict__ in, __half2* __restrict__ hi,
                         __half2* __restrict__ lo, int n4) {
    int i = blockIdx.x * blockDim.x + threadIdx.x;
    if (i >= n4) return;
    float4 v = in[i];
    __half2 l0, l1;
    __half2 h0 = split_hi2(v.x, v.y, l0);
    __half2 h1 = split_hi2(v.z, v.w, l1);
    hi[2 * i] = h0; hi[2 * i + 1] = h1;
    lo[2 * i] = l0; lo[2 * i + 1] = l1;
}

// ---------------- softmax over 1024 cols (fp16 hi in/out) ----------------
__global__ __launch_bounds__(256)
void softmax_k(__half2* S) {
    __shared__ float red[8];
    const long long row = blockIdx.x;
    __half2* sp = S + row * 512;
    const int t = threadIdx.x, lane = t & 31, w = t >> 5;
    __half2 h0 = sp[t], h1 = sp[t + 256];
    float v[4] = { __half2float(h0.x), __half2float(h0.y),
                   __half2float(h1.x), __half2float(h1.y) };

    float mx = fmaxf(fmaxf(v[0], v[1]), fmaxf(v[2], v[3]));
#pragma unroll
    for (int o = 16; o; o >>= 1) mx = fmaxf(mx, __shfl_xor_sync(~0u, mx, o));
    if (lane == 0) red[w] = mx;
    __syncthreads();
    float m2 = red[lane & 7];
#pragma unroll
    for (int o = 4; o; o >>= 1) m2 = fmaxf(m2, __shfl_xor_sync(~0u, m2, o));
    mx = m2;
    __syncthreads();

    float s = 0.f;
#pragma unroll
    for (int q = 0; q < 4; q++) { v[q] = __expf(v[q] - mx); s += v[q]; }
#pragma unroll
    for (int o = 16; o; o >>= 1) s += __shfl_xor_sync(~0u, s, o);
    if (lane == 0) red[w] = s;
    __syncthreads();
    float s2 = red[lane & 7];
#pragma unroll
    for (int o = 4; o; o >>= 1) s2 += __shfl_xor_sync(~0u, s2, o);
    float inv = 1.f / s2;

    __half2 o0, o1;
    o0.x = __float2half(v[0] * inv); o0.y = __float2half(v[1] * inv);
    o1.x = __float2half(v[2] * inv); o1.y = __float2half(v[3] * inv);
    sp[t] = o0; sp[t + 256] = o1;
}

// ---------------- residual add + LayerNorm (D=512) ----------------
__device__ __forceinline__ float bsum(float val, float* red) {
    const int lane = threadIdx.x & 31, w = threadIdx.x >> 5;
#pragma unroll
    for (int o = 16; o; o >>= 1) val += __shfl_xor_sync(~0u, val, o);
    if (lane == 0) red[w] = val;
    __syncthreads();
    float s = red[lane & 7];
#pragma unroll
    for (int o = 4; o; o >>= 1) s += __shfl_xor_sync(~0u, s, o);
    __syncthreads();
    return s;
}

__global__ __launch_bounds__(256)
void add_ln_k(const float2* __restrict__ a, const float2* __restrict__ r,
              const float* __restrict__ g, const float* __restrict__ b,
              float2* __restrict__ o, __half2* oh) {
    __shared__ float red[8];
    const long long row = blockIdx.x;
    const int t = threadIdx.x;
    float2 va = a[row * 256 + t], vr = r[row * 256 + t];
    float x0 = va.x + vr.x, x1 = va.y + vr.y;
    float mean = bsum(x0 + x1, red) * (1.f / 512.f);
    float d0 = x0 - mean, d1 = x1 - mean;
    float var = bsum(d0 * d0 + d1 * d1, red) * (1.f / 512.f);
    float inv = rsqrtf(var + 1e-5f);
    float y0 = d0 * inv * g[2 * t] + b[2 * t];
    float y1 = d1 * inv * g[2 * t + 1] + b[2 * t + 1];
    o[row * 256 + t] = make_float2(y0, y1);
    if (oh) {
        __half2 hh; hh.x = __float2half(y0); hh.y = __float2half(y1);
        oh[row * 256 + t] = hh;
    }
}

// ---------------- host ----------------
static void launch_gemm(bool nt3, const GemmP& p, int M, int N, int batch) {
    dim3 g(N / 128, M / 128, batch);
    if (nt3) gemm_k<true, 3><<<g, 256, SMEM_BYTES>>>(p);
    else     gemm_k<false, 2><<<g, 256, SMEM_BYTES>>>(p);
}
static void cvt_hi(const float* src, __half* h, long long n) {
    int n4 = (int)(n / 4);
    cvt_hi_k<<<(n4 + 255) / 256, 256>>>((const float4*)src, (__half2*)h, n4);
}
static void cvt_sp(const float* src, __half* h, __half* l, long long n) {
    int n4 = (int)(n / 4);
    cvt_sp_k<<<(n4 + 255) / 256, 256>>>((const float4*)src, (__half2*)h, (__half2*)l, n4);
}

extern "C" void kernel_launch(void* const* d_in, const int* in_sizes, int n_in,
                              void* d_out, int out_size) {
    const float* x   = (const float*)d_in[0];
    const float* enc = (const float*)d_in[1];
    const float* sa_wq = (const float*)d_in[2];  const float* sa_bq = (const float*)d_in[3];
    const float* sa_wk = (const float*)d_in[4];  const float* sa_bk = (const float*)d_in[5];
    const float* sa_wv = (const float*)d_in[6];  const float* sa_bv = (const float*)d_in[7];
    const float* sa_wo = (const float*)d_in[8];  const float* sa_bo = (const float*)d_in[9];
    const float* sa_wf = (const float*)d_in[10]; const float* sa_bf = (const float*)d_in[11];
    const float* ca_wq = (const float*)d_in[12]; const float* ca_bq = (const float*)d_in[13];
    const float* ca_wk = (const float*)d_in[14]; const float* ca_bk = (const float*)d_in[15];
    const float* ca_wv = (const float*)d_in[16]; const float* ca_bv = (const float*)d_in[17];
    const float* ca_wo = (const float*)d_in[18]; const float* ca_bo = (const float*)d_in[19];
    const float* ca_wf = (const float*)d_in[20]; const float* ca_bf = (const float*)d_in[21];
    const float* ln1_g = (const float*)d_in[22]; const float* ln1_b = (const float*)d_in[23];
    const float* ln2_g = (const float*)d_in[24]; const float* ln2_b = (const float*)d_in[25];
    const float* ln3_g = (const float*)d_in[26]; const float* ln3_b = (const float*)d_in[27];
    const float* fc1_w = (const float*)d_in[28]; const float* fc1_b = (const float*)d_in[29];
    const float* fc2_w = (const float*)d_in[30]; const float* fc2_b = (const float*)d_in[31];

    cudaFuncSetAttribute((const void*)gemm_k<true, 3>,
                         cudaFuncAttributeMaxDynamicSharedMemorySize, SMEM_BYTES);
    cudaFuncSetAttribute((const void*)gemm_k<false, 2>,
                         cudaFuncAttributeMaxDynamicSharedMemorySize, SMEM_BYTES);

    __half *Qh, *Ql, *Kh, *Kl, *Vh, *Vl, *Sh, *Oh, *Ph, *Mh, *Wh, *Wl;
    __half *xh, *eh, *X1h, *X2h;
    float *Hf, *X1f, *X2f;
    cudaGetSymbolAddress((void**)&Qh, g_Qh);  cudaGetSymbolAddress((void**)&Ql, g_Ql);
    cudaGetSymbolAddress((void**)&Kh, g_Kh);  cudaGetSymbolAddress((void**)&Kl, g_Kl);
    cudaGetSymbolAddress((void**)&Vh, g_Vh);  cudaGetSymbolAddress((void**)&Vl, g_Vl);
    cudaGetSymbolAddress((void**)&Sh, g_Sh);
    cudaGetSymbolAddress((void**)&Oh, g_Oh);
    cudaGetSymbolAddress((void**)&Ph, g_Ph);
    cudaGetSymbolAddress((void**)&Mh, g_Mh);
    cudaGetSymbolAddress((void**)&Wh, g_Wh);  cudaGetSymbolAddress((void**)&Wl, g_Wl);
    cudaGetSymbolAddress((void**)&xh, g_xh);  cudaGetSymbolAddress((void**)&eh, g_eh);
    cudaGetSymbolAddress((void**)&X1h, g_X1h); cudaGetSymbolAddress((void**)&X2h, g_X2h);
    cudaGetSymbolAddress((void**)&Hf, g_Hf);
    cudaGetSymbolAddress((void**)&X1f, g_X1f);
    cudaGetSymbolAddress((void**)&X2f, g_X2f);

    // conversions
    cvt_hi(x,   xh, 2097152); cvt_hi(enc, eh, 2097152);
    cvt_sp(sa_wq, Wh + OW_SAQ, Wl + OW_SAQ, 2097152);
    cvt_sp(sa_wk, Wh + OW_SAK, Wl + OW_SAK, 2097152);
    cvt_sp(sa_wv, Wh + OW_SAV, Wl + OW_SAV, 2097152);
    cvt_sp(sa_wo, Wh + OW_SAO, Wl + OW_SAO, 2097152);
    cvt_sp(sa_wf, Wh + OW_SAF, Wl + OW_SAF, 2097152);
    cvt_sp(ca_wq, Wh + OW_CAQ, Wl + OW_CAQ, 2097152);
    cvt_sp(ca_wk, Wh + OW_CAK, Wl + OW_CAK, 2097152);
    cvt_sp(ca_wv, Wh + OW_CAV, Wl + OW_CAV, 2097152);
    cvt_sp(ca_wo, Wh + OW_CAO, Wl + OW_CAO, 2097152);
    cvt_sp(ca_wf, Wh + OW_CAF, Wl + OW_CAF, 2097152);
    cvt_sp(fc1_w, Wh + OW_FC1, Wl + OW_FC1, 1048576);
    cvt_sp(fc2_w, Wh + OW_FC2, Wl + OW_FC2, 1048576);

    const float ISC = 0.044194173824159216f;  // 1/sqrt(512)

    auto runMHA = [&](const __half* aq, const __half* akv,
                      long long oq, long long ok, long long ov, long long oo, long long of,
                      const float* bq, const float* bk, const float* bv,
                      const float* bo, const float* bfb, bool causal) {
        GemmP p{};
        // Q projection -> split (Q is A of a 3-term GEMM)
        p.Ah = aq; p.Bh = Wh + oq; p.Bl = Wl + oq; p.bias = bq;
        p.Ch = Qh; p.Cl = Ql;
        p.K = 512; p.lda = 512; p.ldb = 512; p.ldc = 4096;
        p.sB2 = 262144; p.sC2 = 512;
        p.div = 8; p.biasStride = 512; p.alpha = 1.f; p.flags = 8;
        launch_gemm(false, p, 4096, 512, 8);
        // K projection -> split
        p.Ah = akv; p.Bh = Wh + ok; p.Bl = Wl + ok; p.bias = bk;
        p.Ch = Kh; p.Cl = Kl;
        launch_gemm(false, p, 4096, 512, 8);
        // V projection -> split (V is B of AV GEMM)
        p.Bh = Wh + ov; p.Bl = Wl + ov; p.bias = bv;
        p.Ch = Vh; p.Cl = Vl;
        launch_gemm(false, p, 4096, 512, 8);
        // scores = Q K^T / sqrt(512): 3-term NT, hi-only out, causal skip+mask
        p = GemmP{};
        p.Ah = Qh; p.Al = Ql; p.Bh = Kh; p.Bl = Kl;
        p.Ch = Sh;
        p.K = 512; p.lda = 4096; p.ldb = 4096; p.ldc = 1024;
        p.sA1 = 4194304; p.sA2 = 512; p.sB1 = 4194304; p.sB2 = 512;
        p.sC1 = 8388608; p.sC2 = 1048576;
        p.div = 8; p.alpha = ISC; p.flags = causal ? (16 | 2) : 16;
        launch_gemm(true, p, 1024, 1024, 32);
        softmax_k<<<32768, 256>>>((__half2*)Sh);
        // O = A V : A probs hi-only, B = V split
        p = GemmP{};
        p.Ah = Sh; p.Bh = Vh; p.Bl = Vl;
        p.Ch = Oh;
        p.K = 1024; p.lda = 1024; p.ldb = 4096; p.ldc = 4096;
        p.sA1 = 8388608; p.sA2 = 1048576; p.sB1 = 4194304; p.sB2 = 512;
        p.sC1 = 4194304; p.sC2 = 512;
        p.div = 8; p.alpha = 1.f; p.flags = 16;
        launch_gemm(false, p, 1024, 512, 32);
        // per-head out projection -> hi-only
        p = GemmP{};
        p.Ah = Oh; p.Bh = Wh + oo; p.Bl = Wl + oo; p.bias = bo;
        p.Ch = Ph;
        p.K = 512; p.lda = 4096; p.ldb = 512; p.ldc = 4096;
        p.sA2 = 512; p.sB2 = 262144; p.sC2 = 512;
        p.div = 8; p.biasStride = 512; p.alpha = 1.f; p.flags = 16;
        launch_gemm(false, p, 4096, 512, 8);
        // final concat projection -> fp32 H
        p = GemmP{};
        p.Ah = Ph; p.Bh = Wh + of; p.Bl = Wl + of; p.bias = bfb;
        p.Cf = Hf;
        p.K = 4096; p.lda = 4096; p.ldb = 512; p.ldc = 512;
        p.div = 1; p.alpha = 1.f; p.flags = 4;
        launch_gemm(false, p, 4096, 512, 1);
    };

    // self-attention (causal) + LN1
    runMHA(xh, xh, OW_SAQ, OW_SAK, OW_SAV, OW_SAO, OW_SAF,
           sa_bq, sa_bk, sa_bv, sa_bo, sa_bf, true);
    add_ln_k<<<4096, 256>>>((const float2*)Hf, (const float2*)x, ln1_g, ln1_b,
                            (float2*)X1f, (__half2*)X1h);

    // cross-attention + LN2
    runMHA(X1h, eh, OW_CAQ, OW_CAK, OW_CAV, OW_CAO, OW_CAF,
           ca_bq, ca_bk, ca_bv, ca_bo, ca_bf, false);
    add_ln_k<<<4096, 256>>>((const float2*)Hf, (const float2*)X1f, ln2_g, ln2_b,
                            (float2*)X2f, (__half2*)X2h);

    // FFN
    {
        GemmP p{};
        p.Ah = X2h; p.Bh = Wh + OW_FC1; p.Bl = Wl + OW_FC1; p.bias = fc1_b;
        p.Ch = Mh;
        p.K = 512; p.lda = 512; p.ldb = 2048; p.ldc = 2048;
        p.div = 1; p.alpha = 1.f; p.flags = 16 | 1;
        launch_gemm(false, p, 4096, 2048, 1);

        p = GemmP{};
        p.Ah = Mh; p.Bh = Wh + OW_FC2; p.Bl = Wl + OW_FC2; p.bias = fc2_b;
        p.Cf = Hf;
        p.K = 2048; p.lda = 2048; p.ldb = 512; p.ldc = 512;
        p.div = 1; p.alpha = 1.f; p.flags = 4;
        launch_gemm(false, p, 4096, 512, 1);
    }
    add_ln_k<<<4096, 256>>>((const float2*)Hf, (const float2*)X2f, ln3_g, ln3_b,
                            (float2*)d_out, nullptr);
}

// round 5
// speedup vs baseline: 4.8011x; 1.6013x over previous
#include <cuda_runtime.h>
#include <cuda_fp16.h>
#include <math.h>

#define SMEM_BYTES 61440
#define SSTR 40

// ---------------- static scratch ----------------
__device__ __half g_Qh[16777216];
__device__ __half g_Kh[16777216];
__device__ __half g_Vh[16777216];
__device__ __half g_Sh[33554432];                     // scores/probs hi only
__device__ __half g_Oh[16777216];
__device__ __half g_Ph[16777216];
__device__ __half g_Mh[8388608];
__device__ __half g_Wh[23068672], g_Wl[23068672];     // weights (lo used only where split)
__device__ __half g_xh[2097152], g_eh[2097152], g_X1h[2097152], g_X2h[2097152];
__device__ float g_Hf[2097152], g_X1f[2097152], g_X2f[2097152];

#define OW_SAQ 0LL
#define OW_SAK 2097152LL
#define OW_SAV 4194304LL
#define OW_SAO 6291456LL
#define OW_SAF 8388608LL
#define OW_CAQ 10485760LL
#define OW_CAK 12582912LL
#define OW_CAV 14680064LL
#define OW_CAO 16777216LL
#define OW_CAF 18874368LL
#define OW_FC1 20971520LL
#define OW_FC2 22020096LL

// ---------------- PTX helpers ----------------
__device__ __forceinline__ void mma16816(float* d, const unsigned* a, const unsigned* b) {
    asm volatile(
        "mma.sync.aligned.m16n8k16.row.col.f32.f16.f16.f32 "
        "{%0,%1,%2,%3}, {%4,%5,%6,%7}, {%8,%9}, {%0,%1,%2,%3};"
        : "+f"(d[0]), "+f"(d[1]), "+f"(d[2]), "+f"(d[3])
        : "r"(a[0]), "r"(a[1]), "r"(a[2]), "r"(a[3]), "r"(b[0]), "r"(b[1]));
}
__device__ __forceinline__ void ldsm4(unsigned* r, unsigned a) {
    asm volatile("ldmatrix.sync.aligned.m8n8.x4.shared.b16 {%0,%1,%2,%3}, [%4];"
                 : "=r"(r[0]), "=r"(r[1]), "=r"(r[2]), "=r"(r[3]) : "r"(a));
}
__device__ __forceinline__ void cp16(unsigned d, const void* s) {
    asm volatile("cp.async.cg.shared.global [%0], [%1], 16;" :: "r"(d), "l"(s));
}
__device__ __forceinline__ __half2 split_hi2(float v0, float v1, __half2& lo) {
    __half h0 = __float2half(v0), h1 = __float2half(v1);
    __half2 hh; hh.x = h0; hh.y = h1;
    lo.x = __float2half(v0 - __half2float(h0));
    lo.y = __float2half(v1 - __half2float(h1));
    return hh;
}

// ---------------- GEMM: C = alpha * A*B + bias ----------------
// A [M,K] fp16 hi-only row-major.
// BT = number of B planes (1: hi only; 2: hi+lo -> 2 mmas)
// NT=true : B stored [N,K] row-major; NT=false: B stored [K,N] (register transpose)
// flags: 1 relu, 2 causal, 4 fp32 out, 16 fp16 hi out
struct GemmP {
    const __half *Ah, *Bh, *Bl;
    const float* bias;
    __half *Ch;
    float* Cf;
    int K, lda, ldb, ldc;
    long long sA1, sA2, sB1, sB2, sC1, sC2;
    int div, biasStride;
    float alpha; int flags;
};

template<bool NT, int BT>
__global__ __launch_bounds__(256) void gemm_k(GemmP p) {
    extern __shared__ unsigned char raw[];
    __half* As = (__half*)raw;                       // [(st)*128+m]*SSTR + k
    __half* Bs = As + 2 * 128 * SSTR;                // [(st*BT+hl)*128+n]*SSTR + k

    const int pb = blockIdx.z, pq = pb / p.div, pr = pb - pq * p.div;
    const int tid = threadIdx.x, lane = tid & 31, warp = tid >> 5;
    const int wm = warp >> 1, wn = warp & 1;
    const int m0 = blockIdx.y * 128, n0 = blockIdx.x * 128;

    // fully-masked causal tile: write -inf, skip compute
    if ((p.flags & 2) && n0 > m0 + 127) {
        __half2* Ch2 = (__half2*)(p.Ch + pq * p.sC1 + pr * p.sC2);
        const __half2 mi = __half2half2(__float2half(-1e30f));
        for (int i = tid; i < 128 * 64; i += 256) {
            int r = i >> 6, c = i & 63;
            Ch2[((long long)(m0 + r) * p.ldc + n0) / 2 + c] = mi;
        }
        return;
    }

    const __half* Abase = p.Ah + pq * p.sA1 + pr * p.sA2;
    const __half* Bbase[2] = { p.Bh + pq * p.sB1 + pr * p.sB2,
                               (BT == 2) ? p.Bl + pq * p.sB1 + pr * p.sB2 : nullptr };

    const unsigned sA = (unsigned)__cvta_generic_to_shared(As);
    const unsigned sB = (unsigned)__cvta_generic_to_shared(Bs);

    const int crow = tid >> 2, cseg = (tid & 3) * 8;
    const int tn = (tid & 63) * 2, tk0 = (tid >> 6) * 8;

    float acc[2][8][4];
#pragma unroll
    for (int i = 0; i < 2; i++)
#pragma unroll
        for (int j = 0; j < 8; j++)
#pragma unroll
            for (int q = 0; q < 4; q++) acc[i][j][q] = 0.f;

    unsigned trh[8], trl[8];

    auto issue_stage = [&](int st, int kt) {
#pragma unroll
        for (int r = 0; r < 2; r++) {
            int row = crow + r * 64;
            cp16(sA + 2u * ((st * 128 + row) * SSTR + cseg),
                 Abase + (long long)(m0 + row) * p.lda + kt + cseg);
        }
        if (NT) {
#pragma unroll
            for (int hl = 0; hl < BT; hl++)
#pragma unroll
                for (int r = 0; r < 2; r++) {
                    int row = crow + r * 64;
                    cp16(sB + 2u * (((st * BT + hl) * 128 + row) * SSTR + cseg),
                         Bbase[hl] + (long long)(n0 + row) * p.ldb + kt + cseg);
                }
        }
        asm volatile("cp.async.commit_group;");
    };
    auto load_trans = [&](int kt) {
#pragma unroll
        for (int kk = 0; kk < 8; kk++) {
            int k = tk0 + kk;
            trh[kk] = *(const unsigned*)(Bbase[0] + (long long)(kt + k) * p.ldb + n0 + tn);
            if (BT == 2)
                trl[kk] = *(const unsigned*)(Bbase[1] + (long long)(kt + k) * p.ldb + n0 + tn);
        }
    };
    auto store_trans = [&](int st) {
#pragma unroll
        for (int kk = 0; kk < 8; kk++) {
            int k = tk0 + kk;
            __half2 h = *(__half2*)&trh[kk];
            Bs[((st * BT + 0) * 128 + tn) * SSTR + k]     = h.x;
            Bs[((st * BT + 0) * 128 + tn + 1) * SSTR + k] = h.y;
            if (BT == 2) {
                __half2 l = *(__half2*)&trl[kk];
                Bs[((st * BT + 1) * 128 + tn) * SSTR + k]     = l.x;
                Bs[((st * BT + 1) * 128 + tn + 1) * SSTR + k] = l.y;
            }
        }
    };

    issue_stage(0, 0);
    if (!NT) load_trans(0);
    asm volatile("cp.async.wait_group 0;" ::: "memory");
    if (!NT) store_trans(0);
    __syncthreads();

    int st = 0;
    for (int kt = 0; kt < p.K; kt += 32) {
        const int nxt = kt + 32;
        const bool more = nxt < p.K;
        if (more) {
            issue_stage(st ^ 1, nxt);
            if (!NT) load_trans(nxt);
        }
#pragma unroll
        for (int ks = 0; ks < 32; ks += 16) {
            unsigned ah[2][4], bh[8][2], blr[8][2];
#pragma unroll
            for (int i = 0; i < 2; i++) {
                int row = wm * 32 + i * 16 + (lane & 15);
                int ko = ks + (lane >> 4) * 8;
                ldsm4(ah[i], sA + 2u * ((st * 128 + row) * SSTR + ko));
            }
#pragma unroll
            for (int jj = 0; jj < 4; jj++) {
                int row = wn * 64 + jj * 16 + (lane & 7) + ((lane >> 4) & 1) * 8;
                int ko = ks + ((lane >> 3) & 1) * 8;
                unsigned t0[4];
                ldsm4(t0, sB + 2u * (((st * BT + 0) * 128 + row) * SSTR + ko));
                bh[2 * jj][0] = t0[0]; bh[2 * jj][1] = t0[1];
                bh[2 * jj + 1][0] = t0[2]; bh[2 * jj + 1][1] = t0[3];
                if (BT == 2) {
                    ldsm4(t0, sB + 2u * (((st * BT + 1) * 128 + row) * SSTR + ko));
                    blr[2 * jj][0] = t0[0]; blr[2 * jj][1] = t0[1];
                    blr[2 * jj + 1][0] = t0[2]; blr[2 * jj + 1][1] = t0[3];
                }
            }
#pragma unroll
            for (int i = 0; i < 2; i++)
#pragma unroll
                for (int j = 0; j < 8; j++) {
                    mma16816(acc[i][j], ah[i], bh[j]);
                    if (BT == 2) mma16816(acc[i][j], ah[i], blr[j]);
                }
        }
        if (more) {
            asm volatile("cp.async.wait_group 0;" ::: "memory");
            if (!NT) store_trans(st ^ 1);
            __syncthreads();
        }
        st ^= 1;
    }

    // epilogue
    __half* Ch = (p.flags & 16) ? p.Ch + pq * p.sC1 + pr * p.sC2 : nullptr;
    float*  Cf = (p.flags & 4)  ? p.Cf + pq * p.sC1 + pr * p.sC2 : nullptr;
    const int rbase = m0 + wm * 32 + (lane >> 2);
    const int cbase = n0 + wn * 64 + (lane & 3) * 2;
#pragma unroll
    for (int i = 0; i < 2; i++)
#pragma unroll
        for (int j = 0; j < 8; j++) {
            int c = cbase + j * 8;
            float b0 = 0.f, b1 = 0.f;
            if (p.bias) {
                b0 = p.bias[pr * p.biasStride + c];
                b1 = p.bias[pr * p.biasStride + c + 1];
            }
#pragma unroll
            for (int h = 0; h < 2; h++) {
                int r = rbase + i * 16 + h * 8;
                float v0 = acc[i][j][2 * h + 0] * p.alpha + b0;
                float v1 = acc[i][j][2 * h + 1] * p.alpha + b1;
                if (p.flags & 2) {
                    if (c > r)     v0 = -1e30f;
                    if (c + 1 > r) v1 = -1e30f;
                }
                if (p.flags & 1) { v0 = fmaxf(v0, 0.f); v1 = fmaxf(v1, 0.f); }
                long long off = (long long)r * p.ldc + c;
                if (p.flags & 4) *(float2*)(Cf + off) = make_float2(v0, v1);
                else {
                    __half2 hi; hi.x = __float2half(v0); hi.y = __float2half(v1);
                    *(__half2*)(Ch + off) = hi;
                }
            }
        }
}

// ---------------- fp32 -> fp16 converters ----------------
__global__ void cvt_hi_k(const float4* __restrict__ in, __half2* __restrict__ hi, int n4) {
    int i = blockIdx.x * blockDim.x + threadIdx.x;
    if (i >= n4) return;
    float4 v = in[i];
    __half2 h0; h0.x = __float2half(v.x); h0.y = __float2half(v.y);
    __half2 h1; h1.x = __float2half(v.z); h1.y = __float2half(v.w);
    hi[2 * i] = h0; hi[2 * i + 1] = h1;
}
__global__ void cvt_sp_k(const float4* __restrict__ in, __half2* __restrict__ hi,
                         __half2* __restrict__ lo, int n4) {
    int i = blockIdx.x * blockDim.x + threadIdx.x;
    if (i >= n4) return;
    float4 v = in[i];
    __half2 l0, l1;
    __half2 h0 = split_hi2(v.x, v.y, l0);
    __half2 h1 = split_hi2(v.z, v.w, l1);
    hi[2 * i] = h0; hi[2 * i + 1] = h1;
    lo[2 * i] = l0; lo[2 * i + 1] = l1;
}

// ---------------- softmax over 1024 cols ----------------
__global__ __launch_bounds__(256)
void softmax_k(__half2* S) {
    __shared__ float red[8];
    const long long row = blockIdx.x;
    __half2* sp = S + row * 512;
    const int t = threadIdx.x, lane = t & 31, w = t >> 5;
    __half2 h0 = sp[t], h1 = sp[t + 256];
    float v[4] = { __half2float(h0.x), __half2float(h0.y),
                   __half2float(h1.x), __half2float(h1.y) };

    float mx = fmaxf(fmaxf(v[0], v[1]), fmaxf(v[2], v[3]));
#pragma unroll
    for (int o = 16; o; o >>= 1) mx = fmaxf(mx, __shfl_xor_sync(~0u, mx, o));
    if (lane == 0) red[w] = mx;
    __syncthreads();
    float m2 = red[lane & 7];
#pragma unroll
    for (int o = 4; o; o >>= 1) m2 = fmaxf(m2, __shfl_xor_sync(~0u, m2, o));
    mx = m2;
    __syncthreads();

    float s = 0.f;
#pragma unroll
    for (int q = 0; q < 4; q++) { v[q] = __expf(v[q] - mx); s += v[q]; }
#pragma unroll
    for (int o = 16; o; o >>= 1) s += __shfl_xor_sync(~0u, s, o);
    if (lane == 0) red[w] = s;
    __syncthreads();
    float s2 = red[lane & 7];
#pragma unroll
    for (int o = 4; o; o >>= 1) s2 += __shfl_xor_sync(~0u, s2, o);
    float inv = 1.f / s2;

    __half2 o0, o1;
    o0.x = __float2half(v[0] * inv); o0.y = __float2half(v[1] * inv);
    o1.x = __float2half(v[2] * inv); o1.y = __float2half(v[3] * inv);
    sp[t] = o0; sp[t + 256] = o1;
}

// ---------------- residual add + LayerNorm (D=512) ----------------
__device__ __forceinline__ float bsum(float val, float* red) {
    const int lane = threadIdx.x & 31, w = threadIdx.x >> 5;
#pragma unroll
    for (int o = 16; o; o >>= 1) val += __shfl_xor_sync(~0u, val, o);
    if (lane == 0) red[w] = val;
    __syncthreads();
    float s = red[lane & 7];
#pragma unroll
    for (int o = 4; o; o >>= 1) s += __shfl_xor_sync(~0u, s, o);
    __syncthreads();
    return s;
}

__global__ __launch_bounds__(256)
void add_ln_k(const float2* __restrict__ a, const float2* __restrict__ r,
              const float* __restrict__ g, const float* __restrict__ b,
              float2* __restrict__ o, __half2* oh) {
    __shared__ float red[8];
    const long long row = blockIdx.x;
    const int t = threadIdx.x;
    float2 va = a[row * 256 + t], vr = r[row * 256 + t];
    float x0 = va.x + vr.x, x1 = va.y + vr.y;
    float mean = bsum(x0 + x1, red) * (1.f / 512.f);
    float d0 = x0 - mean, d1 = x1 - mean;
    float var = bsum(d0 * d0 + d1 * d1, red) * (1.f / 512.f);
    float inv = rsqrtf(var + 1e-5f);
    float y0 = d0 * inv * g[2 * t] + b[2 * t];
    float y1 = d1 * inv * g[2 * t + 1] + b[2 * t + 1];
    o[row * 256 + t] = make_float2(y0, y1);
    if (oh) {
        __half2 hh; hh.x = __float2half(y0); hh.y = __float2half(y1);
        oh[row * 256 + t] = hh;
    }
}

// ---------------- host ----------------
enum GType { G_N1, G_N2, G_T1 };
static void launch_gemm(GType t, const GemmP& p, int M, int N, int batch) {
    dim3 g(N / 128, M / 128, batch);
    if (t == G_N1)      gemm_k<false, 1><<<g, 256, SMEM_BYTES>>>(p);
    else if (t == G_N2) gemm_k<false, 2><<<g, 256, SMEM_BYTES>>>(p);
    else                gemm_k<true, 1><<<g, 256, SMEM_BYTES>>>(p);
}
static void cvt_hi(const float* src, __half* h, long long n) {
    int n4 = (int)(n / 4);
    cvt_hi_k<<<(n4 + 255) / 256, 256>>>((const float4*)src, (__half2*)h, n4);
}
static void cvt_sp(const float* src, __half* h, __half* l, long long n) {
    int n4 = (int)(n / 4);
    cvt_sp_k<<<(n4 + 255) / 256, 256>>>((const float4*)src, (__half2*)h, (__half2*)l, n4);
}

extern "C" void kernel_launch(void* const* d_in, const int* in_sizes, int n_in,
                              void* d_out, int out_size) {
    const float* x   = (const float*)d_in[0];
    const float* enc = (const float*)d_in[1];
    const float* sa_wq = (const float*)d_in[2];  const float* sa_bq = (const float*)d_in[3];
    const float* sa_wk = (const float*)d_in[4];  const float* sa_bk = (const float*)d_in[5];
    const float* sa_wv = (const float*)d_in[6];  const float* sa_bv = (const float*)d_in[7];
    const float* sa_wo = (const float*)d_in[8];  const float* sa_bo = (const float*)d_in[9];
    const float* sa_wf = (const float*)d_in[10]; const float* sa_bf = (const float*)d_in[11];
    const float* ca_wq = (const float*)d_in[12]; const float* ca_bq = (const float*)d_in[13];
    const float* ca_wk = (const float*)d_in[14]; const float* ca_bk = (const float*)d_in[15];
    const float* ca_wv = (const float*)d_in[16]; const float* ca_bv = (const float*)d_in[17];
    const float* ca_wo = (const float*)d_in[18]; const float* ca_bo = (const float*)d_in[19];
    const float* ca_wf = (const float*)d_in[20]; const float* ca_bf = (const float*)d_in[21];
    const float* ln1_g = (const float*)d_in[22]; const float* ln1_b = (const float*)d_in[23];
    const float* ln2_g = (const float*)d_in[24]; const float* ln2_b = (const float*)d_in[25];
    const float* ln3_g = (const float*)d_in[26]; const float* ln3_b = (const float*)d_in[27];
    const float* fc1_w = (const float*)d_in[28]; const float* fc1_b = (const float*)d_in[29];
    const float* fc2_w = (const float*)d_in[30]; const float* fc2_b = (const float*)d_in[31];

    cudaFuncSetAttribute((const void*)gemm_k<false, 1>,
                         cudaFuncAttributeMaxDynamicSharedMemorySize, SMEM_BYTES);
    cudaFuncSetAttribute((const void*)gemm_k<false, 2>,
                         cudaFuncAttributeMaxDynamicSharedMemorySize, SMEM_BYTES);
    cudaFuncSetAttribute((const void*)gemm_k<true, 1>,
                         cudaFuncAttributeMaxDynamicSharedMemorySize, SMEM_BYTES);

    __half *Qh, *Kh, *Vh, *Sh, *Oh, *Ph, *Mh, *Wh, *Wl, *xh, *eh, *X1h, *X2h;
    float *Hf, *X1f, *X2f;
    cudaGetSymbolAddress((void**)&Qh, g_Qh);
    cudaGetSymbolAddress((void**)&Kh, g_Kh);
    cudaGetSymbolAddress((void**)&Vh, g_Vh);
    cudaGetSymbolAddress((void**)&Sh, g_Sh);
    cudaGetSymbolAddress((void**)&Oh, g_Oh);
    cudaGetSymbolAddress((void**)&Ph, g_Ph);
    cudaGetSymbolAddress((void**)&Mh, g_Mh);
    cudaGetSymbolAddress((void**)&Wh, g_Wh);  cudaGetSymbolAddress((void**)&Wl, g_Wl);
    cudaGetSymbolAddress((void**)&xh, g_xh);  cudaGetSymbolAddress((void**)&eh, g_eh);
    cudaGetSymbolAddress((void**)&X1h, g_X1h); cudaGetSymbolAddress((void**)&X2h, g_X2h);
    cudaGetSymbolAddress((void**)&Hf, g_Hf);
    cudaGetSymbolAddress((void**)&X1f, g_X1f);
    cudaGetSymbolAddress((void**)&X2f, g_X2f);

    // conversions: Q/K weights hi-only; error-sensitive weights split
    cvt_hi(x,   xh, 2097152); cvt_hi(enc, eh, 2097152);
    cvt_hi(sa_wq, Wh + OW_SAQ, 2097152);
    cvt_hi(sa_wk, Wh + OW_SAK, 2097152);
    cvt_sp(sa_wv, Wh + OW_SAV, Wl + OW_SAV, 2097152);
    cvt_sp(sa_wo, Wh + OW_SAO, Wl + OW_SAO, 2097152);
    cvt_sp(sa_wf, Wh + OW_SAF, Wl + OW_SAF, 2097152);
    cvt_hi(ca_wq, Wh + OW_CAQ, 2097152);
    cvt_hi(ca_wk, Wh + OW_CAK, 2097152);
    cvt_sp(ca_wv, Wh + OW_CAV, Wl + OW_CAV, 2097152);
    cvt_sp(ca_wo, Wh + OW_CAO, Wl + OW_CAO, 2097152);
    cvt_sp(ca_wf, Wh + OW_CAF, Wl + OW_CAF, 2097152);
    cvt_sp(fc1_w, Wh + OW_FC1, Wl + OW_FC1, 1048576);
    cvt_sp(fc2_w, Wh + OW_FC2, Wl + OW_FC2, 1048576);

    const float ISC = 0.044194173824159216f;  // 1/sqrt(512)

    auto runMHA = [&](const __half* aq, const __half* akv,
                      long long oq, long long ok, long long ov, long long oo, long long of,
                      const float* bq, const float* bk, const float* bv,
                      const float* bo, const float* bfb, bool causal) {
        GemmP p{};
        // Q projection: 1-term
        p.Ah = aq; p.Bh = Wh + oq; p.bias = bq; p.Ch = Qh;
        p.K = 512; p.lda = 512; p.ldb = 512; p.ldc = 4096;
        p.sB2 = 262144; p.sC2 = 512;
        p.div = 8; p.biasStride = 512; p.alpha = 1.f; p.flags = 16;
        launch_gemm(G_N1, p, 4096, 512, 8);
        // K projection: 1-term
        p.Ah = akv; p.Bh = Wh + ok; p.bias = bk; p.Ch = Kh;
        launch_gemm(G_N1, p, 4096, 512, 8);
        // V projection: 2-term (weight split), hi out
        p.Bh = Wh + ov; p.Bl = Wl + ov; p.bias = bv; p.Ch = Vh;
        launch_gemm(G_N2, p, 4096, 512, 8);
        // scores = Qhi Khi^T / sqrt(512): 1-term NT
        p = GemmP{};
        p.Ah = Qh; p.Bh = Kh; p.Ch = Sh;
        p.K = 512; p.lda = 4096; p.ldb = 4096; p.ldc = 1024;
        p.sA1 = 4194304; p.sA2 = 512; p.sB1 = 4194304; p.sB2 = 512;
        p.sC1 = 8388608; p.sC2 = 1048576;
        p.div = 8; p.alpha = ISC; p.flags = causal ? (16 | 2) : 16;
        launch_gemm(G_T1, p, 1024, 1024, 32);
        softmax_k<<<32768, 256>>>((__half2*)Sh);
        // O = A V : both hi-only, 1-term
        p = GemmP{};
        p.Ah = Sh; p.Bh = Vh; p.Ch = Oh;
        p.K = 1024; p.lda = 1024; p.ldb = 4096; p.ldc = 4096;
        p.sA1 = 8388608; p.sA2 = 1048576; p.sB1 = 4194304; p.sB2 = 512;
        p.sC1 = 4194304; p.sC2 = 512;
        p.div = 8; p.alpha = 1.f; p.flags = 16;
        launch_gemm(G_N1, p, 1024, 512, 32);
        // per-head out projection: 2-term
        p = GemmP{};
        p.Ah = Oh; p.Bh = Wh + oo; p.Bl = Wl + oo; p.bias = bo; p.Ch = Ph;
        p.K = 512; p.lda = 4096; p.ldb = 512; p.ldc = 4096;
        p.sA2 = 512; p.sB2 = 262144; p.sC2 = 512;
        p.div = 8; p.biasStride = 512; p.alpha = 1.f; p.flags = 16;
        launch_gemm(G_N2, p, 4096, 512, 8);
        // final concat projection: 2-term -> fp32 H
        p = GemmP{};
        p.Ah = Ph; p.Bh = Wh + of; p.Bl = Wl + of; p.bias = bfb; p.Cf = Hf;
        p.K = 4096; p.lda = 4096; p.ldb = 512; p.ldc = 512;
        p.div = 1; p.alpha = 1.f; p.flags = 4;
        launch_gemm(G_N2, p, 4096, 512, 1);
    };

    // self-attention (causal) + LN1
    runMHA(xh, xh, OW_SAQ, OW_SAK, OW_SAV, OW_SAO, OW_SAF,
           sa_bq, sa_bk, sa_bv, sa_bo, sa_bf, true);
    add_ln_k<<<4096, 256>>>((const float2*)Hf, (const float2*)x, ln1_g, ln1_b,
                            (float2*)X1f, (__half2*)X1h);

    // cross-attention + LN2
    runMHA(X1h, eh, OW_CAQ, OW_CAK, OW_CAV, OW_CAO, OW_CAF,
           ca_bq, ca_bk, ca_bv, ca_bo, ca_bf, false);
    add_ln_k<<<4096, 256>>>((const float2*)Hf, (const float2*)X1f, ln2_g, ln2_b,
                            (float2*)X2f, (__half2*)X2h);

    // FFN
    {
        GemmP p{};
        p.Ah = X2h; p.Bh = Wh + OW_FC1; p.Bl = Wl + OW_FC1; p.bias = fc1_b; p.Ch = Mh;
        p.K = 512; p.lda = 512; p.ldb = 2048; p.ldc = 2048;
        p.div = 1; p.alpha = 1.f; p.flags = 16 | 1;
        launch_gemm(G_N2, p, 4096, 2048, 1);

        p = GemmP{};
        p.Ah = Mh; p.Bh = Wh + OW_FC2; p.Bl = Wl + OW_FC2; p.bias = fc2_b; p.Cf = Hf;
        p.K = 2048; p.lda = 2048; p.ldb = 512; p.ldc = 512;
        p.div = 1; p.alpha = 1.f; p.flags = 4;
        launch_gemm(G_N2, p, 4096, 512, 1);
    }
    add_ln_k<<<4096, 256>>>((const float2*)Hf, (const float2*)X2f, ln3_g, ln3_b,
                            (float2*)d_out, nullptr);
}

// round 6
// speedup vs baseline: 5.8262x; 1.2135x over previous
#include <cuda_runtime.h>
#include <cuda_fp16.h>
#include <math.h>

#define SMEM_BYTES 40960
#define SSTR 40

// ---------------- static scratch ----------------
__device__ __half g_Qh[16777216];
__device__ __half g_Kh[16777216];
__device__ __half g_Vh[16777216];
__device__ __half g_Sh[33554432];                 // scores/probs
__device__ __half g_Oh[16777216];
__device__ __half g_Ph[16777216];
__device__ __half g_Mh[8388608];
__device__ __half g_Wh[23068672];                 // all weights fp16
__device__ __half g_xh[2097152], g_eh[2097152], g_X1h[2097152], g_X2h[2097152];
__device__ float g_Hf[2097152], g_X1f[2097152], g_X2f[2097152];

#define OW_SAQ 0LL
#define OW_SAK 2097152LL
#define OW_SAV 4194304LL
#define OW_SAO 6291456LL
#define OW_SAF 8388608LL
#define OW_CAQ 10485760LL
#define OW_CAK 12582912LL
#define OW_CAV 14680064LL
#define OW_CAO 16777216LL
#define OW_CAF 18874368LL
#define OW_FC1 20971520LL
#define OW_FC2 22020096LL

// ---------------- PTX helpers ----------------
__device__ __forceinline__ void mma16816(float* d, const unsigned* a, const unsigned* b) {
    asm volatile(
        "mma.sync.aligned.m16n8k16.row.col.f32.f16.f16.f32 "
        "{%0,%1,%2,%3}, {%4,%5,%6,%7}, {%8,%9}, {%0,%1,%2,%3};"
        : "+f"(d[0]), "+f"(d[1]), "+f"(d[2]), "+f"(d[3])
        : "r"(a[0]), "r"(a[1]), "r"(a[2]), "r"(a[3]), "r"(b[0]), "r"(b[1]));
}
__device__ __forceinline__ void ldsm4(unsigned* r, unsigned a) {
    asm volatile("ldmatrix.sync.aligned.m8n8.x4.shared.b16 {%0,%1,%2,%3}, [%4];"
                 : "=r"(r[0]), "=r"(r[1]), "=r"(r[2]), "=r"(r[3]) : "r"(a));
}
__device__ __forceinline__ void cp16(unsigned d, const void* s) {
    asm volatile("cp.async.cg.shared.global [%0], [%1], 16;" :: "r"(d), "l"(s));
}

// ---------------- GEMM: C = alpha * A*B + bias ----------------
// A [M,K] fp16 row-major; NT=true: B [N,K] row-major; NT=false: B [K,N] row-major.
// flags: 1 relu, 2 causal mask, 4 fp32 out, 16 fp16 out, 32 causal K-limit (A cols > m0+127 are zero)
struct GemmP {
    const __half *Ah, *Bh;
    const float* bias;
    __half *Ch;
    float* Cf;
    int K, lda, ldb, ldc;
    long long sA1, sA2, sB1, sB2, sC1, sC2;
    int div, biasStride;
    float alpha; int flags;
};

template<bool NT>
__global__ __launch_bounds__(256) void gemm_k(GemmP p) {
    extern __shared__ unsigned char raw[];
    __half* As = (__half*)raw;                    // [st*128+m]*SSTR + k
    __half* Bs = As + 2 * 128 * SSTR;

    const int pb = blockIdx.z, pq = pb / p.div, pr = pb - pq * p.div;
    const int tid = threadIdx.x, lane = tid & 31, warp = tid >> 5;
    const int wm = warp >> 1, wn = warp & 1;
    const int m0 = blockIdx.y * 128, n0 = blockIdx.x * 128;

    // fully-masked causal tile: write -inf, skip compute
    if ((p.flags & 2) && n0 > m0 + 127) {
        __half2* Ch2 = (__half2*)(p.Ch + pq * p.sC1 + pr * p.sC2);
        const __half2 mi = __half2half2(__float2half(-1e30f));
        for (int i = tid; i < 128 * 64; i += 256) {
            int r = i >> 6, c = i & 63;
            Ch2[((long long)(m0 + r) * p.ldc + n0) / 2 + c] = mi;
        }
        return;
    }

    const int Klim = (p.flags & 32) ? (m0 + 128 < p.K ? m0 + 128 : p.K) : p.K;

    const __half* Abase = p.Ah + pq * p.sA1 + pr * p.sA2;
    const __half* Bbase = p.Bh + pq * p.sB1 + pr * p.sB2;

    const unsigned sA = (unsigned)__cvta_generic_to_shared(As);
    const unsigned sB = (unsigned)__cvta_generic_to_shared(Bs);

    const int crow = tid >> 2, cseg = (tid & 3) * 8;
    const int tn = (tid & 63) * 2, tk0 = (tid >> 6) * 8;

    float acc[2][8][4];
#pragma unroll
    for (int i = 0; i < 2; i++)
#pragma unroll
        for (int j = 0; j < 8; j++)
#pragma unroll
            for (int q = 0; q < 4; q++) acc[i][j][q] = 0.f;

    unsigned trh[8];

    auto issue_stage = [&](int st, int kt) {
#pragma unroll
        for (int r = 0; r < 2; r++) {
            int row = crow + r * 64;
            cp16(sA + 2u * ((st * 128 + row) * SSTR + cseg),
                 Abase + (long long)(m0 + row) * p.lda + kt + cseg);
        }
        if (NT) {
#pragma unroll
            for (int r = 0; r < 2; r++) {
                int row = crow + r * 64;
                cp16(sB + 2u * ((st * 128 + row) * SSTR + cseg),
                     Bbase + (long long)(n0 + row) * p.ldb + kt + cseg);
            }
        }
        asm volatile("cp.async.commit_group;");
    };
    auto load_trans = [&](int kt) {
#pragma unroll
        for (int kk = 0; kk < 8; kk++) {
            int k = tk0 + kk;
            trh[kk] = *(const unsigned*)(Bbase + (long long)(kt + k) * p.ldb + n0 + tn);
        }
    };
    auto store_trans = [&](int st) {
#pragma unroll
        for (int kk = 0; kk < 8; kk++) {
            int k = tk0 + kk;
            __half2 h = *(__half2*)&trh[kk];
            Bs[(st * 128 + tn) * SSTR + k]     = h.x;
            Bs[(st * 128 + tn + 1) * SSTR + k] = h.y;
        }
    };

    issue_stage(0, 0);
    if (!NT) load_trans(0);
    asm volatile("cp.async.wait_group 0;" ::: "memory");
    if (!NT) store_trans(0);
    __syncthreads();

    int st = 0;
    for (int kt = 0; kt < Klim; kt += 32) {
        const int nxt = kt + 32;
        const bool more = nxt < Klim;
        if (more) {
            issue_stage(st ^ 1, nxt);
            if (!NT) load_trans(nxt);
        }
#pragma unroll
        for (int ks = 0; ks < 32; ks += 16) {
            unsigned ah[2][4], bh[8][2];
#pragma unroll
            for (int i = 0; i < 2; i++) {
                int row = wm * 32 + i * 16 + (lane & 15);
                int ko = ks + (lane >> 4) * 8;
                ldsm4(ah[i], sA + 2u * ((st * 128 + row) * SSTR + ko));
            }
#pragma unroll
            for (int jj = 0; jj < 4; jj++) {
                int row = wn * 64 + jj * 16 + (lane & 7) + ((lane >> 4) & 1) * 8;
                int ko = ks + ((lane >> 3) & 1) * 8;
                unsigned t0[4];
                ldsm4(t0, sB + 2u * ((st * 128 + row) * SSTR + ko));
                bh[2 * jj][0] = t0[0]; bh[2 * jj][1] = t0[1];
                bh[2 * jj + 1][0] = t0[2]; bh[2 * jj + 1][1] = t0[3];
            }
#pragma unroll
            for (int i = 0; i < 2; i++)
#pragma unroll
                for (int j = 0; j < 8; j++)
                    mma16816(acc[i][j], ah[i], bh[j]);
        }
        if (more) {
            asm volatile("cp.async.wait_group 0;" ::: "memory");
            if (!NT) store_trans(st ^ 1);
            __syncthreads();
        }
        st ^= 1;
    }

    // epilogue
    __half* Ch = (p.flags & 16) ? p.Ch + pq * p.sC1 + pr * p.sC2 : nullptr;
    float*  Cf = (p.flags & 4)  ? p.Cf + pq * p.sC1 + pr * p.sC2 : nullptr;
    const int rbase = m0 + wm * 32 + (lane >> 2);
    const int cbase = n0 + wn * 64 + (lane & 3) * 2;
#pragma unroll
    for (int i = 0; i < 2; i++)
#pragma unroll
        for (int j = 0; j < 8; j++) {
            int c = cbase + j * 8;
            float b0 = 0.f, b1 = 0.f;
            if (p.bias) {
                b0 = p.bias[pr * p.biasStride + c];
                b1 = p.bias[pr * p.biasStride + c + 1];
            }
#pragma unroll
            for (int h = 0; h < 2; h++) {
                int r = rbase + i * 16 + h * 8;
                float v0 = acc[i][j][2 * h + 0] * p.alpha + b0;
                float v1 = acc[i][j][2 * h + 1] * p.alpha + b1;
                if (p.flags & 2) {
                    if (c > r)     v0 = -1e30f;
                    if (c + 1 > r) v1 = -1e30f;
                }
                if (p.flags & 1) { v0 = fmaxf(v0, 0.f); v1 = fmaxf(v1, 0.f); }
                long long off = (long long)r * p.ldc + c;
                if (p.flags & 4) *(float2*)(Cf + off) = make_float2(v0, v1);
                else {
                    __half2 hi; hi.x = __float2half(v0); hi.y = __float2half(v1);
                    *(__half2*)(Ch + off) = hi;
                }
            }
        }
}

// ---------------- fp32 -> fp16 ----------------
__global__ void cvt_hi_k(const float4* __restrict__ in, __half2* __restrict__ hi, int n4) {
    int i = blockIdx.x * blockDim.x + threadIdx.x;
    if (i >= n4) return;
    float4 v = in[i];
    __half2 h0; h0.x = __float2half(v.x); h0.y = __float2half(v.y);
    __half2 h1; h1.x = __float2half(v.z); h1.y = __float2half(v.w);
    hi[2 * i] = h0; hi[2 * i + 1] = h1;
}

// ---------------- softmax over 1024 cols ----------------
__global__ __launch_bounds__(256)
void softmax_k(__half2* S) {
    __shared__ float red[8];
    const long long row = blockIdx.x;
    __half2* sp = S + row * 512;
    const int t = threadIdx.x, lane = t & 31, w = t >> 5;
    __half2 h0 = sp[t], h1 = sp[t + 256];
    float v[4] = { __half2float(h0.x), __half2float(h0.y),
                   __half2float(h1.x), __half2float(h1.y) };

    float mx = fmaxf(fmaxf(v[0], v[1]), fmaxf(v[2], v[3]));
#pragma unroll
    for (int o = 16; o; o >>= 1) mx = fmaxf(mx, __shfl_xor_sync(~0u, mx, o));
    if (lane == 0) red[w] = mx;
    __syncthreads();
    float m2 = red[lane & 7];
#pragma unroll
    for (int o = 4; o; o >>= 1) m2 = fmaxf(m2, __shfl_xor_sync(~0u, m2, o));
    mx = m2;
    __syncthreads();

    float s = 0.f;
#pragma unroll
    for (int q = 0; q < 4; q++) { v[q] = __expf(v[q] - mx); s += v[q]; }
#pragma unroll
    for (int o = 16; o; o >>= 1) s += __shfl_xor_sync(~0u, s, o);
    if (lane == 0) red[w] = s;
    __syncthreads();
    float s2 = red[lane & 7];
#pragma unroll
    for (int o = 4; o; o >>= 1) s2 += __shfl_xor_sync(~0u, s2, o);
    float inv = 1.f / s2;

    __half2 o0, o1;
    o0.x = __float2half(v[0] * inv); o0.y = __float2half(v[1] * inv);
    o1.x = __float2half(v[2] * inv); o1.y = __float2half(v[3] * inv);
    sp[t] = o0; sp[t + 256] = o1;
}

// ---------------- residual add + LayerNorm (D=512) ----------------
__device__ __forceinline__ float bsum(float val, float* red) {
    const int lane = threadIdx.x & 31, w = threadIdx.x >> 5;
#pragma unroll
    for (int o = 16; o; o >>= 1) val += __shfl_xor_sync(~0u, val, o);
    if (lane == 0) red[w] = val;
    __syncthreads();
    float s = red[lane & 7];
#pragma unroll
    for (int o = 4; o; o >>= 1) s += __shfl_xor_sync(~0u, s, o);
    __syncthreads();
    return s;
}

__global__ __launch_bounds__(256)
void add_ln_k(const float2* __restrict__ a, const float2* __restrict__ r,
              const float* __restrict__ g, const float* __restrict__ b,
              float2* __restrict__ o, __half2* oh) {
    __shared__ float red[8];
    const long long row = blockIdx.x;
    const int t = threadIdx.x;
    float2 va = a[row * 256 + t], vr = r[row * 256 + t];
    float x0 = va.x + vr.x, x1 = va.y + vr.y;
    float mean = bsum(x0 + x1, red) * (1.f / 512.f);
    float d0 = x0 - mean, d1 = x1 - mean;
    float var = bsum(d0 * d0 + d1 * d1, red) * (1.f / 512.f);
    float inv = rsqrtf(var + 1e-5f);
    float y0 = d0 * inv * g[2 * t] + b[2 * t];
    float y1 = d1 * inv * g[2 * t + 1] + b[2 * t + 1];
    o[row * 256 + t] = make_float2(y0, y1);
    if (oh) {
        __half2 hh; hh.x = __float2half(y0); hh.y = __float2half(y1);
        oh[row * 256 + t] = hh;
    }
}

// ---------------- host ----------------
static void launch_gemm(bool nt, const GemmP& p, int M, int N, int batch) {
    dim3 g(N / 128, M / 128, batch);
    if (nt) gemm_k<true><<<g, 256, SMEM_BYTES>>>(p);
    else    gemm_k<false><<<g, 256, SMEM_BYTES>>>(p);
}
static void cvt_hi(const float* src, __half* h, long long n) {
    int n4 = (int)(n / 4);
    cvt_hi_k<<<(n4 + 255) / 256, 256>>>((const float4*)src, (__half2*)h, n4);
}

extern "C" void kernel_launch(void* const* d_in, const int* in_sizes, int n_in,
                              void* d_out, int out_size) {
    const float* x   = (const float*)d_in[0];
    const float* enc = (const float*)d_in[1];
    const float* sa_wq = (const float*)d_in[2];  const float* sa_bq = (const float*)d_in[3];
    const float* sa_wk = (const float*)d_in[4];  const float* sa_bk = (const float*)d_in[5];
    const float* sa_wv = (const float*)d_in[6];  const float* sa_bv = (const float*)d_in[7];
    const float* sa_wo = (const float*)d_in[8];  const float* sa_bo = (const float*)d_in[9];
    const float* sa_wf = (const float*)d_in[10]; const float* sa_bf = (const float*)d_in[11];
    const float* ca_wq = (const float*)d_in[12]; const float* ca_bq = (const float*)d_in[13];
    const float* ca_wk = (const float*)d_in[14]; const float* ca_bk = (const float*)d_in[15];
    const float* ca_wv = (const float*)d_in[16]; const float* ca_bv = (const float*)d_in[17];
    const float* ca_wo = (const float*)d_in[18]; const float* ca_bo = (const float*)d_in[19];
    const float* ca_wf = (const float*)d_in[20]; const float* ca_bf = (const float*)d_in[21];
    const float* ln1_g = (const float*)d_in[22]; const float* ln1_b = (const float*)d_in[23];
    const float* ln2_g = (const float*)d_in[24]; const float* ln2_b = (const float*)d_in[25];
    const float* ln3_g = (const float*)d_in[26]; const float* ln3_b = (const float*)d_in[27];
    const float* fc1_w = (const float*)d_in[28]; const float* fc1_b = (const float*)d_in[29];
    const float* fc2_w = (const float*)d_in[30]; const float* fc2_b = (const float*)d_in[31];

    cudaFuncSetAttribute((const void*)gemm_k<false>,
                         cudaFuncAttributeMaxDynamicSharedMemorySize, SMEM_BYTES);
    cudaFuncSetAttribute((const void*)gemm_k<true>,
                         cudaFuncAttributeMaxDynamicSharedMemorySize, SMEM_BYTES);

    __half *Qh, *Kh, *Vh, *Sh, *Oh, *Ph, *Mh, *Wh, *xh, *eh, *X1h, *X2h;
    float *Hf, *X1f, *X2f;
    cudaGetSymbolAddress((void**)&Qh, g_Qh);
    cudaGetSymbolAddress((void**)&Kh, g_Kh);
    cudaGetSymbolAddress((void**)&Vh, g_Vh);
    cudaGetSymbolAddress((void**)&Sh, g_Sh);
    cudaGetSymbolAddress((void**)&Oh, g_Oh);
    cudaGetSymbolAddress((void**)&Ph, g_Ph);
    cudaGetSymbolAddress((void**)&Mh, g_Mh);
    cudaGetSymbolAddress((void**)&Wh, g_Wh);
    cudaGetSymbolAddress((void**)&xh, g_xh);  cudaGetSymbolAddress((void**)&eh, g_eh);
    cudaGetSymbolAddress((void**)&X1h, g_X1h); cudaGetSymbolAddress((void**)&X2h, g_X2h);
    cudaGetSymbolAddress((void**)&Hf, g_Hf);
    cudaGetSymbolAddress((void**)&X1f, g_X1f);
    cudaGetSymbolAddress((void**)&X2f, g_X2f);

    // conversions (all fp16 hi)
    cvt_hi(x,   xh, 2097152); cvt_hi(enc, eh, 2097152);
    cvt_hi(sa_wq, Wh + OW_SAQ, 2097152);
    cvt_hi(sa_wk, Wh + OW_SAK, 2097152);
    cvt_hi(sa_wv, Wh + OW_SAV, 2097152);
    cvt_hi(sa_wo, Wh + OW_SAO, 2097152);
    cvt_hi(sa_wf, Wh + OW_SAF, 2097152);
    cvt_hi(ca_wq, Wh + OW_CAQ, 2097152);
    cvt_hi(ca_wk, Wh + OW_CAK, 2097152);
    cvt_hi(ca_wv, Wh + OW_CAV, 2097152);
    cvt_hi(ca_wo, Wh + OW_CAO, 2097152);
    cvt_hi(ca_wf, Wh + OW_CAF, 2097152);
    cvt_hi(fc1_w, Wh + OW_FC1, 1048576);
    cvt_hi(fc2_w, Wh + OW_FC2, 1048576);

    const float ISC = 0.044194173824159216f;  // 1/sqrt(512)

    auto runMHA = [&](const __half* aq, const __half* akv,
                      long long oq, long long ok, long long ov, long long oo, long long of,
                      const float* bq, const float* bk, const float* bv,
                      const float* bo, const float* bfb, bool causal) {
        GemmP p{};
        // Q projection
        p.Ah = aq; p.Bh = Wh + oq; p.bias = bq; p.Ch = Qh;
        p.K = 512; p.lda = 512; p.ldb = 512; p.ldc = 4096;
        p.sB2 = 262144; p.sC2 = 512;
        p.div = 8; p.biasStride = 512; p.alpha = 1.f; p.flags = 16;
        launch_gemm(false, p, 4096, 512, 8);
        // K projection
        p.Ah = akv; p.Bh = Wh + ok; p.bias = bk; p.Ch = Kh;
        launch_gemm(false, p, 4096, 512, 8);
        // V projection
        p.Bh = Wh + ov; p.bias = bv; p.Ch = Vh;
        launch_gemm(false, p, 4096, 512, 8);
        // scores = Q K^T / sqrt(512)
        p = GemmP{};
        p.Ah = Qh; p.Bh = Kh; p.Ch = Sh;
        p.K = 512; p.lda = 4096; p.ldb = 4096; p.ldc = 1024;
        p.sA1 = 4194304; p.sA2 = 512; p.sB1 = 4194304; p.sB2 = 512;
        p.sC1 = 8388608; p.sC2 = 1048576;
        p.div = 8; p.alpha = ISC; p.flags = causal ? (16 | 2) : 16;
        launch_gemm(true, p, 1024, 1024, 32);
        softmax_k<<<32768, 256>>>((__half2*)Sh);
        // O = A V  (causal: probs cols > m0+127 are exactly 0 -> K-limit)
        p = GemmP{};
        p.Ah = Sh; p.Bh = Vh; p.Ch = Oh;
        p.K = 1024; p.lda = 1024; p.ldb = 4096; p.ldc = 4096;
        p.sA1 = 8388608; p.sA2 = 1048576; p.sB1 = 4194304; p.sB2 = 512;
        p.sC1 = 4194304; p.sC2 = 512;
        p.div = 8; p.alpha = 1.f; p.flags = causal ? (16 | 32) : 16;
        launch_gemm(false, p, 1024, 512, 32);
        // per-head out projection
        p = GemmP{};
        p.Ah = Oh; p.Bh = Wh + oo; p.bias = bo; p.Ch = Ph;
        p.K = 512; p.lda = 4096; p.ldb = 512; p.ldc = 4096;
        p.sA2 = 512; p.sB2 = 262144; p.sC2 = 512;
        p.div = 8; p.biasStride = 512; p.alpha = 1.f; p.flags = 16;
        launch_gemm(false, p, 4096, 512, 8);
        // final concat projection -> fp32 H
        p = GemmP{};
        p.Ah = Ph; p.Bh = Wh + of; p.bias = bfb; p.Cf = Hf;
        p.K = 4096; p.lda = 4096; p.ldb = 512; p.ldc = 512;
        p.div = 1; p.alpha = 1.f; p.flags = 4;
        launch_gemm(false, p, 4096, 512, 1);
    };

    // self-attention (causal) + LN1
    runMHA(xh, xh, OW_SAQ, OW_SAK, OW_SAV, OW_SAO, OW_SAF,
           sa_bq, sa_bk, sa_bv, sa_bo, sa_bf, true);
    add_ln_k<<<4096, 256>>>((const float2*)Hf, (const float2*)x, ln1_g, ln1_b,
                            (float2*)X1f, (__half2*)X1h);

    // cross-attention + LN2
    runMHA(X1h, eh, OW_CAQ, OW_CAK, OW_CAV, OW_CAO, OW_CAF,
           ca_bq, ca_bk, ca_bv, ca_bo, ca_bf, false);
    add_ln_k<<<4096, 256>>>((const float2*)Hf, (const float2*)X1f, ln2_g, ln2_b,
                            (float2*)X2f, (__half2*)X2h);

    // FFN
    {
        GemmP p{};
        p.Ah = X2h; p.Bh = Wh + OW_FC1; p.bias = fc1_b; p.Ch = Mh;
        p.K = 512; p.lda = 512; p.ldb = 2048; p.ldc = 2048;
        p.div = 1; p.alpha = 1.f; p.flags = 16 | 1;
        launch_gemm(false, p, 4096, 2048, 1);

        p = GemmP{};
        p.Ah = Mh; p.Bh = Wh + OW_FC2; p.bias = fc2_b; p.Cf = Hf;
        p.K = 2048; p.lda = 2048; p.ldb = 512; p.ldc = 512;
        p.div = 1; p.alpha = 1.f; p.flags = 4;
        launch_gemm(false, p, 4096, 512, 1);
    }
    add_ln_k<<<4096, 256>>>((const float2*)Hf, (const float2*)X2f, ln3_g, ln3_b,
                            (float2*)d_out, nullptr);
}

// round 8
// speedup vs baseline: 6.0539x; 1.0391x over previous
#include <cuda_runtime.h>
#include <cuda_fp16.h>
#include <math.h>

#define ASTR 40                 // A smem row stride (halfs): 32 k + 8 pad
#define BSTR 136                // NT=false B smem row stride (halfs): 128 n + 8 pad
#define A_ST  (128 * ASTR)      // halfs per A stage
#define BT_ST (128 * ASTR)      // NT=true  B stage ([n][k])
#define BN_ST (32 * BSTR)       // NT=false B stage ([k][n])
#define SMEM_BYTES 40960

// ---------------- static scratch ----------------
__device__ __half g_Qh[16777216];
__device__ __half g_Kh[16777216];
__device__ __half g_Vh[16777216];
__device__ __half g_Sh[33554432];
__device__ __half g_Oh[16777216];
__device__ __half g_Ph[16777216];
__device__ __half g_Mh[8388608];
__device__ __half g_Wh[23068672];
__device__ __half g_xh[2097152], g_eh[2097152], g_X1h[2097152], g_X2h[2097152];
__device__ float g_Hf[2097152], g_X1f[2097152], g_X2f[2097152];

#define OW_SAQ 0LL
#define OW_SAK 2097152LL
#define OW_SAV 4194304LL
#define OW_SAO 6291456LL
#define OW_SAF 8388608LL
#define OW_CAQ 10485760LL
#define OW_CAK 12582912LL
#define OW_CAV 14680064LL
#define OW_CAO 16777216LL
#define OW_CAF 18874368LL
#define OW_FC1 20971520LL
#define OW_FC2 22020096LL

// ---------------- PTX helpers ----------------
__device__ __forceinline__ void mma16816(float* d, const unsigned* a, const unsigned* b) {
    asm volatile(
        "mma.sync.aligned.m16n8k16.row.col.f32.f16.f16.f32 "
        "{%0,%1,%2,%3}, {%4,%5,%6,%7}, {%8,%9}, {%0,%1,%2,%3};"
        : "+f"(d[0]), "+f"(d[1]), "+f"(d[2]), "+f"(d[3])
        : "r"(a[0]), "r"(a[1]), "r"(a[2]), "r"(a[3]), "r"(b[0]), "r"(b[1]));
}
__device__ __forceinline__ void ldsm4(unsigned* r, unsigned a) {
    asm volatile("ldmatrix.sync.aligned.m8n8.x4.shared.b16 {%0,%1,%2,%3}, [%4];"
                 : "=r"(r[0]), "=r"(r[1]), "=r"(r[2]), "=r"(r[3]) : "r"(a));
}
__device__ __forceinline__ void ldsm4t(unsigned* r, unsigned a) {
    asm volatile("ldmatrix.sync.aligned.m8n8.x4.trans.shared.b16 {%0,%1,%2,%3}, [%4];"
                 : "=r"(r[0]), "=r"(r[1]), "=r"(r[2]), "=r"(r[3]) : "r"(a));
}
__device__ __forceinline__ void cp16(unsigned d, const void* s) {
    asm volatile("cp.async.cg.shared.global [%0], [%1], 16;" :: "r"(d), "l"(s));
}

// ---------------- GEMM: C = alpha * A*B + bias ----------------
// A [M,K] fp16 row-major.
// NT=true : B [N,K] row-major (smem [n][k], non-trans ldmatrix)
// NT=false: B [K,N] row-major (smem [k][n] direct cp.async, trans ldmatrix)
// flags: 1 relu, 2 causal mask, 4 fp32 out, 16 fp16 out, 32 causal K-limit
struct GemmP {
    const __half *Ah, *Bh;
    const float* bias;
    __half *Ch;
    float* Cf;
    int K, lda, ldb, ldc;
    long long sA1, sA2, sB1, sB2, sC1, sC2;
    int div, biasStride;
    float alpha; int flags;
};

template<bool NT>
__global__ __launch_bounds__(256) void gemm_k(GemmP p) {
    extern __shared__ unsigned char raw[];
    __half* As = (__half*)raw;
    __half* Bs = As + 2 * A_ST;

    const int pb = blockIdx.z, pq = pb / p.div, pr = pb - pq * p.div;
    const int tid = threadIdx.x, lane = tid & 31, warp = tid >> 5;
    const int wm = warp >> 1, wn = warp & 1;
    const int m0 = blockIdx.y * 128, n0 = blockIdx.x * 128;

    // fully-masked causal tile: write -inf, skip compute
    if ((p.flags & 2) && n0 > m0 + 127) {
        __half2* Ch2 = (__half2*)(p.Ch + pq * p.sC1 + pr * p.sC2);
        const __half2 mi = __half2half2(__float2half(-1e30f));
        for (int i = tid; i < 128 * 64; i += 256) {
            int r = i >> 6, c = i & 63;
            Ch2[((long long)(m0 + r) * p.ldc + n0) / 2 + c] = mi;
        }
        return;
    }

    const int Klim = (p.flags & 32) ? (m0 + 128 < p.K ? m0 + 128 : p.K) : p.K;

    const __half* Abase = p.Ah + pq * p.sA1 + pr * p.sA2;
    const __half* Bbase = p.Bh + pq * p.sB1 + pr * p.sB2;

    const unsigned sA = (unsigned)__cvta_generic_to_shared(As);
    const unsigned sB = (unsigned)__cvta_generic_to_shared(Bs);

    const int crow = tid >> 2, cseg = (tid & 3) * 8;     // A map: 128 rows x 4 segs (x2)

    float acc[2][8][4];
#pragma unroll
    for (int i = 0; i < 2; i++)
#pragma unroll
        for (int j = 0; j < 8; j++)
#pragma unroll
            for (int q = 0; q < 4; q++) acc[i][j][q] = 0.f;

    auto issue_stage = [&](int st, int kt) {
#pragma unroll
        for (int r = 0; r < 2; r++) {
            int row = crow + r * 64;
            cp16(sA + 2u * (st * A_ST + row * ASTR + cseg),
                 Abase + (long long)(m0 + row) * p.lda + kt + cseg);
        }
        if (NT) {
#pragma unroll
            for (int r = 0; r < 2; r++) {
                int row = crow + r * 64;
                cp16(sB + 2u * (st * BT_ST + row * ASTR + cseg),
                     Bbase + (long long)(n0 + row) * p.ldb + kt + cseg);
            }
        } else {
            // B stage: 32 k-rows x 128 n = 8192 B -> 512 cp16 = 2 per thread
#pragma unroll
            for (int it = 0; it < 2; it++) {
                int i = tid + it * 256;
                int row = i >> 4, seg = i & 15;
                cp16(sB + 2u * (st * BN_ST + row * BSTR + seg * 8),
                     Bbase + (long long)(kt + row) * p.ldb + n0 + seg * 8);
            }
        }
        asm volatile("cp.async.commit_group;");
    };

    issue_stage(0, 0);
    asm volatile("cp.async.wait_group 0;" ::: "memory");
    __syncthreads();

    int st = 0;
    for (int kt = 0; kt < Klim; kt += 32) {
        const int nxt = kt + 32;
        const bool more = nxt < Klim;
        if (more) issue_stage(st ^ 1, nxt);
#pragma unroll
        for (int ks = 0; ks < 32; ks += 16) {
            unsigned ah[2][4], bh[8][2];
#pragma unroll
            for (int i = 0; i < 2; i++) {
                int row = wm * 32 + i * 16 + (lane & 15);
                int ko = ks + (lane >> 4) * 8;
                ldsm4(ah[i], sA + 2u * (st * A_ST + row * ASTR + ko));
            }
#pragma unroll
            for (int jj = 0; jj < 4; jj++) {
                unsigned t0[4];
                if (NT) {
                    int row = wn * 64 + jj * 16 + (lane & 7) + ((lane >> 4) & 1) * 8;
                    int ko = ks + ((lane >> 3) & 1) * 8;
                    ldsm4(t0, sB + 2u * (st * BT_ST + row * ASTR + ko));
                } else {
                    int krow = ks + (lane & 7) + ((lane >> 3) & 1) * 8;
                    int ncol = wn * 64 + jj * 16 + ((lane >> 4) & 1) * 8;
                    ldsm4t(t0, sB + 2u * (st * BN_ST + krow * BSTR + ncol));
                }
                bh[2 * jj][0] = t0[0]; bh[2 * jj][1] = t0[1];
                bh[2 * jj + 1][0] = t0[2]; bh[2 * jj + 1][1] = t0[3];
            }
#pragma unroll
            for (int i = 0; i < 2; i++)
#pragma unroll
                for (int j = 0; j < 8; j++)
                    mma16816(acc[i][j], ah[i], bh[j]);
        }
        if (more) {
            asm volatile("cp.async.wait_group 0;" ::: "memory");
            __syncthreads();
        }
        st ^= 1;
    }

    // epilogue
    __half* Ch = (p.flags & 16) ? p.Ch + pq * p.sC1 + pr * p.sC2 : nullptr;
    float*  Cf = (p.flags & 4)  ? p.Cf + pq * p.sC1 + pr * p.sC2 : nullptr;
    const int rbase = m0 + wm * 32 + (lane >> 2);
    const int cbase = n0 + wn * 64 + (lane & 3) * 2;
#pragma unroll
    for (int i = 0; i < 2; i++)
#pragma unroll
        for (int j = 0; j < 8; j++) {
            int c = cbase + j * 8;
            float b0 = 0.f, b1 = 0.f;
            if (p.bias) {
                b0 = p.bias[pr * p.biasStride + c];
                b1 = p.bias[pr * p.biasStride + c + 1];
            }
#pragma unroll
            for (int h = 0; h < 2; h++) {
                int r = rbase + i * 16 + h * 8;
                float v0 = acc[i][j][2 * h + 0] * p.alpha + b0;
                float v1 = acc[i][j][2 * h + 1] * p.alpha + b1;
                if (p.flags & 2) {
                    if (c > r)     v0 = -1e30f;
                    if (c + 1 > r) v1 = -1e30f;
                }
                if (p.flags & 1) { v0 = fmaxf(v0, 0.f); v1 = fmaxf(v1, 0.f); }
                long long off = (long long)r * p.ldc + c;
                if (p.flags & 4) *(float2*)(Cf + off) = make_float2(v0, v1);
                else {
                    __half2 hi; hi.x = __float2half(v0); hi.y = __float2half(v1);
                    *(__half2*)(Ch + off) = hi;
                }
            }
        }
}

// ---------------- merged fp32 -> fp16 conversion (one launch) ----------------
#define NCVT 14
struct CvtP {
    const float4* src[NCVT];
    __half2* dst[NCVT];
    int n4[NCVT];
};
__global__ __launch_bounds__(256) void cvt_all_k(CvtP p) {
    const int ten = blockIdx.y;
    int i = blockIdx.x * blockDim.x + threadIdx.x;
    if (i >= p.n4[ten]) return;
    float4 v = p.src[ten][i];
    __half2 h0; h0.x = __float2half(v.x); h0.y = __float2half(v.y);
    __half2 h1; h1.x = __float2half(v.z); h1.y = __float2half(v.w);
    p.dst[ten][2 * i] = h0;
    p.dst[ten][2 * i + 1] = h1;
}

// ---------------- softmax over 1024 cols ----------------
__global__ __launch_bounds__(256)
void softmax_k(__half2* S) {
    __shared__ float red[8];
    const long long row = blockIdx.x;
    __half2* sp = S + row * 512;
    const int t = threadIdx.x, lane = t & 31, w = t >> 5;
    __half2 h0 = sp[t], h1 = sp[t + 256];
    float v[4] = { __half2float(h0.x), __half2float(h0.y),
                   __half2float(h1.x), __half2float(h1.y) };

    float mx = fmaxf(fmaxf(v[0], v[1]), fmaxf(v[2], v[3]));
#pragma unroll
    for (int o = 16; o; o >>= 1) mx = fmaxf(mx, __shfl_xor_sync(~0u, mx, o));
    if (lane == 0) red[w] = mx;
    __syncthreads();
    float m2 = red[lane & 7];
#pragma unroll
    for (int o = 4; o; o >>= 1) m2 = fmaxf(m2, __shfl_xor_sync(~0u, m2, o));
    mx = m2;
    __syncthreads();

    float s = 0.f;
#pragma unroll
    for (int q = 0; q < 4; q++) { v[q] = __expf(v[q] - mx); s += v[q]; }
#pragma unroll
    for (int o = 16; o; o >>= 1) s += __shfl_xor_sync(~0u, s, o);
    if (lane == 0) red[w] = s;
    __syncthreads();
    float s2 = red[lane & 7];
#pragma unroll
    for (int o = 4; o; o >>= 1) s2 += __shfl_xor_sync(~0u, s2, o);
    float inv = 1.f / s2;

    __half2 o0, o1;
    o0.x = __float2half(v[0] * inv); o0.y = __float2half(v[1] * inv);
    o1.x = __float2half(v[2] * inv); o1.y = __float2half(v[3] * inv);
    sp[t] = o0; sp[t + 256] = o1;
}

// ---------------- residual add + LayerNorm (D=512) ----------------
__device__ __forceinline__ float bsum(float val, float* red) {
    const int lane = threadIdx.x & 31, w = threadIdx.x >> 5;
#pragma unroll
    for (int o = 16; o; o >>= 1) val += __shfl_xor_sync(~0u, val, o);
    if (lane == 0) red[w] = val;
    __syncthreads();
    float s = red[lane & 7];
#pragma unroll
    for (int o = 4; o; o >>= 1) s += __shfl_xor_sync(~0u, s, o);
    __syncthreads();
    return s;
}

__global__ __launch_bounds__(256)
void add_ln_k(const float2* __restrict__ a, const float2* __restrict__ r,
              const float* __restrict__ g, const float* __restrict__ b,
              float2* __restrict__ o, __half2* oh) {
    __shared__ float red[8];
    const long long row = blockIdx.x;
    const int t = threadIdx.x;
    float2 va = a[row * 256 + t], vr = r[row * 256 + t];
    float x0 = va.x + vr.x, x1 = va.y + vr.y;
    float mean = bsum(x0 + x1, red) * (1.f / 512.f);
    float d0 = x0 - mean, d1 = x1 - mean;
    float var = bsum(d0 * d0 + d1 * d1, red) * (1.f / 512.f);
    float inv = rsqrtf(var + 1e-5f);
    float y0 = d0 * inv * g[2 * t] + b[2 * t];
    float y1 = d1 * inv * g[2 * t + 1] + b[2 * t + 1];
    o[row * 256 + t] = make_float2(y0, y1);
    if (oh) {
        __half2 hh; hh.x = __float2half(y0); hh.y = __float2half(y1);
        oh[row * 256 + t] = hh;
    }
}

// ---------------- host ----------------
static void launch_gemm(bool nt, const GemmP& p, int M, int N, int batch) {
    dim3 g(N / 128, M / 128, batch);
    if (nt) gemm_k<true><<<g, 256, SMEM_BYTES>>>(p);
    else    gemm_k<false><<<g, 256, SMEM_BYTES>>>(p);
}

extern "C" void kernel_launch(void* const* d_in, const int* in_sizes, int n_in,
                              void* d_out, int out_size) {
    const float* x   = (const float*)d_in[0];
    const float* enc = (const float*)d_in[1];
    const float* sa_wq = (const float*)d_in[2];  const float* sa_bq = (const float*)d_in[3];
    const float* sa_wk = (const float*)d_in[4];  const float* sa_bk = (const float*)d_in[5];
    const float* sa_wv = (const float*)d_in[6];  const float* sa_bv = (const float*)d_in[7];
    const float* sa_wo = (const float*)d_in[8];  const float* sa_bo = (const float*)d_in[9];
    const float* sa_wf = (const float*)d_in[10]; const float* sa_bf = (const float*)d_in[11];
    const float* ca_wq = (const float*)d_in[12]; const float* ca_bq = (const float*)d_in[13];
    const float* ca_wk = (const float*)d_in[14]; const float* ca_bk = (const float*)d_in[15];
    const float* ca_wv = (const float*)d_in[16]; const float* ca_bv = (const float*)d_in[17];
    const float* ca_wo = (const float*)d_in[18]; const float* ca_bo = (const float*)d_in[19];
    const float* ca_wf = (const float*)d_in[20]; const float* ca_bf = (const float*)d_in[21];
    const float* ln1_g = (const float*)d_in[22]; const float* ln1_b = (const float*)d_in[23];
    const float* ln2_g = (const float*)d_in[24]; const float* ln2_b = (const float*)d_in[25];
    const float* ln3_g = (const float*)d_in[26]; const float* ln3_b = (const float*)d_in[27];
    const float* fc1_w = (const float*)d_in[28]; const float* fc1_b = (const float*)d_in[29];
    const float* fc2_w = (const float*)d_in[30]; const float* fc2_b = (const float*)d_in[31];

    cudaFuncSetAttribute((const void*)gemm_k<false>,
                         cudaFuncAttributeMaxDynamicSharedMemorySize, SMEM_BYTES);
    cudaFuncSetAttribute((const void*)gemm_k<true>,
                         cudaFuncAttributeMaxDynamicSharedMemorySize, SMEM_BYTES);

    __half *Qh, *Kh, *Vh, *Sh, *Oh, *Ph, *Mh, *Wh, *xh, *eh, *X1h, *X2h;
    float *Hf, *X1f, *X2f;
    cudaGetSymbolAddress((void**)&Qh, g_Qh);
    cudaGetSymbolAddress((void**)&Kh, g_Kh);
    cudaGetSymbolAddress((void**)&Vh, g_Vh);
    cudaGetSymbolAddress((void**)&Sh, g_Sh);
    cudaGetSymbolAddress((void**)&Oh, g_Oh);
    cudaGetSymbolAddress((void**)&Ph, g_Ph);
    cudaGetSymbolAddress((void**)&Mh, g_Mh);
    cudaGetSymbolAddress((void**)&Wh, g_Wh);
    cudaGetSymbolAddress((void**)&xh, g_xh);  cudaGetSymbolAddress((void**)&eh, g_eh);
    cudaGetSymbolAddress((void**)&X1h, g_X1h); cudaGetSymbolAddress((void**)&X2h, g_X2h);
    cudaGetSymbolAddress((void**)&Hf, g_Hf);
    cudaGetSymbolAddress((void**)&X1f, g_X1f);
    cudaGetSymbolAddress((void**)&X2f, g_X2f);

    // one merged conversion launch
    {
        CvtP cp{};
        const float* srcs[NCVT] = { x, enc, sa_wq, sa_wk, sa_wv, sa_wo, sa_wf,
                                    ca_wq, ca_wk, ca_wv, ca_wo, ca_wf, fc1_w, fc2_w };
        __half* dsts[NCVT] = { xh, eh, Wh + OW_SAQ, Wh + OW_SAK, Wh + OW_SAV,
                               Wh + OW_SAO, Wh + OW_SAF, Wh + OW_CAQ, Wh + OW_CAK,
                               Wh + OW_CAV, Wh + OW_CAO, Wh + OW_CAF,
                               Wh + OW_FC1, Wh + OW_FC2 };
        for (int i = 0; i < NCVT; i++) {
            cp.src[i] = (const float4*)srcs[i];
            cp.dst[i] = (__half2*)dsts[i];
            cp.n4[i] = (i >= 12) ? 262144 : 524288;
        }
        cvt_all_k<<<dim3(2048, NCVT), 256>>>(cp);
    }

    const float ISC = 0.044194173824159216f;  // 1/sqrt(512)

    auto runMHA = [&](const __half* aq, const __half* akv,
                      long long oq, long long ok, long long ov, long long oo, long long of,
                      const float* bq, const float* bk, const float* bv,
                      const float* bo, const float* bfb, bool causal) {
        GemmP p{};
        // Q projection
        p.Ah = aq; p.Bh = Wh + oq; p.bias = bq; p.Ch = Qh;
        p.K = 512; p.lda = 512; p.ldb = 512; p.ldc = 4096;
        p.sB2 = 262144; p.sC2 = 512;
        p.div = 8; p.biasStride = 512; p.alpha = 1.f; p.flags = 16;
        launch_gemm(false, p, 4096, 512, 8);
        // K projection
        p.Ah = akv; p.Bh = Wh + ok; p.bias = bk; p.Ch = Kh;
        launch_gemm(false, p, 4096, 512, 8);
        // V projection
        p.Bh = Wh + ov; p.bias = bv; p.Ch = Vh;
        launch_gemm(false, p, 4096, 512, 8);
        // scores = Q K^T / sqrt(512)
        p = GemmP{};
        p.Ah = Qh; p.Bh = Kh; p.Ch = Sh;
        p.K = 512; p.lda = 4096; p.ldb = 4096; p.ldc = 1024;
        p.sA1 = 4194304; p.sA2 = 512; p.sB1 = 4194304; p.sB2 = 512;
        p.sC1 = 8388608; p.sC2 = 1048576;
        p.div = 8; p.alpha = ISC; p.flags = causal ? (16 | 2) : 16;
        launch_gemm(true, p, 1024, 1024, 32);
        softmax_k<<<32768, 256>>>((__half2*)Sh);
        // O = A V  (causal: probs cols > m0+127 exactly 0 -> K-limit)
        p = GemmP{};
        p.Ah = Sh; p.Bh = Vh; p.Ch = Oh;
        p.K = 1024; p.lda = 1024; p.ldb = 4096; p.ldc = 4096;
        p.sA1 = 8388608; p.sA2 = 1048576; p.sB1 = 4194304; p.sB2 = 512;
        p.sC1 = 4194304; p.sC2 = 512;
        p.div = 8; p.alpha = 1.f; p.flags = causal ? (16 | 32) : 16;
        launch_gemm(false, p, 1024, 512, 32);
        // per-head out projection
        p = GemmP{};
        p.Ah = Oh; p.Bh = Wh + oo; p.bias = bo; p.Ch = Ph;
        p.K = 512; p.lda = 4096; p.ldb = 512; p.ldc = 4096;
        p.sA2 = 512; p.sB2 = 262144; p.sC2 = 512;
        p.div = 8; p.biasStride = 512; p.alpha = 1.f; p.flags = 16;
        launch_gemm(false, p, 4096, 512, 8);
        // final concat projection -> fp32 H
        p = GemmP{};
        p.Ah = Ph; p.Bh = Wh + of; p.bias = bfb; p.Cf = Hf;
        p.K = 4096; p.lda = 4096; p.ldb = 512; p.ldc = 512;
        p.div = 1; p.alpha = 1.f; p.flags = 4;
        launch_gemm(false, p, 4096, 512, 1);
    };

    // self-attention (causal) + LN1
    runMHA(xh, xh, OW_SAQ, OW_SAK, OW_SAV, OW_SAO, OW_SAF,
           sa_bq, sa_bk, sa_bv, sa_bo, sa_bf, true);
    add_ln_k<<<4096, 256>>>((const float2*)Hf, (const float2*)x, ln1_g, ln1_b,
                            (float2*)X1f, (__half2*)X1h);

    // cross-attention + LN2
    runMHA(X1h, eh, OW_CAQ, OW_CAK, OW_CAV, OW_CAO, OW_CAF,
           ca_bq, ca_bk, ca_bv, ca_bo, ca_bf, false);
    add_ln_k<<<4096, 256>>>((const float2*)Hf, (const float2*)X1f, ln2_g, ln2_b,
                            (float2*)X2f, (__half2*)X2h);

    // FFN
    {
        GemmP p{};
        p.Ah = X2h; p.Bh = Wh + OW_FC1; p.bias = fc1_b; p.Ch = Mh;
        p.K = 512; p.lda = 512; p.ldb = 2048; p.ldc = 2048;
        p.div = 1; p.alpha = 1.f; p.flags = 16 | 1;
        launch_gemm(false, p, 4096, 2048, 1);

        p = GemmP{};
        p.Ah = Mh; p.Bh = Wh + OW_FC2; p.bias = fc2_b; p.Cf = Hf;
        p.K = 2048; p.lda = 2048; p.ldb = 512; p.ldc = 512;
        p.div = 1; p.alpha = 1.f; p.flags = 4;
        launch_gemm(false, p, 4096, 512, 1);
    }
    add_ln_k<<<4096, 256>>>((const float2*)Hf, (const float2*)X2f, ln3_g, ln3_b,
                            (float2*)d_out, nullptr);
}

// round 9
// speedup vs baseline: 6.4288x; 1.0619x over previous
#include <cuda_runtime.h>
#include <cuda_fp16.h>
#include <math.h>

#define ASTR 40                  // A smem row stride (halfs): 32 k + 8 pad
#define BSTR 136                 // NT=false B smem row stride (halfs): 128 n + 8 pad
#define A_ST  (128 * ASTR)       // A tile halfs (5120)
#define STG   (2 * A_ST)         // stage stride in halfs (A + B region = 10240)
#define SMEM_BYTES (3 * STG * 2) // 3 stages * 20480 B = 61440

// ---------------- static scratch ----------------
__device__ __half g_Qh[16777216];
__device__ __half g_Kh[16777216];
__device__ __half g_Vh[16777216];
__device__ __half g_Sh[33554432];
__device__ __half g_Oh[16777216];
__device__ __half g_Ph[16777216];
__device__ __half g_Mh[8388608];
__device__ __half g_Wh[23068672];
__device__ __half g_xh[2097152], g_eh[2097152], g_X1h[2097152], g_X2h[2097152];
__device__ float g_Hf[2097152], g_X1f[2097152], g_X2f[2097152];

#define OW_SAQ 0LL
#define OW_SAK 2097152LL
#define OW_SAV 4194304LL
#define OW_SAO 6291456LL
#define OW_SAF 8388608LL
#define OW_CAQ 10485760LL
#define OW_CAK 12582912LL
#define OW_CAV 14680064LL
#define OW_CAO 16777216LL
#define OW_CAF 18874368LL
#define OW_FC1 20971520LL
#define OW_FC2 22020096LL

// ---------------- PTX helpers ----------------
__device__ __forceinline__ void mma16816(float* d, const unsigned* a, const unsigned* b) {
    asm volatile(
        "mma.sync.aligned.m16n8k16.row.col.f32.f16.f16.f32 "
        "{%0,%1,%2,%3}, {%4,%5,%6,%7}, {%8,%9}, {%0,%1,%2,%3};"
        : "+f"(d[0]), "+f"(d[1]), "+f"(d[2]), "+f"(d[3])
        : "r"(a[0]), "r"(a[1]), "r"(a[2]), "r"(a[3]), "r"(b[0]), "r"(b[1]));
}
__device__ __forceinline__ void ldsm4(unsigned* r, unsigned a) {
    asm volatile("ldmatrix.sync.aligned.m8n8.x4.shared.b16 {%0,%1,%2,%3}, [%4];"
                 : "=r"(r[0]), "=r"(r[1]), "=r"(r[2]), "=r"(r[3]) : "r"(a));
}
__device__ __forceinline__ void ldsm4t(unsigned* r, unsigned a) {
    asm volatile("ldmatrix.sync.aligned.m8n8.x4.trans.shared.b16 {%0,%1,%2,%3}, [%4];"
                 : "=r"(r[0]), "=r"(r[1]), "=r"(r[2]), "=r"(r[3]) : "r"(a));
}
__device__ __forceinline__ void cp16(unsigned d, const void* s) {
    asm volatile("cp.async.cg.shared.global [%0], [%1], 16;" :: "r"(d), "l"(s));
}

// ---------------- GEMM: C = alpha * A*B + bias ----------------
// A [M,K] fp16 row-major.
// NT=true : B [N,K] row-major (smem [n][k], non-trans ldmatrix)
// NT=false: B [K,N] row-major (smem [k][n], trans ldmatrix)
// flags: 1 relu, 2 causal mask, 4 fp32 out, 16 fp16 out, 32 causal K-limit
struct GemmP {
    const __half *Ah, *Bh;
    const float* bias;
    __half *Ch;
    float* Cf;
    int K, lda, ldb, ldc;
    long long sA1, sA2, sB1, sB2, sC1, sC2;
    int div, biasStride;
    float alpha; int flags;
};

template<bool NT>
__global__ __launch_bounds__(256) void gemm_k(GemmP p) {
    extern __shared__ unsigned char raw[];
    __half* Sm = (__half*)raw;

    const int pb = blockIdx.z, pq = pb / p.div, pr = pb - pq * p.div;
    const int tid = threadIdx.x, lane = tid & 31, warp = tid >> 5;
    const int wm = warp >> 1, wn = warp & 1;
    const int m0 = blockIdx.y * 128, n0 = blockIdx.x * 128;

    // fully-masked causal tile: write -inf, skip compute
    if ((p.flags & 2) && n0 > m0 + 127) {
        __half2* Ch2 = (__half2*)(p.Ch + pq * p.sC1 + pr * p.sC2);
        const __half2 mi = __half2half2(__float2half(-1e30f));
        for (int i = tid; i < 128 * 64; i += 256) {
            int r = i >> 6, c = i & 63;
            Ch2[((long long)(m0 + r) * p.ldc + n0) / 2 + c] = mi;
        }
        return;
    }

    const int Klim = (p.flags & 32) ? (m0 + 128 < p.K ? m0 + 128 : p.K) : p.K;
    const int nch = Klim >> 5;          // number of 32-k chunks (always >= 2 here)

    const __half* Abase = p.Ah + pq * p.sA1 + pr * p.sA2;
    const __half* Bbase = p.Bh + pq * p.sB1 + pr * p.sB2;

    const unsigned sBase = (unsigned)__cvta_generic_to_shared(Sm);

    const int crow = tid >> 2, cseg = (tid & 3) * 8;

    float acc[2][8][4];
#pragma unroll
    for (int i = 0; i < 2; i++)
#pragma unroll
        for (int j = 0; j < 8; j++)
#pragma unroll
            for (int q = 0; q < 4; q++) acc[i][j][q] = 0.f;

    auto issue_stage = [&](int st, int kt) {
        const unsigned sA = sBase + 2u * (st * STG);
        const unsigned sB = sA + 2u * A_ST;
#pragma unroll
        for (int r = 0; r < 2; r++) {
            int row = crow + r * 64;
            cp16(sA + 2u * (row * ASTR + cseg),
                 Abase + (long long)(m0 + row) * p.lda + kt + cseg);
        }
        if (NT) {
#pragma unroll
            for (int r = 0; r < 2; r++) {
                int row = crow + r * 64;
                cp16(sB + 2u * (row * ASTR + cseg),
                     Bbase + (long long)(n0 + row) * p.ldb + kt + cseg);
            }
        } else {
#pragma unroll
            for (int it = 0; it < 2; it++) {
                int i = tid + it * 256;
                int row = i >> 4, seg = i & 15;
                cp16(sB + 2u * (row * BSTR + seg * 8),
                     Bbase + (long long)(kt + row) * p.ldb + n0 + seg * 8);
            }
        }
        asm volatile("cp.async.commit_group;");
    };

    // prologue: 2 stages in flight
    issue_stage(0, 0);
    issue_stage(1, 32);
    asm volatile("cp.async.wait_group 1;" ::: "memory");
    __syncthreads();

    int st = 0;
    for (int c = 0; c < nch; c++) {
        if (c + 2 < nch) issue_stage((c + 2) % 3, (c + 2) * 32);
        const unsigned sA = sBase + 2u * (st * STG);
        const unsigned sB = sA + 2u * A_ST;
#pragma unroll
        for (int ks = 0; ks < 32; ks += 16) {
            unsigned ah[2][4], bh[8][2];
#pragma unroll
            for (int i = 0; i < 2; i++) {
                int row = wm * 32 + i * 16 + (lane & 15);
                int ko = ks + (lane >> 4) * 8;
                ldsm4(ah[i], sA + 2u * (row * ASTR + ko));
            }
#pragma unroll
            for (int jj = 0; jj < 4; jj++) {
                unsigned t0[4];
                if (NT) {
                    int row = wn * 64 + jj * 16 + (lane & 7) + ((lane >> 4) & 1) * 8;
                    int ko = ks + ((lane >> 3) & 1) * 8;
                    ldsm4(t0, sB + 2u * (row * ASTR + ko));
                } else {
                    int krow = ks + (lane & 7) + ((lane >> 3) & 1) * 8;
                    int ncol = wn * 64 + jj * 16 + ((lane >> 4) & 1) * 8;
                    ldsm4t(t0, sB + 2u * (krow * BSTR + ncol));
                }
                bh[2 * jj][0] = t0[0]; bh[2 * jj][1] = t0[1];
                bh[2 * jj + 1][0] = t0[2]; bh[2 * jj + 1][1] = t0[3];
            }
#pragma unroll
            for (int i = 0; i < 2; i++)
#pragma unroll
                for (int j = 0; j < 8; j++)
                    mma16816(acc[i][j], ah[i], bh[j]);
        }
        if (c + 1 < nch) {
            if (c + 2 < nch) { asm volatile("cp.async.wait_group 1;" ::: "memory"); }
            else             { asm volatile("cp.async.wait_group 0;" ::: "memory"); }
            __syncthreads();
        }
        st = (st == 2) ? 0 : st + 1;
    }

    // epilogue
    __half* Ch = (p.flags & 16) ? p.Ch + pq * p.sC1 + pr * p.sC2 : nullptr;
    float*  Cf = (p.flags & 4)  ? p.Cf + pq * p.sC1 + pr * p.sC2 : nullptr;
    const int rbase = m0 + wm * 32 + (lane >> 2);
    const int cbase = n0 + wn * 64 + (lane & 3) * 2;
#pragma unroll
    for (int i = 0; i < 2; i++)
#pragma unroll
        for (int j = 0; j < 8; j++) {
            int c = cbase + j * 8;
            float b0 = 0.f, b1 = 0.f;
            if (p.bias) {
                b0 = p.bias[pr * p.biasStride + c];
                b1 = p.bias[pr * p.biasStride + c + 1];
            }
#pragma unroll
            for (int h = 0; h < 2; h++) {
                int r = rbase + i * 16 + h * 8;
                float v0 = acc[i][j][2 * h + 0] * p.alpha + b0;
                float v1 = acc[i][j][2 * h + 1] * p.alpha + b1;
                if (p.flags & 2) {
                    if (c > r)     v0 = -1e30f;
                    if (c + 1 > r) v1 = -1e30f;
                }
                if (p.flags & 1) { v0 = fmaxf(v0, 0.f); v1 = fmaxf(v1, 0.f); }
                long long off = (long long)r * p.ldc + c;
                if (p.flags & 4) *(float2*)(Cf + off) = make_float2(v0, v1);
                else {
                    __half2 hi; hi.x = __float2half(v0); hi.y = __float2half(v1);
                    *(__half2*)(Ch + off) = hi;
                }
            }
        }
}

// ---------------- merged fp32 -> fp16 conversion (one launch) ----------------
#define NCVT 14
struct CvtP {
    const float4* src[NCVT];
    __half2* dst[NCVT];
    int n4[NCVT];
};
__global__ __launch_bounds__(256) void cvt_all_k(CvtP p) {
    const int ten = blockIdx.y;
    int i = blockIdx.x * blockDim.x + threadIdx.x;
    if (i >= p.n4[ten]) return;
    float4 v = p.src[ten][i];
    __half2 h0; h0.x = __float2half(v.x); h0.y = __float2half(v.y);
    __half2 h1; h1.x = __float2half(v.z); h1.y = __float2half(v.w);
    p.dst[ten][2 * i] = h0;
    p.dst[ten][2 * i + 1] = h1;
}

// ---------------- softmax over 1024 cols ----------------
__global__ __launch_bounds__(256)
void softmax_k(__half2* S) {
    __shared__ float red[8];
    const long long row = blockIdx.x;
    __half2* sp = S + row * 512;
    const int t = threadIdx.x, lane = t & 31, w = t >> 5;
    __half2 h0 = sp[t], h1 = sp[t + 256];
    float v[4] = { __half2float(h0.x), __half2float(h0.y),
                   __half2float(h1.x), __half2float(h1.y) };

    float mx = fmaxf(fmaxf(v[0], v[1]), fmaxf(v[2], v[3]));
#pragma unroll
    for (int o = 16; o; o >>= 1) mx = fmaxf(mx, __shfl_xor_sync(~0u, mx, o));
    if (lane == 0) red[w] = mx;
    __syncthreads();
    float m2 = red[lane & 7];
#pragma unroll
    for (int o = 4; o; o >>= 1) m2 = fmaxf(m2, __shfl_xor_sync(~0u, m2, o));
    mx = m2;
    __syncthreads();

    float s = 0.f;
#pragma unroll
    for (int q = 0; q < 4; q++) { v[q] = __expf(v[q] - mx); s += v[q]; }
#pragma unroll
    for (int o = 16; o; o >>= 1) s += __shfl_xor_sync(~0u, s, o);
    if (lane == 0) red[w] = s;
    __syncthreads();
    float s2 = red[lane & 7];
#pragma unroll
    for (int o = 4; o; o >>= 1) s2 += __shfl_xor_sync(~0u, s2, o);
    float inv = 1.f / s2;

    __half2 o0, o1;
    o0.x = __float2half(v[0] * inv); o0.y = __float2half(v[1] * inv);
    o1.x = __float2half(v[2] * inv); o1.y = __float2half(v[3] * inv);
    sp[t] = o0; sp[t + 256] = o1;
}

// ---------------- residual add + LayerNorm (D=512) ----------------
__device__ __forceinline__ float bsum(float val, float* red) {
    const int lane = threadIdx.x & 31, w = threadIdx.x >> 5;
#pragma unroll
    for (int o = 16; o; o >>= 1) val += __shfl_xor_sync(~0u, val, o);
    if (lane == 0) red[w] = val;
    __syncthreads();
    float s = red[lane & 7];
#pragma unroll
    for (int o = 4; o; o >>= 1) s += __shfl_xor_sync(~0u, s, o);
    __syncthreads();
    return s;
}

__global__ __launch_bounds__(256)
void add_ln_k(const float2* __restrict__ a, const float2* __restrict__ r,
              const float* __restrict__ g, const float* __restrict__ b,
              float2* __restrict__ o, __half2* oh) {
    __shared__ float red[8];
    const long long row = blockIdx.x;
    const int t = threadIdx.x;
    float2 va = a[row * 256 + t], vr = r[row * 256 + t];
    float x0 = va.x + vr.x, x1 = va.y + vr.y;
    float mean = bsum(x0 + x1, red) * (1.f / 512.f);
    float d0 = x0 - mean, d1 = x1 - mean;
    float var = bsum(d0 * d0 + d1 * d1, red) * (1.f / 512.f);
    float inv = rsqrtf(var + 1e-5f);
    float y0 = d0 * inv * g[2 * t] + b[2 * t];
    float y1 = d1 * inv * g[2 * t + 1] + b[2 * t + 1];
    o[row * 256 + t] = make_float2(y0, y1);
    if (oh) {
        __half2 hh; hh.x = __float2half(y0); hh.y = __float2half(y1);
        oh[row * 256 + t] = hh;
    }
}

// ---------------- host ----------------
static void launch_gemm(bool nt, const GemmP& p, int M, int N, int batch) {
    dim3 g(N / 128, M / 128, batch);
    if (nt) gemm_k<true><<<g, 256, SMEM_BYTES>>>(p);
    else    gemm_k<false><<<g, 256, SMEM_BYTES>>>(p);
}

extern "C" void kernel_launch(void* const* d_in, const int* in_sizes, int n_in,
                              void* d_out, int out_size) {
    const float* x   = (const float*)d_in[0];
    const float* enc = (const float*)d_in[1];
    const float* sa_wq = (const float*)d_in[2];  const float* sa_bq = (const float*)d_in[3];
    const float* sa_wk = (const float*)d_in[4];  const float* sa_bk = (const float*)d_in[5];
    const float* sa_wv = (const float*)d_in[6];  const float* sa_bv = (const float*)d_in[7];
    const float* sa_wo = (const float*)d_in[8];  const float* sa_bo = (const float*)d_in[9];
    const float* sa_wf = (const float*)d_in[10]; const float* sa_bf = (const float*)d_in[11];
    const float* ca_wq = (const float*)d_in[12]; const float* ca_bq = (const float*)d_in[13];
    const float* ca_wk = (const float*)d_in[14]; const float* ca_bk = (const float*)d_in[15];
    const float* ca_wv = (const float*)d_in[16]; const float* ca_bv = (const float*)d_in[17];
    const float* ca_wo = (const float*)d_in[18]; const float* ca_bo = (const float*)d_in[19];
    const float* ca_wf = (const float*)d_in[20]; const float* ca_bf = (const float*)d_in[21];
    const float* ln1_g = (const float*)d_in[22]; const float* ln1_b = (const float*)d_in[23];
    const float* ln2_g = (const float*)d_in[24]; const float* ln2_b = (const float*)d_in[25];
    const float* ln3_g = (const float*)d_in[26]; const float* ln3_b = (const float*)d_in[27];
    const float* fc1_w = (const float*)d_in[28]; const float* fc1_b = (const float*)d_in[29];
    const float* fc2_w = (const float*)d_in[30]; const float* fc2_b = (const float*)d_in[31];

    cudaFuncSetAttribute((const void*)gemm_k<false>,
                         cudaFuncAttributeMaxDynamicSharedMemorySize, SMEM_BYTES);
    cudaFuncSetAttribute((const void*)gemm_k<true>,
                         cudaFuncAttributeMaxDynamicSharedMemorySize, SMEM_BYTES);

    __half *Qh, *Kh, *Vh, *Sh, *Oh, *Ph, *Mh, *Wh, *xh, *eh, *X1h, *X2h;
    float *Hf, *X1f, *X2f;
    cudaGetSymbolAddress((void**)&Qh, g_Qh);
    cudaGetSymbolAddress((void**)&Kh, g_Kh);
    cudaGetSymbolAddress((void**)&Vh, g_Vh);
    cudaGetSymbolAddress((void**)&Sh, g_Sh);
    cudaGetSymbolAddress((void**)&Oh, g_Oh);
    cudaGetSymbolAddress((void**)&Ph, g_Ph);
    cudaGetSymbolAddress((void**)&Mh, g_Mh);
    cudaGetSymbolAddress((void**)&Wh, g_Wh);
    cudaGetSymbolAddress((void**)&xh, g_xh);  cudaGetSymbolAddress((void**)&eh, g_eh);
    cudaGetSymbolAddress((void**)&X1h, g_X1h); cudaGetSymbolAddress((void**)&X2h, g_X2h);
    cudaGetSymbolAddress((void**)&Hf, g_Hf);
    cudaGetSymbolAddress((void**)&X1f, g_X1f);
    cudaGetSymbolAddress((void**)&X2f, g_X2f);

    // one merged conversion launch
    {
        CvtP cp{};
        const float* srcs[NCVT] = { x, enc, sa_wq, sa_wk, sa_wv, sa_wo, sa_wf,
                                    ca_wq, ca_wk, ca_wv, ca_wo, ca_wf, fc1_w, fc2_w };
        __half* dsts[NCVT] = { xh, eh, Wh + OW_SAQ, Wh + OW_SAK, Wh + OW_SAV,
                               Wh + OW_SAO, Wh + OW_SAF, Wh + OW_CAQ, Wh + OW_CAK,
                               Wh + OW_CAV, Wh + OW_CAO, Wh + OW_CAF,
                               Wh + OW_FC1, Wh + OW_FC2 };
        for (int i = 0; i < NCVT; i++) {
            cp.src[i] = (const float4*)srcs[i];
            cp.dst[i] = (__half2*)dsts[i];
            cp.n4[i] = (i >= 12) ? 262144 : 524288;
        }
        cvt_all_k<<<dim3(2048, NCVT), 256>>>(cp);
    }

    const float ISC = 0.044194173824159216f;  // 1/sqrt(512)

    auto runMHA = [&](const __half* aq, const __half* akv,
                      long long oq, long long ok, long long ov, long long oo, long long of,
                      const float* bq, const float* bk, const float* bv,
                      const float* bo, const float* bfb, bool causal) {
        GemmP p{};
        // Q projection
        p.Ah = aq; p.Bh = Wh + oq; p.bias = bq; p.Ch = Qh;
        p.K = 512; p.lda = 512; p.ldb = 512; p.ldc = 4096;
        p.sB2 = 262144; p.sC2 = 512;
        p.div = 8; p.biasStride = 512; p.alpha = 1.f; p.flags = 16;
        launch_gemm(false, p, 4096, 512, 8);
        // K projection
        p.Ah = akv; p.Bh = Wh + ok; p.bias = bk; p.Ch = Kh;
        launch_gemm(false, p, 4096, 512, 8);
        // V projection
        p.Bh = Wh + ov; p.bias = bv; p.Ch = Vh;
        launch_gemm(false, p, 4096, 512, 8);
        // scores = Q K^T / sqrt(512)
        p = GemmP{};
        p.Ah = Qh; p.Bh = Kh; p.Ch = Sh;
        p.K = 512; p.lda = 4096; p.ldb = 4096; p.ldc = 1024;
        p.sA1 = 4194304; p.sA2 = 512; p.sB1 = 4194304; p.sB2 = 512;
        p.sC1 = 8388608; p.sC2 = 1048576;
        p.div = 8; p.alpha = ISC; p.flags = causal ? (16 | 2) : 16;
        launch_gemm(true, p, 1024, 1024, 32);
        softmax_k<<<32768, 256>>>((__half2*)Sh);
        // O = A V  (causal: probs cols > m0+127 exactly 0 -> K-limit)
        p = GemmP{};
        p.Ah = Sh; p.Bh = Vh; p.Ch = Oh;
        p.K = 1024; p.lda = 1024; p.ldb = 4096; p.ldc = 4096;
        p.sA1 = 8388608; p.sA2 = 1048576; p.sB1 = 4194304; p.sB2 = 512;
        p.sC1 = 4194304; p.sC2 = 512;
        p.div = 8; p.alpha = 1.f; p.flags = causal ? (16 | 32) : 16;
        launch_gemm(false, p, 1024, 512, 32);
        // per-head out projection
        p = GemmP{};
        p.Ah = Oh; p.Bh = Wh + oo; p.bias = bo; p.Ch = Ph;
        p.K = 512; p.lda = 4096; p.ldb = 512; p.ldc = 4096;
        p.sA2 = 512; p.sB2 = 262144; p.sC2 = 512;
        p.div = 8; p.biasStride = 512; p.alpha = 1.f; p.flags = 16;
        launch_gemm(false, p, 4096, 512, 8);
        // final concat projection -> fp32 H
        p = GemmP{};
        p.Ah = Ph; p.Bh = Wh + of; p.bias = bfb; p.Cf = Hf;
        p.K = 4096; p.lda = 4096; p.ldb = 512; p.ldc = 512;
        p.div = 1; p.alpha = 1.f; p.flags = 4;
        launch_gemm(false, p, 4096, 512, 1);
    };

    // self-attention (causal) + LN1
    runMHA(xh, xh, OW_SAQ, OW_SAK, OW_SAV, OW_SAO, OW_SAF,
           sa_bq, sa_bk, sa_bv, sa_bo, sa_bf, true);
    add_ln_k<<<4096, 256>>>((const float2*)Hf, (const float2*)x, ln1_g, ln1_b,
                            (float2*)X1f, (__half2*)X1h);

    // cross-attention + LN2
    runMHA(X1h, eh, OW_CAQ, OW_CAK, OW_CAV, OW_CAO, OW_CAF,
           ca_bq, ca_bk, ca_bv, ca_bo, ca_bf, false);
    add_ln_k<<<4096, 256>>>((const float2*)Hf, (const float2*)X1f, ln2_g, ln2_b,
                            (float2*)X2f, (__half2*)X2h);

    // FFN
    {
        GemmP p{};
        p.Ah = X2h; p.Bh = Wh + OW_FC1; p.bias = fc1_b; p.Ch = Mh;
        p.K = 512; p.lda = 512; p.ldb = 2048; p.ldc = 2048;
        p.div = 1; p.alpha = 1.f; p.flags = 16 | 1;
        launch_gemm(false, p, 4096, 2048, 1);

        p = GemmP{};
        p.Ah = Mh; p.Bh = Wh + OW_FC2; p.bias = fc2_b; p.Cf = Hf;
        p.K = 2048; p.lda = 2048; p.ldb = 512; p.ldc = 512;
        p.div = 1; p.alpha = 1.f; p.flags = 4;
        launch_gemm(false, p, 4096, 512, 1);
    }
    add_ln_k<<<4096, 256>>>((const float2*)Hf, (const float2*)X2f, ln3_g, ln3_b,
                            (float2*)d_out, nullptr);
}

// round 10
// speedup vs baseline: 7.1205x; 1.1076x over previous
#include <cuda_runtime.h>
#include <cuda_fp16.h>
#include <math.h>

#define ASTR 72                  // A smem row stride (halfs): 64 k + 8 pad
#define BSTR 136                 // NT=false B smem row stride (halfs): 128 n + 8 pad
#define A_ST  (128 * ASTR)       // A tile halfs (9216)
#define STG   (2 * A_ST)         // stage stride halfs (A + B region = 18432)
#define SMEM_BYTES (3 * STG * 2) // 3 stages * 36864 B = 110592

// ---------------- static scratch ----------------
__device__ __half g_QKV[50331648];       // Q | K | V, 16M halfs each
__device__ __half g_Sh[33554432];
__device__ __half g_Oh[16777216];
__device__ __half g_Ph[16777216];
__device__ __half g_Mh[8388608];
__device__ __half g_Wh[23068672];
__device__ __half g_xh[2097152], g_eh[2097152], g_X1h[2097152], g_X2h[2097152];
__device__ float g_Hf[2097152], g_X1f[2097152], g_X2f[2097152];

#define OW_SAQ 0LL
#define OW_SAK 2097152LL
#define OW_SAV 4194304LL
#define OW_SAO 6291456LL
#define OW_SAF 8388608LL
#define OW_CAQ 10485760LL
#define OW_CAK 12582912LL
#define OW_CAV 14680064LL
#define OW_CAO 16777216LL
#define OW_CAF 18874368LL
#define OW_FC1 20971520LL
#define OW_FC2 22020096LL

// ---------------- PTX helpers ----------------
__device__ __forceinline__ void mma16816(float* d, const unsigned* a, const unsigned* b) {
    asm volatile(
        "mma.sync.aligned.m16n8k16.row.col.f32.f16.f16.f32 "
        "{%0,%1,%2,%3}, {%4,%5,%6,%7}, {%8,%9}, {%0,%1,%2,%3};"
        : "+f"(d[0]), "+f"(d[1]), "+f"(d[2]), "+f"(d[3])
        : "r"(a[0]), "r"(a[1]), "r"(a[2]), "r"(a[3]), "r"(b[0]), "r"(b[1]));
}
__device__ __forceinline__ void ldsm4(unsigned* r, unsigned a) {
    asm volatile("ldmatrix.sync.aligned.m8n8.x4.shared.b16 {%0,%1,%2,%3}, [%4];"
                 : "=r"(r[0]), "=r"(r[1]), "=r"(r[2]), "=r"(r[3]) : "r"(a));
}
__device__ __forceinline__ void ldsm4t(unsigned* r, unsigned a) {
    asm volatile("ldmatrix.sync.aligned.m8n8.x4.trans.shared.b16 {%0,%1,%2,%3}, [%4];"
                 : "=r"(r[0]), "=r"(r[1]), "=r"(r[2]), "=r"(r[3]) : "r"(a));
}
__device__ __forceinline__ void cp16(unsigned d, const void* s) {
    asm volatile("cp.async.cg.shared.global [%0], [%1], 16;" :: "r"(d), "l"(s));
}

// ---------------- GEMM: C = alpha * A*B + bias ----------------
// A [M,K] fp16 row-major.
// NT=true : B [N,K] row-major (smem [n][k], non-trans ldmatrix)
// NT=false: B [K,N] row-major (smem [k][n], trans ldmatrix)
// flags: 1 relu, 2 causal mask, 4 fp32 out, 16 fp16 out, 32 causal K-limit,
//        64 multi-op mode: pq>0 -> A=Ah2; bias selected from {bias,biasB,biasC}[pq]
struct GemmP {
    const __half *Ah, *Ah2, *Bh;
    const float *bias, *biasB, *biasC;
    __half *Ch;
    float* Cf;
    int K, lda, ldb, ldc;
    long long sA1, sA2, sB1, sB2, sC1, sC2;
    int div, biasStride;
    float alpha; int flags;
};

template<bool NT>
__global__ __launch_bounds__(256, 2) void gemm_k(GemmP p) {
    extern __shared__ unsigned char raw[];
    __half* Sm = (__half*)raw;

    const int pb = blockIdx.z, pq = pb / p.div, pr = pb - pq * p.div;
    const int tid = threadIdx.x, lane = tid & 31, warp = tid >> 5;
    const int wm = warp >> 1, wn = warp & 1;
    const int m0 = blockIdx.y * 128, n0 = blockIdx.x * 128;

    // fully-masked causal tile: write -inf, skip compute
    if ((p.flags & 2) && n0 > m0 + 127) {
        __half2* Ch2 = (__half2*)(p.Ch + pq * p.sC1 + pr * p.sC2);
        const __half2 mi = __half2half2(__float2half(-1e30f));
        for (int i = tid; i < 128 * 64; i += 256) {
            int r = i >> 6, c = i & 63;
            Ch2[((long long)(m0 + r) * p.ldc + n0) / 2 + c] = mi;
        }
        return;
    }

    const int Klim = (p.flags & 32) ? (m0 + 128 < p.K ? m0 + 128 : p.K) : p.K;
    const int nch = Klim >> 6;               // 64-k chunks, always >= 2

    const __half* Abase = ((p.flags & 64) && pq > 0) ? p.Ah2 : p.Ah;
    Abase += pq * p.sA1 + pr * p.sA2;
    const __half* Bbase = p.Bh + pq * p.sB1 + pr * p.sB2;
    const float* bias = p.bias;
    if (p.flags & 64) bias = (pq == 0) ? p.bias : ((pq == 1) ? p.biasB : p.biasC);

    const unsigned sBase = (unsigned)__cvta_generic_to_shared(Sm);

    float acc[2][8][4];
#pragma unroll
    for (int i = 0; i < 2; i++)
#pragma unroll
        for (int j = 0; j < 8; j++)
#pragma unroll
            for (int q = 0; q < 4; q++) acc[i][j][q] = 0.f;

    auto issue_stage = [&](int st, int kt) {
        const unsigned sA = sBase + 2u * (st * STG);
        const unsigned sB = sA + 2u * A_ST;
        // A: 128 rows x 8 segs(16B) = 1024 cp16 -> 4/thread
#pragma unroll
        for (int it = 0; it < 4; it++) {
            int i = tid + it * 256;
            int row = i >> 3, seg = i & 7;
            cp16(sA + 2u * (row * ASTR + seg * 8),
                 Abase + (long long)(m0 + row) * p.lda + kt + seg * 8);
        }
        if (NT) {
#pragma unroll
            for (int it = 0; it < 4; it++) {
                int i = tid + it * 256;
                int row = i >> 3, seg = i & 7;
                cp16(sB + 2u * (row * ASTR + seg * 8),
                     Bbase + (long long)(n0 + row) * p.ldb + kt + seg * 8);
            }
        } else {
            // B: 64 k-rows x 16 segs(16B) = 1024 cp16 -> 4/thread
#pragma unroll
            for (int it = 0; it < 4; it++) {
                int i = tid + it * 256;
                int row = i >> 4, seg = i & 15;
                cp16(sB + 2u * (row * BSTR + seg * 8),
                     Bbase + (long long)(kt + row) * p.ldb + n0 + seg * 8);
            }
        }
        asm volatile("cp.async.commit_group;");
    };

    // prologue: 2 stages in flight
    issue_stage(0, 0);
    issue_stage(1, 64);
    asm volatile("cp.async.wait_group 1;" ::: "memory");
    __syncthreads();

    int st = 0;
    for (int c = 0; c < nch; c++) {
        if (c + 2 < nch) issue_stage((c + 2) % 3, (c + 2) * 64);
        const unsigned sA = sBase + 2u * (st * STG);
        const unsigned sB = sA + 2u * A_ST;
#pragma unroll
        for (int ks = 0; ks < 64; ks += 16) {
            unsigned ah[2][4], bh[8][2];
#pragma unroll
            for (int i = 0; i < 2; i++) {
                int row = wm * 32 + i * 16 + (lane & 15);
                int ko = ks + (lane >> 4) * 8;
                ldsm4(ah[i], sA + 2u * (row * ASTR + ko));
            }
#pragma unroll
            for (int jj = 0; jj < 4; jj++) {
                unsigned t0[4];
                if (NT) {
                    int row = wn * 64 + jj * 16 + (lane & 7) + ((lane >> 4) & 1) * 8;
                    int ko = ks + ((lane >> 3) & 1) * 8;
                    ldsm4(t0, sB + 2u * (row * ASTR + ko));
                } else {
                    int krow = ks + (lane & 7) + ((lane >> 3) & 1) * 8;
                    int ncol = wn * 64 + jj * 16 + ((lane >> 4) & 1) * 8;
                    ldsm4t(t0, sB + 2u * (krow * BSTR + ncol));
                }
                bh[2 * jj][0] = t0[0]; bh[2 * jj][1] = t0[1];
                bh[2 * jj + 1][0] = t0[2]; bh[2 * jj + 1][1] = t0[3];
            }
#pragma unroll
            for (int i = 0; i < 2; i++)
#pragma unroll
                for (int j = 0; j < 8; j++)
                    mma16816(acc[i][j], ah[i], bh[j]);
        }
        if (c + 1 < nch) {
            if (c + 2 < nch) { asm volatile("cp.async.wait_group 1;" ::: "memory"); }
            else             { asm volatile("cp.async.wait_group 0;" ::: "memory"); }
            __syncthreads();
        }
        st = (st == 2) ? 0 : st + 1;
    }

    // epilogue
    __half* Ch = (p.flags & 16) ? p.Ch + pq * p.sC1 + pr * p.sC2 : nullptr;
    float*  Cf = (p.flags & 4)  ? p.Cf + pq * p.sC1 + pr * p.sC2 : nullptr;
    const int rbase = m0 + wm * 32 + (lane >> 2);
    const int cbase = n0 + wn * 64 + (lane & 3) * 2;
#pragma unroll
    for (int i = 0; i < 2; i++)
#pragma unroll
        for (int j = 0; j < 8; j++) {
            int c = cbase + j * 8;
            float b0 = 0.f, b1 = 0.f;
            if (bias) {
                b0 = bias[pr * p.biasStride + c];
                b1 = bias[pr * p.biasStride + c + 1];
            }
#pragma unroll
            for (int h = 0; h < 2; h++) {
                int r = rbase + i * 16 + h * 8;
                float v0 = acc[i][j][2 * h + 0] * p.alpha + b0;
                float v1 = acc[i][j][2 * h + 1] * p.alpha + b1;
                if (p.flags & 2) {
                    if (c > r)     v0 = -1e30f;
                    if (c + 1 > r) v1 = -1e30f;
                }
                if (p.flags & 1) { v0 = fmaxf(v0, 0.f); v1 = fmaxf(v1, 0.f); }
                long long off = (long long)r * p.ldc + c;
                if (p.flags & 4) *(float2*)(Cf + off) = make_float2(v0, v1);
                else {
                    __half2 hi; hi.x = __float2half(v0); hi.y = __float2half(v1);
                    *(__half2*)(Ch + off) = hi;
                }
            }
        }
}

// ---------------- merged fp32 -> fp16 conversion (one launch) ----------------
#define NCVT 14
struct CvtP {
    const float4* src[NCVT];
    __half2* dst[NCVT];
    int n4[NCVT];
};
__global__ __launch_bounds__(256) void cvt_all_k(CvtP p) {
    const int ten = blockIdx.y;
    int i = blockIdx.x * blockDim.x + threadIdx.x;
    if (i >= p.n4[ten]) return;
    float4 v = p.src[ten][i];
    __half2 h0; h0.x = __float2half(v.x); h0.y = __float2half(v.y);
    __half2 h1; h1.x = __float2half(v.z); h1.y = __float2half(v.w);
    p.dst[ten][2 * i] = h0;
    p.dst[ten][2 * i + 1] = h1;
}

// ---------------- softmax over 1024 cols ----------------
__global__ __launch_bounds__(256)
void softmax_k(__half2* S) {
    __shared__ float red[8];
    const long long row = blockIdx.x;
    __half2* sp = S + row * 512;
    const int t = threadIdx.x, lane = t & 31, w = t >> 5;
    __half2 h0 = sp[t], h1 = sp[t + 256];
    float v[4] = { __half2float(h0.x), __half2float(h0.y),
                   __half2float(h1.x), __half2float(h1.y) };

    float mx = fmaxf(fmaxf(v[0], v[1]), fmaxf(v[2], v[3]));
#pragma unroll
    for (int o = 16; o; o >>= 1) mx = fmaxf(mx, __shfl_xor_sync(~0u, mx, o));
    if (lane == 0) red[w] = mx;
    __syncthreads();
    float m2 = red[lane & 7];
#pragma unroll
    for (int o = 4; o; o >>= 1) m2 = fmaxf(m2, __shfl_xor_sync(~0u, m2, o));
    mx = m2;
    __syncthreads();

    float s = 0.f;
#pragma unroll
    for (int q = 0; q < 4; q++) { v[q] = __expf(v[q] - mx); s += v[q]; }
#pragma unroll
    for (int o = 16; o; o >>= 1) s += __shfl_xor_sync(~0u, s, o);
    if (lane == 0) red[w] = s;
    __syncthreads();
    float s2 = red[lane & 7];
#pragma unroll
    for (int o = 4; o; o >>= 1) s2 += __shfl_xor_sync(~0u, s2, o);
    float inv = 1.f / s2;

    __half2 o0, o1;
    o0.x = __float2half(v[0] * inv); o0.y = __float2half(v[1] * inv);
    o1.x = __float2half(v[2] * inv); o1.y = __float2half(v[3] * inv);
    sp[t] = o0; sp[t + 256] = o1;
}

// ---------------- residual add + LayerNorm (D=512) ----------------
__device__ __forceinline__ float bsum(float val, float* red) {
    const int lane = threadIdx.x & 31, w = threadIdx.x >> 5;
#pragma unroll
    for (int o = 16; o; o >>= 1) val += __shfl_xor_sync(~0u, val, o);
    if (lane == 0) red[w] = val;
    __syncthreads();
    float s = red[lane & 7];
#pragma unroll
    for (int o = 4; o; o >>= 1) s += __shfl_xor_sync(~0u, s, o);
    __syncthreads();
    return s;
}

__global__ __launch_bounds__(256)
void add_ln_k(const float2* __restrict__ a, const float2* __restrict__ r,
              const float* __restrict__ g, const float* __restrict__ b,
              float2* __restrict__ o, __half2* oh) {
    __shared__ float red[8];
    const long long row = blockIdx.x;
    const int t = threadIdx.x;
    float2 va = a[row * 256 + t], vr = r[row * 256 + t];
    float x0 = va.x + vr.x, x1 = va.y + vr.y;
    float mean = bsum(x0 + x1, red) * (1.f / 512.f);
    float d0 = x0 - mean, d1 = x1 - mean;
    float var = bsum(d0 * d0 + d1 * d1, red) * (1.f / 512.f);
    float inv = rsqrtf(var + 1e-5f);
    float y0 = d0 * inv * g[2 * t] + b[2 * t];
    float y1 = d1 * inv * g[2 * t + 1] + b[2 * t + 1];
    o[row * 256 + t] = make_float2(y0, y1);
    if (oh) {
        __half2 hh; hh.x = __float2half(y0); hh.y = __float2half(y1);
        oh[row * 256 + t] = hh;
    }
}

// ---------------- host ----------------
static void launch_gemm(bool nt, const GemmP& p, int M, int N, int batch) {
    dim3 g(N / 128, M / 128, batch);
    if (nt) gemm_k<true><<<g, 256, SMEM_BYTES>>>(p);
    else    gemm_k<false><<<g, 256, SMEM_BYTES>>>(p);
}

extern "C" void kernel_launch(void* const* d_in, const int* in_sizes, int n_in,
                              void* d_out, int out_size) {
    const float* x   = (const float*)d_in[0];
    const float* enc = (const float*)d_in[1];
    const float* sa_wq = (const float*)d_in[2];  const float* sa_bq = (const float*)d_in[3];
    const float* sa_wk = (const float*)d_in[4];  const float* sa_bk = (const float*)d_in[5];
    const float* sa_wv = (const float*)d_in[6];  const float* sa_bv = (const float*)d_in[7];
    const float* sa_wo = (const float*)d_in[8];  const float* sa_bo = (const float*)d_in[9];
    const float* sa_wf = (const float*)d_in[10]; const float* sa_bf = (const float*)d_in[11];
    const float* ca_wq = (const float*)d_in[12]; const float* ca_bq = (const float*)d_in[13];
    const float* ca_wk = (const float*)d_in[14]; const float* ca_bk = (const float*)d_in[15];
    const float* ca_wv = (const float*)d_in[16]; const float* ca_bv = (const float*)d_in[17];
    const float* ca_wo = (const float*)d_in[18]; const float* ca_bo = (const float*)d_in[19];
    const float* ca_wf = (const float*)d_in[20]; const float* ca_bf = (const float*)d_in[21];
    const float* ln1_g = (const float*)d_in[22]; const float* ln1_b = (const float*)d_in[23];
    const float* ln2_g = (const float*)d_in[24]; const float* ln2_b = (const float*)d_in[25];
    const float* ln3_g = (const float*)d_in[26]; const float* ln3_b = (const float*)d_in[27];
    const float* fc1_w = (const float*)d_in[28]; const float* fc1_b = (const float*)d_in[29];
    const float* fc2_w = (const float*)d_in[30]; const float* fc2_b = (const float*)d_in[31];

    cudaFuncSetAttribute((const void*)gemm_k<false>,
                         cudaFuncAttributeMaxDynamicSharedMemorySize, SMEM_BYTES);
    cudaFuncSetAttribute((const void*)gemm_k<true>,
                         cudaFuncAttributeMaxDynamicSharedMemorySize, SMEM_BYTES);

    __half *QKV, *Sh, *Oh, *Ph, *Mh, *Wh, *xh, *eh, *X1h, *X2h;
    float *Hf, *X1f, *X2f;
    cudaGetSymbolAddress((void**)&QKV, g_QKV);
    cudaGetSymbolAddress((void**)&Sh, g_Sh);
    cudaGetSymbolAddress((void**)&Oh, g_Oh);
    cudaGetSymbolAddress((void**)&Ph, g_Ph);
    cudaGetSymbolAddress((void**)&Mh, g_Mh);
    cudaGetSymbolAddress((void**)&Wh, g_Wh);
    cudaGetSymbolAddress((void**)&xh, g_xh);  cudaGetSymbolAddress((void**)&eh, g_eh);
    cudaGetSymbolAddress((void**)&X1h, g_X1h); cudaGetSymbolAddress((void**)&X2h, g_X2h);
    cudaGetSymbolAddress((void**)&Hf, g_Hf);
    cudaGetSymbolAddress((void**)&X1f, g_X1f);
    cudaGetSymbolAddress((void**)&X2f, g_X2f);

    __half* Qh = QKV;
    __half* Kh = QKV + 16777216;
    __half* Vh = QKV + 33554432;

    // one merged conversion launch
    {
        CvtP cp{};
        const float* srcs[NCVT] = { x, enc, sa_wq, sa_wk, sa_wv, sa_wo, sa_wf,
                                    ca_wq, ca_wk, ca_wv, ca_wo, ca_wf, fc1_w, fc2_w };
        __half* dsts[NCVT] = { xh, eh, Wh + OW_SAQ, Wh + OW_SAK, Wh + OW_SAV,
                               Wh + OW_SAO, Wh + OW_SAF, Wh + OW_CAQ, Wh + OW_CAK,
                               Wh + OW_CAV, Wh + OW_CAO, Wh + OW_CAF,
                               Wh + OW_FC1, Wh + OW_FC2 };
        for (int i = 0; i < NCVT; i++) {
            cp.src[i] = (const float4*)srcs[i];
            cp.dst[i] = (__half2*)dsts[i];
            cp.n4[i] = (i >= 12) ? 262144 : 524288;
        }
        cvt_all_k<<<dim3(2048, NCVT), 256>>>(cp);
    }

    const float ISC = 0.044194173824159216f;  // 1/sqrt(512)

    auto runMHA = [&](const __half* aq, const __half* akv, long long oqkv,
                      long long oo, long long of,
                      const float* bq, const float* bk, const float* bv,
                      const float* bo, const float* bfb, bool causal) {
        GemmP p{};
        // fused Q/K/V projections: batch 24 = 3 ops x 8 heads
        p.Ah = aq; p.Ah2 = akv; p.Bh = Wh + oqkv;
        p.bias = bq; p.biasB = bk; p.biasC = bv;
        p.Ch = QKV;
        p.K = 512; p.lda = 512; p.ldb = 512; p.ldc = 4096;
        p.sB1 = 2097152; p.sB2 = 262144; p.sC1 = 16777216; p.sC2 = 512;
        p.div = 8; p.biasStride = 512; p.alpha = 1.f; p.flags = 16 | 64;
        launch_gemm(false, p, 4096, 512, 24);
        // scores = Q K^T / sqrt(512)
        p = GemmP{};
        p.Ah = Qh; p.Bh = Kh; p.Ch = Sh;
        p.K = 512; p.lda = 4096; p.ldb = 4096; p.ldc = 1024;
        p.sA1 = 4194304; p.sA2 = 512; p.sB1 = 4194304; p.sB2 = 512;
        p.sC1 = 8388608; p.sC2 = 1048576;
        p.div = 8; p.alpha = ISC; p.flags = causal ? (16 | 2) : 16;
        launch_gemm(true, p, 1024, 1024, 32);
        softmax_k<<<32768, 256>>>((__half2*)Sh);
        // O = A V  (causal: probs cols > m0+127 exactly 0 -> K-limit)
        p = GemmP{};
        p.Ah = Sh; p.Bh = Vh; p.Ch = Oh;
        p.K = 1024; p.lda = 1024; p.ldb = 4096; p.ldc = 4096;
        p.sA1 = 8388608; p.sA2 = 1048576; p.sB1 = 4194304; p.sB2 = 512;
        p.sC1 = 4194304; p.sC2 = 512;
        p.div = 8; p.alpha = 1.f; p.flags = causal ? (16 | 32) : 16;
        launch_gemm(false, p, 1024, 512, 32);
        // per-head out projection
        p = GemmP{};
        p.Ah = Oh; p.Bh = Wh + oo; p.bias = bo; p.Ch = Ph;
        p.K = 512; p.lda = 4096; p.ldb = 512; p.ldc = 4096;
        p.sA2 = 512; p.sB2 = 262144; p.sC2 = 512;
        p.div = 8; p.biasStride = 512; p.alpha = 1.f; p.flags = 16;
        launch_gemm(false, p, 4096, 512, 8);
        // final concat projection -> fp32 H
        p = GemmP{};
        p.Ah = Ph; p.Bh = Wh + of; p.bias = bfb; p.Cf = Hf;
        p.K = 4096; p.lda = 4096; p.ldb = 512; p.ldc = 512;
        p.div = 1; p.alpha = 1.f; p.flags = 4;
        launch_gemm(false, p, 4096, 512, 1);
    };

    // self-attention (causal) + LN1
    runMHA(xh, xh, OW_SAQ, OW_SAO, OW_SAF, sa_bq, sa_bk, sa_bv, sa_bo, sa_bf, true);
    add_ln_k<<<4096, 256>>>((const float2*)Hf, (const float2*)x, ln1_g, ln1_b,
                            (float2*)X1f, (__half2*)X1h);

    // cross-attention + LN2
    runMHA(X1h, eh, OW_CAQ, OW_CAO, OW_CAF, ca_bq, ca_bk, ca_bv, ca_bo, ca_bf, false);
    add_ln_k<<<4096, 256>>>((const float2*)Hf, (const float2*)X1f, ln2_g, ln2_b,
                            (float2*)X2f, (__half2*)X2h);

    // FFN
    {
        GemmP p{};
        p.Ah = X2h; p.Bh = Wh + OW_FC1; p.bias = fc1_b; p.Ch = Mh;
        p.K = 512; p.lda = 512; p.ldb = 2048; p.ldc = 2048;
        p.div = 1; p.biasStride = 0; p.alpha = 1.f; p.flags = 16 | 1;
        launch_gemm(false, p, 4096, 2048, 1);

        p = GemmP{};
        p.Ah = Mh; p.Bh = Wh + OW_FC2; p.bias = fc2_b; p.Cf = Hf;
        p.K = 2048; p.lda = 2048; p.ldb = 512; p.ldc = 512;
        p.div = 1; p.biasStride = 0; p.alpha = 1.f; p.flags = 4;
        launch_gemm(false, p, 4096, 512, 1);
    }
    add_ln_k<<<4096, 256>>>((const float2*)Hf, (const float2*)X2f, ln3_g, ln3_b,
                            (float2*)d_out, nullptr);
}

// round 11
// speedup vs baseline: 7.3924x; 1.0382x over previous
#include <cuda_runtime.h>
#include <cuda_fp16.h>
#include <math.h>

#define ASTR 72                  // A smem row stride (halfs): 64 k + 8 pad
#define BSTR 136                 // NT=false B smem row stride (halfs): 128 n + 8 pad
#define A_ST  (128 * ASTR)
#define STG   (2 * A_ST)
#define SMEM_BYTES (3 * STG * 2) // 110592

// ---------------- static scratch ----------------
__device__ __half g_QKV[50331648];       // Q | K | V
__device__ __half g_Sh[33554432];
__device__ __half g_Oh[16777216];
__device__ __half g_Ph[16777216];
__device__ __half g_Mh[8388608];
__device__ __half g_Wh[23068672];
__device__ __half g_xh[2097152], g_eh[2097152], g_X1h[2097152], g_X2h[2097152];
__device__ float g_Hf[4194304];          // two split-K partials
__device__ float g_X1f[2097152], g_X2f[2097152];

#define OW_SAQ 0LL
#define OW_SAK 2097152LL
#define OW_SAV 4194304LL
#define OW_SAO 6291456LL
#define OW_SAF 8388608LL
#define OW_CAQ 10485760LL
#define OW_CAK 12582912LL
#define OW_CAV 14680064LL
#define OW_CAO 16777216LL
#define OW_CAF 18874368LL
#define OW_FC1 20971520LL
#define OW_FC2 22020096LL

// ---------------- PTX helpers ----------------
__device__ __forceinline__ void mma16816(float* d, const unsigned* a, const unsigned* b) {
    asm volatile(
        "mma.sync.aligned.m16n8k16.row.col.f32.f16.f16.f32 "
        "{%0,%1,%2,%3}, {%4,%5,%6,%7}, {%8,%9}, {%0,%1,%2,%3};"
        : "+f"(d[0]), "+f"(d[1]), "+f"(d[2]), "+f"(d[3])
        : "r"(a[0]), "r"(a[1]), "r"(a[2]), "r"(a[3]), "r"(b[0]), "r"(b[1]));
}
__device__ __forceinline__ void ldsm4(unsigned* r, unsigned a) {
    asm volatile("ldmatrix.sync.aligned.m8n8.x4.shared.b16 {%0,%1,%2,%3}, [%4];"
                 : "=r"(r[0]), "=r"(r[1]), "=r"(r[2]), "=r"(r[3]) : "r"(a));
}
__device__ __forceinline__ void ldsm4t(unsigned* r, unsigned a) {
    asm volatile("ldmatrix.sync.aligned.m8n8.x4.trans.shared.b16 {%0,%1,%2,%3}, [%4];"
                 : "=r"(r[0]), "=r"(r[1]), "=r"(r[2]), "=r"(r[3]) : "r"(a));
}
__device__ __forceinline__ void cp16(unsigned d, const void* s) {
    asm volatile("cp.async.cg.shared.global [%0], [%1], 16;" :: "r"(d), "l"(s));
}

// ---------------- GEMM: C = alpha * A*B + bias ----------------
// flags: 1 relu, 2 causal mask, 4 fp32 out, 16 fp16 out, 32 causal K-limit,
//        64 multi-op: pq>0 -> A=Ah2 base; bias from {bias,biasB,biasC}[pq]
struct GemmP {
    const __half *Ah, *Ah2, *Bh;
    const float *bias, *biasB, *biasC;
    __half *Ch;
    float* Cf;
    int K, lda, ldb, ldc;
    long long sA1, sA2, sB1, sB2, sC1, sC2;
    int div, biasStride;
    float alpha; int flags;
};

template<bool NT>
__global__ __launch_bounds__(256, 2) void gemm_k(GemmP p) {
    extern __shared__ unsigned char raw[];
    __half* Sm = (__half*)raw;

    const int pb = blockIdx.z, pq = pb / p.div, pr = pb - pq * p.div;
    const int tid = threadIdx.x, lane = tid & 31, warp = tid >> 5;
    const int wm = warp >> 1, wn = warp & 1;
    const int m0 = blockIdx.y * 128, n0 = blockIdx.x * 128;

    if ((p.flags & 2) && n0 > m0 + 127) {
        __half2* Ch2 = (__half2*)(p.Ch + pq * p.sC1 + pr * p.sC2);
        const __half2 mi = __half2half2(__float2half(-1e30f));
        for (int i = tid; i < 128 * 64; i += 256) {
            int r = i >> 6, c = i & 63;
            Ch2[((long long)(m0 + r) * p.ldc + n0) / 2 + c] = mi;
        }
        return;
    }

    const int Klim = (p.flags & 32) ? (m0 + 128 < p.K ? m0 + 128 : p.K) : p.K;
    const int nch = Klim >> 6;

    const __half* Abase = ((p.flags & 64) && pq > 0) ? p.Ah2 : p.Ah;
    Abase += pq * p.sA1 + pr * p.sA2;
    const __half* Bbase = p.Bh + pq * p.sB1 + pr * p.sB2;
    const float* bias = p.bias;
    if (p.flags & 64) bias = (pq == 0) ? p.bias : ((pq == 1) ? p.biasB : p.biasC);

    const unsigned sBase = (unsigned)__cvta_generic_to_shared(Sm);

    float acc[2][8][4];
#pragma unroll
    for (int i = 0; i < 2; i++)
#pragma unroll
        for (int j = 0; j < 8; j++)
#pragma unroll
            for (int q = 0; q < 4; q++) acc[i][j][q] = 0.f;

    auto issue_stage = [&](int st, int kt) {
        const unsigned sA = sBase + 2u * (st * STG);
        const unsigned sB = sA + 2u * A_ST;
#pragma unroll
        for (int it = 0; it < 4; it++) {
            int i = tid + it * 256;
            int row = i >> 3, seg = i & 7;
            cp16(sA + 2u * (row * ASTR + seg * 8),
                 Abase + (long long)(m0 + row) * p.lda + kt + seg * 8);
        }
        if (NT) {
#pragma unroll
            for (int it = 0; it < 4; it++) {
                int i = tid + it * 256;
                int row = i >> 3, seg = i & 7;
                cp16(sB + 2u * (row * ASTR + seg * 8),
                     Bbase + (long long)(n0 + row) * p.ldb + kt + seg * 8);
            }
        } else {
#pragma unroll
            for (int it = 0; it < 4; it++) {
                int i = tid + it * 256;
                int row = i >> 4, seg = i & 15;
                cp16(sB + 2u * (row * BSTR + seg * 8),
                     Bbase + (long long)(kt + row) * p.ldb + n0 + seg * 8);
            }
        }
        asm volatile("cp.async.commit_group;");
    };

    issue_stage(0, 0);
    issue_stage(1, 64);
    asm volatile("cp.async.wait_group 1;" ::: "memory");
    __syncthreads();

    int st = 0;
    for (int c = 0; c < nch; c++) {
        if (c + 2 < nch) issue_stage((c + 2) % 3, (c + 2) * 64);
        const unsigned sA = sBase + 2u * (st * STG);
        const unsigned sB = sA + 2u * A_ST;
#pragma unroll
        for (int ks = 0; ks < 64; ks += 16) {
            unsigned ah[2][4], bh[8][2];
#pragma unroll
            for (int i = 0; i < 2; i++) {
                int row = wm * 32 + i * 16 + (lane & 15);
                int ko = ks + (lane >> 4) * 8;
                ldsm4(ah[i], sA + 2u * (row * ASTR + ko));
            }
#pragma unroll
            for (int jj = 0; jj < 4; jj++) {
                unsigned t0[4];
                if (NT) {
                    int row = wn * 64 + jj * 16 + (lane & 7) + ((lane >> 4) & 1) * 8;
                    int ko = ks + ((lane >> 3) & 1) * 8;
                    ldsm4(t0, sB + 2u * (row * ASTR + ko));
                } else {
                    int krow = ks + (lane & 7) + ((lane >> 3) & 1) * 8;
                    int ncol = wn * 64 + jj * 16 + ((lane >> 4) & 1) * 8;
                    ldsm4t(t0, sB + 2u * (krow * BSTR + ncol));
                }
                bh[2 * jj][0] = t0[0]; bh[2 * jj][1] = t0[1];
                bh[2 * jj + 1][0] = t0[2]; bh[2 * jj + 1][1] = t0[3];
            }
#pragma unroll
            for (int i = 0; i < 2; i++)
#pragma unroll
                for (int j = 0; j < 8; j++)
                    mma16816(acc[i][j], ah[i], bh[j]);
        }
        if (c + 1 < nch) {
            if (c + 2 < nch) { asm volatile("cp.async.wait_group 1;" ::: "memory"); }
            else             { asm volatile("cp.async.wait_group 0;" ::: "memory"); }
            __syncthreads();
        }
        st = (st == 2) ? 0 : st + 1;
    }

    // epilogue
    __half* Ch = (p.flags & 16) ? p.Ch + pq * p.sC1 + pr * p.sC2 : nullptr;
    float*  Cf = (p.flags & 4)  ? p.Cf + pq * p.sC1 + pr * p.sC2 : nullptr;
    const int rbase = m0 + wm * 32 + (lane >> 2);
    const int cbase = n0 + wn * 64 + (lane & 3) * 2;
#pragma unroll
    for (int i = 0; i < 2; i++)
#pragma unroll
        for (int j = 0; j < 8; j++) {
            int c = cbase + j * 8;
            float b0 = 0.f, b1 = 0.f;
            if (bias) {
                b0 = bias[pr * p.biasStride + c];
                b1 = bias[pr * p.biasStride + c + 1];
            }
#pragma unroll
            for (int h = 0; h < 2; h++) {
                int r = rbase + i * 16 + h * 8;
                float v0 = acc[i][j][2 * h + 0] * p.alpha + b0;
                float v1 = acc[i][j][2 * h + 1] * p.alpha + b1;
                if (p.flags & 2) {
                    if (c > r)     v0 = -1e30f;
                    if (c + 1 > r) v1 = -1e30f;
                }
                if (p.flags & 1) { v0 = fmaxf(v0, 0.f); v1 = fmaxf(v1, 0.f); }
                long long off = (long long)r * p.ldc + c;
                if (p.flags & 4) *(float2*)(Cf + off) = make_float2(v0, v1);
                else {
                    __half2 hi; hi.x = __float2half(v0); hi.y = __float2half(v1);
                    *(__half2*)(Ch + off) = hi;
                }
            }
        }
}

// ---------------- merged fp32 -> fp16 conversion ----------------
#define NCVT 14
struct CvtP {
    const float4* src[NCVT];
    __half2* dst[NCVT];
    int n4[NCVT];
};
__global__ __launch_bounds__(256) void cvt_all_k(CvtP p) {
    const int ten = blockIdx.y;
    int i = blockIdx.x * blockDim.x + threadIdx.x;
    if (i >= p.n4[ten]) return;
    float4 v = p.src[ten][i];
    __half2 h0; h0.x = __float2half(v.x); h0.y = __float2half(v.y);
    __half2 h1; h1.x = __float2half(v.z); h1.y = __float2half(v.w);
    p.dst[ten][2 * i] = h0;
    p.dst[ten][2 * i + 1] = h1;
}

// ---------------- softmax over 1024 cols (no max pass; causal load-skip) ----------------
__global__ __launch_bounds__(256)
void softmax_k(__half2* S, int causal) {
    __shared__ float red[8];
    const long long row = blockIdx.x;
    const int rloc = (int)(row & 1023);
    const int lim = causal ? rloc : 1023;
    __half2* sp = S + row * 512;
    const int t = threadIdx.x, lane = t & 31, w = t >> 5;

    float e0 = 0.f, e1 = 0.f, e2 = 0.f, e3 = 0.f;
    const bool a0 = (2 * t) <= lim;
    const bool a1 = (512 + 2 * t) <= lim;
    if (a0) {
        __half2 h0 = sp[t];
        e0 = __expf(__half2float(h0.x));   // masked cols hold -1e30 -> exp = 0
        e1 = __expf(__half2float(h0.y));
    }
    if (a1) {
        __half2 h1 = sp[t + 256];
        e2 = __expf(__half2float(h1.x));
        e3 = __expf(__half2float(h1.y));
    }

    float s = e0 + e1 + e2 + e3;
#pragma unroll
    for (int o = 16; o; o >>= 1) s += __shfl_xor_sync(~0u, s, o);
    if (lane == 0) red[w] = s;
    __syncthreads();
    float s2 = red[lane & 7];
#pragma unroll
    for (int o = 4; o; o >>= 1) s2 += __shfl_xor_sync(~0u, s2, o);
    float inv = 1.f / s2;

    __half2 o0, o1;
    o0.x = __float2half(e0 * inv); o0.y = __float2half(e1 * inv);
    o1.x = __float2half(e2 * inv); o1.y = __float2half(e3 * inv);
    sp[t] = o0;          // inactive threads store exact 0s
    sp[t + 256] = o1;
}

// ---------------- residual add (two partials) + LayerNorm (D=512) ----------------
__device__ __forceinline__ float bsum(float val, float* red) {
    const int lane = threadIdx.x & 31, w = threadIdx.x >> 5;
#pragma unroll
    for (int o = 16; o; o >>= 1) val += __shfl_xor_sync(~0u, val, o);
    if (lane == 0) red[w] = val;
    __syncthreads();
    float s = red[lane & 7];
#pragma unroll
    for (int o = 4; o; o >>= 1) s += __shfl_xor_sync(~0u, s, o);
    __syncthreads();
    return s;
}

__global__ __launch_bounds__(256)
void add_ln_k(const float2* __restrict__ a, const float2* __restrict__ a2,
              const float2* __restrict__ r,
              const float* __restrict__ g, const float* __restrict__ b,
              float2* __restrict__ o, __half2* oh) {
    __shared__ float red[8];
    const long long row = blockIdx.x;
    const int t = threadIdx.x;
    float2 va = a[row * 256 + t], vb = a2[row * 256 + t], vr = r[row * 256 + t];
    float x0 = va.x + vb.x + vr.x, x1 = va.y + vb.y + vr.y;
    float mean = bsum(x0 + x1, red) * (1.f / 512.f);
    float d0 = x0 - mean, d1 = x1 - mean;
    float var = bsum(d0 * d0 + d1 * d1, red) * (1.f / 512.f);
    float inv = rsqrtf(var + 1e-5f);
    float y0 = d0 * inv * g[2 * t] + b[2 * t];
    float y1 = d1 * inv * g[2 * t + 1] + b[2 * t + 1];
    o[row * 256 + t] = make_float2(y0, y1);
    if (oh) {
        __half2 hh; hh.x = __float2half(y0); hh.y = __float2half(y1);
        oh[row * 256 + t] = hh;
    }
}

// ---------------- host ----------------
static void launch_gemm(bool nt, const GemmP& p, int M, int N, int batch) {
    dim3 g(N / 128, M / 128, batch);
    if (nt) gemm_k<true><<<g, 256, SMEM_BYTES>>>(p);
    else    gemm_k<false><<<g, 256, SMEM_BYTES>>>(p);
}

extern "C" void kernel_launch(void* const* d_in, const int* in_sizes, int n_in,
                              void* d_out, int out_size) {
    const float* x   = (const float*)d_in[0];
    const float* enc = (const float*)d_in[1];
    const float* sa_wq = (const float*)d_in[2];  const float* sa_bq = (const float*)d_in[3];
    const float* sa_wk = (const float*)d_in[4];  const float* sa_bk = (const float*)d_in[5];
    const float* sa_wv = (const float*)d_in[6];  const float* sa_bv = (const float*)d_in[7];
    const float* sa_wo = (const float*)d_in[8];  const float* sa_bo = (const float*)d_in[9];
    const float* sa_wf = (const float*)d_in[10]; const float* sa_bf = (const float*)d_in[11];
    const float* ca_wq = (const float*)d_in[12]; const float* ca_bq = (const float*)d_in[13];
    const float* ca_wk = (const float*)d_in[14]; const float* ca_bk = (const float*)d_in[15];
    const float* ca_wv = (const float*)d_in[16]; const float* ca_bv = (const float*)d_in[17];
    const float* ca_wo = (const float*)d_in[18]; const float* ca_bo = (const float*)d_in[19];
    const float* ca_wf = (const float*)d_in[20]; const float* ca_bf = (const float*)d_in[21];
    const float* ln1_g = (const float*)d_in[22]; const float* ln1_b = (const float*)d_in[23];
    const float* ln2_g = (const float*)d_in[24]; const float* ln2_b = (const float*)d_in[25];
    const float* ln3_g = (const float*)d_in[26]; const float* ln3_b = (const float*)d_in[27];
    const float* fc1_w = (const float*)d_in[28]; const float* fc1_b = (const float*)d_in[29];
    const float* fc2_w = (const float*)d_in[30]; const float* fc2_b = (const float*)d_in[31];

    cudaFuncSetAttribute((const void*)gemm_k<false>,
                         cudaFuncAttributeMaxDynamicSharedMemorySize, SMEM_BYTES);
    cudaFuncSetAttribute((const void*)gemm_k<true>,
                         cudaFuncAttributeMaxDynamicSharedMemorySize, SMEM_BYTES);

    __half *QKV, *Sh, *Oh, *Ph, *Mh, *Wh, *xh, *eh, *X1h, *X2h;
    float *Hf, *X1f, *X2f;
    cudaGetSymbolAddress((void**)&QKV, g_QKV);
    cudaGetSymbolAddress((void**)&Sh, g_Sh);
    cudaGetSymbolAddress((void**)&Oh, g_Oh);
    cudaGetSymbolAddress((void**)&Ph, g_Ph);
    cudaGetSymbolAddress((void**)&Mh, g_Mh);
    cudaGetSymbolAddress((void**)&Wh, g_Wh);
    cudaGetSymbolAddress((void**)&xh, g_xh);  cudaGetSymbolAddress((void**)&eh, g_eh);
    cudaGetSymbolAddress((void**)&X1h, g_X1h); cudaGetSymbolAddress((void**)&X2h, g_X2h);
    cudaGetSymbolAddress((void**)&Hf, g_Hf);
    cudaGetSymbolAddress((void**)&X1f, g_X1f);
    cudaGetSymbolAddress((void**)&X2f, g_X2f);

    __half* Qh = QKV;
    __half* Kh = QKV + 16777216;
    __half* Vh = QKV + 33554432;
    float* Hf2 = Hf + 2097152;

    // one merged conversion launch
    {
        CvtP cp{};
        const float* srcs[NCVT] = { x, enc, sa_wq, sa_wk, sa_wv, sa_wo, sa_wf,
                                    ca_wq, ca_wk, ca_wv, ca_wo, ca_wf, fc1_w, fc2_w };
        __half* dsts[NCVT] = { xh, eh, Wh + OW_SAQ, Wh + OW_SAK, Wh + OW_SAV,
                               Wh + OW_SAO, Wh + OW_SAF, Wh + OW_CAQ, Wh + OW_CAK,
                               Wh + OW_CAV, Wh + OW_CAO, Wh + OW_CAF,
                               Wh + OW_FC1, Wh + OW_FC2 };
        for (int i = 0; i < NCVT; i++) {
            cp.src[i] = (const float4*)srcs[i];
            cp.dst[i] = (__half2*)dsts[i];
            cp.n4[i] = (i >= 12) ? 262144 : 524288;
        }
        cvt_all_k<<<dim3(2048, NCVT), 256>>>(cp);
    }

    const float ISC = 0.044194173824159216f;  // 1/sqrt(512)

    auto runMHA = [&](const __half* aq, const __half* akv, long long oqkv,
                      long long oo, long long of,
                      const float* bq, const float* bk, const float* bv,
                      const float* bo, const float* bfb, bool causal) {
        GemmP p{};
        // fused Q/K/V projections: batch 24 = 3 ops x 8 heads
        p.Ah = aq; p.Ah2 = akv; p.Bh = Wh + oqkv;
        p.bias = bq; p.biasB = bk; p.biasC = bv;
        p.Ch = QKV;
        p.K = 512; p.lda = 512; p.ldb = 512; p.ldc = 4096;
        p.sB1 = 2097152; p.sB2 = 262144; p.sC1 = 16777216; p.sC2 = 512;
        p.div = 8; p.biasStride = 512; p.alpha = 1.f; p.flags = 16 | 64;
        launch_gemm(false, p, 4096, 512, 24);
        // scores = Q K^T / sqrt(512)
        p = GemmP{};
        p.Ah = Qh; p.Bh = Kh; p.Ch = Sh;
        p.K = 512; p.lda = 4096; p.ldb = 4096; p.ldc = 1024;
        p.sA1 = 4194304; p.sA2 = 512; p.sB1 = 4194304; p.sB2 = 512;
        p.sC1 = 8388608; p.sC2 = 1048576;
        p.div = 8; p.alpha = ISC; p.flags = causal ? (16 | 2) : 16;
        launch_gemm(true, p, 1024, 1024, 32);
        softmax_k<<<32768, 256>>>((__half2*)Sh, causal ? 1 : 0);
        // O = A V  (causal K-limit)
        p = GemmP{};
        p.Ah = Sh; p.Bh = Vh; p.Ch = Oh;
        p.K = 1024; p.lda = 1024; p.ldb = 4096; p.ldc = 4096;
        p.sA1 = 8388608; p.sA2 = 1048576; p.sB1 = 4194304; p.sB2 = 512;
        p.sC1 = 4194304; p.sC2 = 512;
        p.div = 8; p.alpha = 1.f; p.flags = causal ? (16 | 32) : 16;
        launch_gemm(false, p, 1024, 512, 32);
        // per-head out projection
        p = GemmP{};
        p.Ah = Oh; p.Bh = Wh + oo; p.bias = bo; p.Ch = Ph;
        p.K = 512; p.lda = 4096; p.ldb = 512; p.ldc = 4096;
        p.sA2 = 512; p.sB2 = 262144; p.sC2 = 512;
        p.div = 8; p.biasStride = 512; p.alpha = 1.f; p.flags = 16;
        launch_gemm(false, p, 4096, 512, 8);
        // final concat projection: split-K=2 -> Hf (bias) + Hf2 (no bias)
        p = GemmP{};
        p.Ah = Ph; p.Ah2 = Ph; p.Bh = Wh + of;
        p.bias = bfb; p.biasB = nullptr; p.biasC = nullptr;
        p.Cf = Hf;
        p.K = 2048; p.lda = 4096; p.ldb = 512; p.ldc = 512;
        p.sA1 = 2048; p.sB1 = 2048LL * 512; p.sC1 = 2097152;
        p.div = 1; p.alpha = 1.f; p.flags = 4 | 64;
        launch_gemm(false, p, 4096, 512, 2);
    };

    // self-attention (causal) + LN1
    runMHA(xh, xh, OW_SAQ, OW_SAO, OW_SAF, sa_bq, sa_bk, sa_bv, sa_bo, sa_bf, true);
    add_ln_k<<<4096, 256>>>((const float2*)Hf, (const float2*)Hf2, (const float2*)x,
                            ln1_g, ln1_b, (float2*)X1f, (__half2*)X1h);

    // cross-attention + LN2
    runMHA(X1h, eh, OW_CAQ, OW_CAO, OW_CAF, ca_bq, ca_bk, ca_bv, ca_bo, ca_bf, false);
    add_ln_k<<<4096, 256>>>((const float2*)Hf, (const float2*)Hf2, (const float2*)X1f,
                            ln2_g, ln2_b, (float2*)X2f, (__half2*)X2h);

    // FFN
    {
        GemmP p{};
        p.Ah = X2h; p.Bh = Wh + OW_FC1; p.bias = fc1_b; p.Ch = Mh;
        p.K = 512; p.lda = 512; p.ldb = 2048; p.ldc = 2048;
        p.div = 1; p.biasStride = 0; p.alpha = 1.f; p.flags = 16 | 1;
        launch_gemm(false, p, 4096, 2048, 1);

        // FC2: split-K=2 -> Hf (bias) + Hf2 (no bias)
        p = GemmP{};
        p.Ah = Mh; p.Ah2 = Mh; p.Bh = Wh + OW_FC2;
        p.bias = fc2_b; p.biasB = nullptr; p.biasC = nullptr;
        p.Cf = Hf;
        p.K = 1024; p.lda = 2048; p.ldb = 512; p.ldc = 512;
        p.sA1 = 1024; p.sB1 = 1024LL * 512; p.sC1 = 2097152;
        p.div = 1; p.alpha = 1.f; p.flags = 4 | 64;
        launch_gemm(false, p, 4096, 512, 2);
    }
    add_ln_k<<<4096, 256>>>((const float2*)Hf, (const float2*)Hf2, (const float2*)X2f,
                            ln3_g, ln3_b, (float2*)d_out, nullptr);
}

// round 12
// speedup vs baseline: 7.6221x; 1.0311x over previous
#include <cuda_runtime.h>
#include <cuda_fp16.h>
#include <math.h>

#define ASTR 72
#define BSTR 136
#define A_ST  (128 * ASTR)
#define STG   (2 * A_ST)
#define SMEM_BYTES (3 * STG * 2) // 110592

// ---------------- static scratch ----------------
__device__ __half g_QKV[50331648];       // Q | K | V
__device__ __half g_Sh[33554432];
__device__ __half g_Oh[16777216];
__device__ __half g_Ph[16777216];
__device__ __half g_Mh[8388608];
__device__ __half g_Wh[23068672];
__device__ __half g_xh[2097152], g_eh[2097152], g_X1h[2097152], g_X2h[2097152];
__device__ float g_Hf[4194304];
__device__ float g_X1f[2097152], g_X2f[2097152];
__device__ float g_RS[32768];            // attention row sums (32 bh x 1024)

#define OW_SAQ 0LL
#define OW_SAK 2097152LL
#define OW_SAV 4194304LL
#define OW_SAO 6291456LL
#define OW_SAF 8388608LL
#define OW_CAQ 10485760LL
#define OW_CAK 12582912LL
#define OW_CAV 14680064LL
#define OW_CAO 16777216LL
#define OW_CAF 18874368LL
#define OW_FC1 20971520LL
#define OW_FC2 22020096LL

// ---------------- PTX helpers ----------------
__device__ __forceinline__ void mma16816(float* d, const unsigned* a, const unsigned* b) {
    asm volatile(
        "mma.sync.aligned.m16n8k16.row.col.f32.f16.f16.f32 "
        "{%0,%1,%2,%3}, {%4,%5,%6,%7}, {%8,%9}, {%0,%1,%2,%3};"
        : "+f"(d[0]), "+f"(d[1]), "+f"(d[2]), "+f"(d[3])
        : "r"(a[0]), "r"(a[1]), "r"(a[2]), "r"(a[3]), "r"(b[0]), "r"(b[1]));
}
__device__ __forceinline__ void ldsm4(unsigned* r, unsigned a) {
    asm volatile("ldmatrix.sync.aligned.m8n8.x4.shared.b16 {%0,%1,%2,%3}, [%4];"
                 : "=r"(r[0]), "=r"(r[1]), "=r"(r[2]), "=r"(r[3]) : "r"(a));
}
__device__ __forceinline__ void ldsm4t(unsigned* r, unsigned a) {
    asm volatile("ldmatrix.sync.aligned.m8n8.x4.trans.shared.b16 {%0,%1,%2,%3}, [%4];"
                 : "=r"(r[0]), "=r"(r[1]), "=r"(r[2]), "=r"(r[3]) : "r"(a));
}
__device__ __forceinline__ void cp16(unsigned d, const void* s) {
    asm volatile("cp.async.cg.shared.global [%0], [%1], 16;" :: "r"(d), "l"(s));
}

// ---------------- GEMM: C = alpha * A*B + bias ----------------
// flags: 1 relu, 2 causal (skip fully-masked tiles; mask diag), 4 fp32 out, 16 fp16 out,
//        32 causal K-limit, 64 multi-op (A/bias select by pq),
//        128 exp epilogue + rowsum atomics (scores), 256 divide-by-rowsum (AV)
struct GemmP {
    const __half *Ah, *Ah2, *Bh;
    const float *bias, *biasB, *biasC;
    __half *Ch;
    float* Cf;
    float* rsum;
    int K, lda, ldb, ldc;
    long long sA1, sA2, sB1, sB2, sC1, sC2;
    int div, biasStride;
    float alpha; int flags;
};

template<bool NT>
__global__ __launch_bounds__(256, 2) void gemm_k(GemmP p) {
    extern __shared__ unsigned char raw[];
    __half* Sm = (__half*)raw;

    const int pb = blockIdx.z, pq = pb / p.div, pr = pb - pq * p.div;
    const int tid = threadIdx.x, lane = tid & 31, warp = tid >> 5;
    const int wm = warp >> 1, wn = warp & 1;
    const int m0 = blockIdx.y * 128, n0 = blockIdx.x * 128;

    // fully-masked causal tile: nothing downstream ever reads it -> skip entirely
    if ((p.flags & 2) && n0 > m0 + 127) return;

    const int Klim = (p.flags & 32) ? (m0 + 128 < p.K ? m0 + 128 : p.K) : p.K;
    const int nch = Klim >> 6;

    const __half* Abase = ((p.flags & 64) && pq > 0) ? p.Ah2 : p.Ah;
    Abase += pq * p.sA1 + pr * p.sA2;
    const __half* Bbase = p.Bh + pq * p.sB1 + pr * p.sB2;
    const float* bias = p.bias;
    if (p.flags & 64) bias = (pq == 0) ? p.bias : ((pq == 1) ? p.biasB : p.biasC);

    const unsigned sBase = (unsigned)__cvta_generic_to_shared(Sm);

    float acc[2][8][4];
#pragma unroll
    for (int i = 0; i < 2; i++)
#pragma unroll
        for (int j = 0; j < 8; j++)
#pragma unroll
            for (int q = 0; q < 4; q++) acc[i][j][q] = 0.f;

    auto issue_stage = [&](int st, int kt) {
        const unsigned sA = sBase + 2u * (st * STG);
        const unsigned sB = sA + 2u * A_ST;
#pragma unroll
        for (int it = 0; it < 4; it++) {
            int i = tid + it * 256;
            int row = i >> 3, seg = i & 7;
            cp16(sA + 2u * (row * ASTR + seg * 8),
                 Abase + (long long)(m0 + row) * p.lda + kt + seg * 8);
        }
        if (NT) {
#pragma unroll
            for (int it = 0; it < 4; it++) {
                int i = tid + it * 256;
                int row = i >> 3, seg = i & 7;
                cp16(sB + 2u * (row * ASTR + seg * 8),
                     Bbase + (long long)(n0 + row) * p.ldb + kt + seg * 8);
            }
        } else {
#pragma unroll
            for (int it = 0; it < 4; it++) {
                int i = tid + it * 256;
                int row = i >> 4, seg = i & 15;
                cp16(sB + 2u * (row * BSTR + seg * 8),
                     Bbase + (long long)(kt + row) * p.ldb + n0 + seg * 8);
            }
        }
        asm volatile("cp.async.commit_group;");
    };

    issue_stage(0, 0);
    issue_stage(1, 64);
    asm volatile("cp.async.wait_group 1;" ::: "memory");
    __syncthreads();

    int st = 0;
    for (int c = 0; c < nch; c++) {
        if (c + 2 < nch) issue_stage((c + 2) % 3, (c + 2) * 64);
        const unsigned sA = sBase + 2u * (st * STG);
        const unsigned sB = sA + 2u * A_ST;
#pragma unroll
        for (int ks = 0; ks < 64; ks += 16) {
            unsigned ah[2][4], bh[8][2];
#pragma unroll
            for (int i = 0; i < 2; i++) {
                int row = wm * 32 + i * 16 + (lane & 15);
                int ko = ks + (lane >> 4) * 8;
                ldsm4(ah[i], sA + 2u * (row * ASTR + ko));
            }
#pragma unroll
            for (int jj = 0; jj < 4; jj++) {
                unsigned t0[4];
                if (NT) {
                    int row = wn * 64 + jj * 16 + (lane & 7) + ((lane >> 4) & 1) * 8;
                    int ko = ks + ((lane >> 3) & 1) * 8;
                    ldsm4(t0, sB + 2u * (row * ASTR + ko));
                } else {
                    int krow = ks + (lane & 7) + ((lane >> 3) & 1) * 8;
                    int ncol = wn * 64 + jj * 16 + ((lane >> 4) & 1) * 8;
                    ldsm4t(t0, sB + 2u * (krow * BSTR + ncol));
                }
                bh[2 * jj][0] = t0[0]; bh[2 * jj][1] = t0[1];
                bh[2 * jj + 1][0] = t0[2]; bh[2 * jj + 1][1] = t0[3];
            }
#pragma unroll
            for (int i = 0; i < 2; i++)
#pragma unroll
                for (int j = 0; j < 8; j++)
                    mma16816(acc[i][j], ah[i], bh[j]);
        }
        if (c + 1 < nch) {
            if (c + 2 < nch) { asm volatile("cp.async.wait_group 1;" ::: "memory"); }
            else             { asm volatile("cp.async.wait_group 0;" ::: "memory"); }
            __syncthreads();
        }
        st = (st == 2) ? 0 : st + 1;
    }

    // ---------- epilogue ----------
    __half* Ch = (p.flags & 16) ? p.Ch + pq * p.sC1 + pr * p.sC2 : nullptr;
    float*  Cf = (p.flags & 4)  ? p.Cf + pq * p.sC1 + pr * p.sC2 : nullptr;
    const int rbase = m0 + wm * 32 + (lane >> 2);
    const int cbase = n0 + wn * 64 + (lane & 3) * 2;

    float rs_inv[2][2], rs_acc[2][2];
#pragma unroll
    for (int i = 0; i < 2; i++)
#pragma unroll
        for (int h = 0; h < 2; h++) {
            rs_acc[i][h] = 0.f;
            if (p.flags & 256)
                rs_inv[i][h] = 1.f / p.rsum[(long long)pb * 1024 + rbase + i * 16 + h * 8];
        }

#pragma unroll
    for (int i = 0; i < 2; i++)
#pragma unroll
        for (int j = 0; j < 8; j++) {
            int c = cbase + j * 8;
            float b0 = 0.f, b1 = 0.f;
            if (bias) {
                b0 = bias[pr * p.biasStride + c];
                b1 = bias[pr * p.biasStride + c + 1];
            }
#pragma unroll
            for (int h = 0; h < 2; h++) {
                int r = rbase + i * 16 + h * 8;
                float v0 = acc[i][j][2 * h + 0] * p.alpha + b0;
                float v1 = acc[i][j][2 * h + 1] * p.alpha + b1;
                if (p.flags & 2) {
                    if (c > r)     v0 = -1e30f;
                    if (c + 1 > r) v1 = -1e30f;
                }
                if (p.flags & 1) { v0 = fmaxf(v0, 0.f); v1 = fmaxf(v1, 0.f); }
                if (p.flags & 128) {
                    v0 = __expf(v0); v1 = __expf(v1);       // masked -> 0
                    rs_acc[i][h] += v0 + v1;
                }
                if (p.flags & 256) { v0 *= rs_inv[i][h]; v1 *= rs_inv[i][h]; }
                long long off = (long long)r * p.ldc + c;
                if (p.flags & 4) *(float2*)(Cf + off) = make_float2(v0, v1);
                else {
                    __half2 hi; hi.x = __float2half(v0); hi.y = __float2half(v1);
                    *(__half2*)(Ch + off) = hi;
                }
            }
        }

    if (p.flags & 128) {
#pragma unroll
        for (int i = 0; i < 2; i++)
#pragma unroll
            for (int h = 0; h < 2; h++) {
                float s = rs_acc[i][h];
                s += __shfl_xor_sync(~0u, s, 1);
                s += __shfl_xor_sync(~0u, s, 2);
                if ((lane & 3) == 0)
                    atomicAdd(&p.rsum[(long long)pb * 1024 + rbase + i * 16 + h * 8], s);
            }
    }
}

// ---------------- merged fp32 -> fp16 conversion ----------------
#define NCVT 14
struct CvtP {
    const float4* src[NCVT];
    __half2* dst[NCVT];
    int n4[NCVT];
};
__global__ __launch_bounds__(256) void cvt_all_k(CvtP p) {
    const int ten = blockIdx.y;
    int i = blockIdx.x * blockDim.x + threadIdx.x;
    if (i >= p.n4[ten]) return;
    float4 v = p.src[ten][i];
    __half2 h0; h0.x = __float2half(v.x); h0.y = __float2half(v.y);
    __half2 h1; h1.x = __float2half(v.z); h1.y = __float2half(v.w);
    p.dst[ten][2 * i] = h0;
    p.dst[ten][2 * i + 1] = h1;
}

// ---------------- residual add (two partials) + LayerNorm (D=512) ----------------
__device__ __forceinline__ float bsum(float val, float* red) {
    const int lane = threadIdx.x & 31, w = threadIdx.x >> 5;
#pragma unroll
    for (int o = 16; o; o >>= 1) val += __shfl_xor_sync(~0u, val, o);
    if (lane == 0) red[w] = val;
    __syncthreads();
    float s = red[lane & 7];
#pragma unroll
    for (int o = 4; o; o >>= 1) s += __shfl_xor_sync(~0u, s, o);
    __syncthreads();
    return s;
}

__global__ __launch_bounds__(256)
void add_ln_k(const float2* __restrict__ a, const float2* __restrict__ a2,
              const float2* __restrict__ r,
              const float* __restrict__ g, const float* __restrict__ b,
              float2* __restrict__ o, __half2* oh) {
    __shared__ float red[8];
    const long long row = blockIdx.x;
    const int t = threadIdx.x;
    float2 va = a[row * 256 + t], vb = a2[row * 256 + t], vr = r[row * 256 + t];
    float x0 = va.x + vb.x + vr.x, x1 = va.y + vb.y + vr.y;
    float mean = bsum(x0 + x1, red) * (1.f / 512.f);
    float d0 = x0 - mean, d1 = x1 - mean;
    float var = bsum(d0 * d0 + d1 * d1, red) * (1.f / 512.f);
    float inv = rsqrtf(var + 1e-5f);
    float y0 = d0 * inv * g[2 * t] + b[2 * t];
    float y1 = d1 * inv * g[2 * t + 1] + b[2 * t + 1];
    o[row * 256 + t] = make_float2(y0, y1);
    if (oh) {
        __half2 hh; hh.x = __float2half(y0); hh.y = __float2half(y1);
        oh[row * 256 + t] = hh;
    }
}

// ---------------- host ----------------
static void launch_gemm(bool nt, const GemmP& p, int M, int N, int batch) {
    dim3 g(N / 128, M / 128, batch);
    if (nt) gemm_k<true><<<g, 256, SMEM_BYTES>>>(p);
    else    gemm_k<false><<<g, 256, SMEM_BYTES>>>(p);
}

extern "C" void kernel_launch(void* const* d_in, const int* in_sizes, int n_in,
                              void* d_out, int out_size) {
    const float* x   = (const float*)d_in[0];
    const float* enc = (const float*)d_in[1];
    const float* sa_wq = (const float*)d_in[2];  const float* sa_bq = (const float*)d_in[3];
    const float* sa_wk = (const float*)d_in[4];  const float* sa_bk = (const float*)d_in[5];
    const float* sa_wv = (const float*)d_in[6];  const float* sa_bv = (const float*)d_in[7];
    const float* sa_wo = (const float*)d_in[8];  const float* sa_bo = (const float*)d_in[9];
    const float* sa_wf = (const float*)d_in[10]; const float* sa_bf = (const float*)d_in[11];
    const float* ca_wq = (const float*)d_in[12]; const float* ca_bq = (const float*)d_in[13];
    const float* ca_wk = (const float*)d_in[14]; const float* ca_bk = (const float*)d_in[15];
    const float* ca_wv = (const float*)d_in[16]; const float* ca_bv = (const float*)d_in[17];
    const float* ca_wo = (const float*)d_in[18]; const float* ca_bo = (const float*)d_in[19];
    const float* ca_wf = (const float*)d_in[20]; const float* ca_bf = (const float*)d_in[21];
    const float* ln1_g = (const float*)d_in[22]; const float* ln1_b = (const float*)d_in[23];
    const float* ln2_g = (const float*)d_in[24]; const float* ln2_b = (const float*)d_in[25];
    const float* ln3_g = (const float*)d_in[26]; const float* ln3_b = (const float*)d_in[27];
    const float* fc1_w = (const float*)d_in[28]; const float* fc1_b = (const float*)d_in[29];
    const float* fc2_w = (const float*)d_in[30]; const float* fc2_b = (const float*)d_in[31];

    cudaFuncSetAttribute((const void*)gemm_k<false>,
                         cudaFuncAttributeMaxDynamicSharedMemorySize, SMEM_BYTES);
    cudaFuncSetAttribute((const void*)gemm_k<true>,
                         cudaFuncAttributeMaxDynamicSharedMemorySize, SMEM_BYTES);

    __half *QKV, *Sh, *Oh, *Ph, *Mh, *Wh, *xh, *eh, *X1h, *X2h;
    float *Hf, *X1f, *X2f, *RS;
    cudaGetSymbolAddress((void**)&QKV, g_QKV);
    cudaGetSymbolAddress((void**)&Sh, g_Sh);
    cudaGetSymbolAddress((void**)&Oh, g_Oh);
    cudaGetSymbolAddress((void**)&Ph, g_Ph);
    cudaGetSymbolAddress((void**)&Mh, g_Mh);
    cudaGetSymbolAddress((void**)&Wh, g_Wh);
    cudaGetSymbolAddress((void**)&xh, g_xh);  cudaGetSymbolAddress((void**)&eh, g_eh);
    cudaGetSymbolAddress((void**)&X1h, g_X1h); cudaGetSymbolAddress((void**)&X2h, g_X2h);
    cudaGetSymbolAddress((void**)&Hf, g_Hf);
    cudaGetSymbolAddress((void**)&X1f, g_X1f);
    cudaGetSymbolAddress((void**)&X2f, g_X2f);
    cudaGetSymbolAddress((void**)&RS, g_RS);

    __half* Qh = QKV;
    __half* Kh = QKV + 16777216;
    __half* Vh = QKV + 33554432;
    float* Hf2 = Hf + 2097152;

    // one merged conversion launch
    {
        CvtP cp{};
        const float* srcs[NCVT] = { x, enc, sa_wq, sa_wk, sa_wv, sa_wo, sa_wf,
                                    ca_wq, ca_wk, ca_wv, ca_wo, ca_wf, fc1_w, fc2_w };
        __half* dsts[NCVT] = { xh, eh, Wh + OW_SAQ, Wh + OW_SAK, Wh + OW_SAV,
                               Wh + OW_SAO, Wh + OW_SAF, Wh + OW_CAQ, Wh + OW_CAK,
                               Wh + OW_CAV, Wh + OW_CAO, Wh + OW_CAF,
                               Wh + OW_FC1, Wh + OW_FC2 };
        for (int i = 0; i < NCVT; i++) {
            cp.src[i] = (const float4*)srcs[i];
            cp.dst[i] = (__half2*)dsts[i];
            cp.n4[i] = (i >= 12) ? 262144 : 524288;
        }
        cvt_all_k<<<dim3(2048, NCVT), 256>>>(cp);
    }

    const float ISC = 0.044194173824159216f;  // 1/sqrt(512)

    auto runMHA = [&](const __half* aq, const __half* akv, long long oqkv,
                      long long oo, long long of,
                      const float* bq, const float* bk, const float* bv,
                      const float* bo, const float* bfb, bool causal) {
        GemmP p{};
        // fused Q/K/V projections: batch 24
        p.Ah = aq; p.Ah2 = akv; p.Bh = Wh + oqkv;
        p.bias = bq; p.biasB = bk; p.biasC = bv;
        p.Ch = QKV;
        p.K = 512; p.lda = 512; p.ldb = 512; p.ldc = 4096;
        p.sB1 = 2097152; p.sB2 = 262144; p.sC1 = 16777216; p.sC2 = 512;
        p.div = 8; p.biasStride = 512; p.alpha = 1.f; p.flags = 16 | 64;
        launch_gemm(false, p, 4096, 512, 24);
        // rowsum <- 0
        cudaMemsetAsync(RS, 0, 32768 * sizeof(float), 0);
        // scores: exp(Q K^T / sqrt(512)) stored fp16 + rowsum atomics
        p = GemmP{};
        p.Ah = Qh; p.Bh = Kh; p.Ch = Sh; p.rsum = RS;
        p.K = 512; p.lda = 4096; p.ldb = 4096; p.ldc = 1024;
        p.sA1 = 4194304; p.sA2 = 512; p.sB1 = 4194304; p.sB2 = 512;
        p.sC1 = 8388608; p.sC2 = 1048576;
        p.div = 8; p.alpha = ISC; p.flags = 128 | 16 | (causal ? 2 : 0);
        launch_gemm(true, p, 1024, 1024, 32);
        // O = P V / rowsum  (causal K-limit)
        p = GemmP{};
        p.Ah = Sh; p.Bh = Vh; p.Ch = Oh; p.rsum = RS;
        p.K = 1024; p.lda = 1024; p.ldb = 4096; p.ldc = 4096;
        p.sA1 = 8388608; p.sA2 = 1048576; p.sB1 = 4194304; p.sB2 = 512;
        p.sC1 = 4194304; p.sC2 = 512;
        p.div = 8; p.alpha = 1.f; p.flags = 256 | 16 | (causal ? 32 : 0);
        launch_gemm(false, p, 1024, 512, 32);
        // per-head out projection
        p = GemmP{};
        p.Ah = Oh; p.Bh = Wh + oo; p.bias = bo; p.Ch = Ph;
        p.K = 512; p.lda = 4096; p.ldb = 512; p.ldc = 4096;
        p.sA2 = 512; p.sB2 = 262144; p.sC2 = 512;
        p.div = 8; p.biasStride = 512; p.alpha = 1.f; p.flags = 16;
        launch_gemm(false, p, 4096, 512, 8);
        // final concat projection: split-K=2
        p = GemmP{};
        p.Ah = Ph; p.Ah2 = Ph; p.Bh = Wh + of;
        p.bias = bfb; p.biasB = nullptr; p.biasC = nullptr;
        p.Cf = Hf;
        p.K = 2048; p.lda = 4096; p.ldb = 512; p.ldc = 512;
        p.sA1 = 2048; p.sB1 = 2048LL * 512; p.sC1 = 2097152;
        p.div = 1; p.alpha = 1.f; p.flags = 4 | 64;
        launch_gemm(false, p, 4096, 512, 2);
    };

    // self-attention (causal) + LN1
    runMHA(xh, xh, OW_SAQ, OW_SAO, OW_SAF, sa_bq, sa_bk, sa_bv, sa_bo, sa_bf, true);
    add_ln_k<<<4096, 256>>>((const float2*)Hf, (const float2*)Hf2, (const float2*)x,
                            ln1_g, ln1_b, (float2*)X1f, (__half2*)X1h);

    // cross-attention + LN2
    runMHA(X1h, eh, OW_CAQ, OW_CAO, OW_CAF, ca_bq, ca_bk, ca_bv, ca_bo, ca_bf, false);
    add_ln_k<<<4096, 256>>>((const float2*)Hf, (const float2*)Hf2, (const float2*)X1f,
                            ln2_g, ln2_b, (float2*)X2f, (__half2*)X2h);

    // FFN
    {
        GemmP p{};
        p.Ah = X2h; p.Bh = Wh + OW_FC1; p.bias = fc1_b; p.Ch = Mh;
        p.K = 512; p.lda = 512; p.ldb = 2048; p.ldc = 2048;
        p.div = 1; p.biasStride = 0; p.alpha = 1.f; p.flags = 16 | 1;
        launch_gemm(false, p, 4096, 2048, 1);

        // FC2: split-K=2
        p = GemmP{};
        p.Ah = Mh; p.Ah2 = Mh; p.Bh = Wh + OW_FC2;
        p.bias = fc2_b; p.biasB = nullptr; p.biasC = nullptr;
        p.Cf = Hf;
        p.K = 1024; p.lda = 2048; p.ldb = 512; p.ldc = 512;
        p.sA1 = 1024; p.sB1 = 1024LL * 512; p.sC1 = 2097152;
        p.div = 1; p.alpha = 1.f; p.flags = 4 | 64;
        launch_gemm(false, p, 4096, 512, 2);
    }
    add_ln_k<<<4096, 256>>>((const float2*)Hf, (const float2*)Hf2, (const float2*)X2f,
                            ln3_g, ln3_b, (float2*)d_out, nullptr);
}